// round 1
// baseline (speedup 1.0000x reference)
#include <cuda_runtime.h>
#include <math.h>
#include <stddef.h>

// Problem constants (B=1)
#define SEQ   2048
#define HID   2048
#define NHEADS 16
#define NKVH   4
#define DHEAD  128
#define KVW   (NKVH * DHEAD)      // 512
#define GQA_REP (NHEADS / NKVH)   // 4

// Scratch (module-scope device arrays: the sanctioned no-alloc workaround)
__device__ float g_q[SEQ * HID];                    // 16 MB
__device__ float g_k[SEQ * KVW];                    // 4 MB
__device__ float g_v[SEQ * KVW];                    // 4 MB
__device__ float g_ctx[SEQ * HID];                  // 16 MB
__device__ float g_p[(size_t)NHEADS * SEQ * SEQ];   // 256 MB attention probs

// ---------------------------------------------------------------------------
// TN GEMM body: C[bm:bm+128, bn:bn+128] = A[M,K] * B[N,K]^T   (row-major, K-contig)
// 256 threads, 8x8 accumulators per thread, 16-wide K tiles.
// All dims used here are multiples of 128 (M,N) and 16 (K): no bounds checks.
// ---------------------------------------------------------------------------
__device__ __forceinline__ void gemm_tn_body(
    const float* __restrict__ A, int lda,
    const float* __restrict__ B, int ldb,
    float* __restrict__ C, int ldc,
    int K, int bm, int bn)
{
    __shared__ float As[16][132];
    __shared__ float Bs[16][132];
    const int tid = threadIdx.x;
    const int lr = tid >> 2;            // 0..63
    const int lc = (tid & 3) << 2;      // 0,4,8,12
    const float* Ap = A + (size_t)(bm + lr) * lda + lc;
    const float* Bp = B + (size_t)(bn + lr) * ldb + lc;
    const int ty = tid >> 4;            // 0..15
    const int tx = tid & 15;            // 0..15

    float acc[8][8];
#pragma unroll
    for (int i = 0; i < 8; i++)
#pragma unroll
        for (int j = 0; j < 8; j++) acc[i][j] = 0.f;

    for (int k0 = 0; k0 < K; k0 += 16) {
        float4 a0 = *(const float4*)Ap;
        float4 a1 = *(const float4*)(Ap + (size_t)64 * lda);
        float4 b0 = *(const float4*)Bp;
        float4 b1 = *(const float4*)(Bp + (size_t)64 * ldb);
        As[lc+0][lr]    = a0.x; As[lc+1][lr]    = a0.y; As[lc+2][lr]    = a0.z; As[lc+3][lr]    = a0.w;
        As[lc+0][lr+64] = a1.x; As[lc+1][lr+64] = a1.y; As[lc+2][lr+64] = a1.z; As[lc+3][lr+64] = a1.w;
        Bs[lc+0][lr]    = b0.x; Bs[lc+1][lr]    = b0.y; Bs[lc+2][lr]    = b0.z; Bs[lc+3][lr]    = b0.w;
        Bs[lc+0][lr+64] = b1.x; Bs[lc+1][lr+64] = b1.y; Bs[lc+2][lr+64] = b1.z; Bs[lc+3][lr+64] = b1.w;
        __syncthreads();
#pragma unroll
        for (int kk = 0; kk < 16; kk++) {
            float ar[8], br[8];
            *(float4*)&ar[0] = *(const float4*)&As[kk][ty * 8];
            *(float4*)&ar[4] = *(const float4*)&As[kk][ty * 8 + 4];
            *(float4*)&br[0] = *(const float4*)&Bs[kk][tx * 8];
            *(float4*)&br[4] = *(const float4*)&Bs[kk][tx * 8 + 4];
#pragma unroll
            for (int i = 0; i < 8; i++)
#pragma unroll
                for (int j = 0; j < 8; j++)
                    acc[i][j] = fmaf(ar[i], br[j], acc[i][j]);
        }
        __syncthreads();
        Ap += 16; Bp += 16;
    }
#pragma unroll
    for (int i = 0; i < 8; i++) {
        float* Cp = C + (size_t)(bm + ty * 8 + i) * ldc + bn + tx * 8;
        *(float4*)(Cp)     = make_float4(acc[i][0], acc[i][1], acc[i][2], acc[i][3]);
        *(float4*)(Cp + 4) = make_float4(acc[i][4], acc[i][5], acc[i][6], acc[i][7]);
    }
}

// ---------------------------------------------------------------------------
// NN GEMM body: C = A[M,K] * B[K,N]   (B row-major, N-contig). Same tiling.
// ---------------------------------------------------------------------------
__device__ __forceinline__ void gemm_nn_body(
    const float* __restrict__ A, int lda,
    const float* __restrict__ B, int ldb,
    float* __restrict__ C, int ldc,
    int K, int bm, int bn)
{
    __shared__ float As[16][132];
    __shared__ float Bs[16][132];
    const int tid = threadIdx.x;
    const int lr = tid >> 2;
    const int lc = (tid & 3) << 2;
    const float* Ap = A + (size_t)(bm + lr) * lda + lc;
    const int kr = tid >> 5;            // 0..7
    const int kc = (tid & 31) << 2;     // 0..124
    const float* Bp = B + (size_t)kr * ldb + bn + kc;
    const int ty = tid >> 4;
    const int tx = tid & 15;

    float acc[8][8];
#pragma unroll
    for (int i = 0; i < 8; i++)
#pragma unroll
        for (int j = 0; j < 8; j++) acc[i][j] = 0.f;

    for (int k0 = 0; k0 < K; k0 += 16) {
        float4 a0 = *(const float4*)Ap;
        float4 a1 = *(const float4*)(Ap + (size_t)64 * lda);
        float4 b0 = *(const float4*)Bp;
        float4 b1 = *(const float4*)(Bp + (size_t)8 * ldb);
        As[lc+0][lr]    = a0.x; As[lc+1][lr]    = a0.y; As[lc+2][lr]    = a0.z; As[lc+3][lr]    = a0.w;
        As[lc+0][lr+64] = a1.x; As[lc+1][lr+64] = a1.y; As[lc+2][lr+64] = a1.z; As[lc+3][lr+64] = a1.w;
        *(float4*)&Bs[kr][kc]     = b0;
        *(float4*)&Bs[kr + 8][kc] = b1;
        __syncthreads();
#pragma unroll
        for (int kk = 0; kk < 16; kk++) {
            float ar[8], br[8];
            *(float4*)&ar[0] = *(const float4*)&As[kk][ty * 8];
            *(float4*)&ar[4] = *(const float4*)&As[kk][ty * 8 + 4];
            *(float4*)&br[0] = *(const float4*)&Bs[kk][tx * 8];
            *(float4*)&br[4] = *(const float4*)&Bs[kk][tx * 8 + 4];
#pragma unroll
            for (int i = 0; i < 8; i++)
#pragma unroll
                for (int j = 0; j < 8; j++)
                    acc[i][j] = fmaf(ar[i], br[j], acc[i][j]);
        }
        __syncthreads();
        Ap += 16;
        Bp += (size_t)16 * ldb;
    }
#pragma unroll
    for (int i = 0; i < 8; i++) {
        float* Cp = C + (size_t)(bm + ty * 8 + i) * ldc + bn + tx * 8;
        *(float4*)(Cp)     = make_float4(acc[i][0], acc[i][1], acc[i][2], acc[i][3]);
        *(float4*)(Cp + 4) = make_float4(acc[i][4], acc[i][5], acc[i][6], acc[i][7]);
    }
}

// ---------------------------------------------------------------------------
// Kernels
// ---------------------------------------------------------------------------
__global__ __launch_bounds__(256) void k_gemm_tn(
    const float* __restrict__ A, int lda,
    const float* __restrict__ B, int ldb,
    float* __restrict__ C, int ldc, int K)
{
    gemm_tn_body(A, lda, B, ldb, C, ldc, K, blockIdx.y * 128, blockIdx.x * 128);
}

// scores[h][q][k] = dot(Q[q, h*128:...], K[k, (h/4)*128:...]); skip fully-masked blocks
__global__ __launch_bounds__(256) void k_gemm_qk(
    const float* __restrict__ Q, const float* __restrict__ Kmat, float* __restrict__ P)
{
    if (blockIdx.x > blockIdx.y) return;   // strictly above the diagonal: all masked
    const int h = blockIdx.z;
    gemm_tn_body(Q + h * DHEAD, HID,
                 Kmat + (h / GQA_REP) * DHEAD, KVW,
                 P + (size_t)h * SEQ * SEQ, SEQ,
                 DHEAD, blockIdx.y * 128, blockIdx.x * 128);
}

// ctx[q][h*128+d] = sum_k P[h][q][k] * V[k][(h/4)*128+d]; causal K-loop limit
__global__ __launch_bounds__(256) void k_gemm_av(
    const float* __restrict__ P, const float* __restrict__ V, float* __restrict__ Ctx)
{
    const int h = blockIdx.z;
    const int bm = blockIdx.y * 128;
    const int kend = bm + 128;             // keys beyond the diagonal block are zero/unused
    gemm_nn_body(P + (size_t)h * SEQ * SEQ, SEQ,
                 V + (h / GQA_REP) * DHEAD, KVW,
                 Ctx + h * DHEAD, HID,
                 kend, bm, blockIdx.x * 128);
}

// Fused per-(s,head) RMSNorm + RoPE, in place. One block of 128 threads per row.
__global__ __launch_bounds__(128) void k_normrope(
    float* __restrict__ X, int rowstride,
    const float* __restrict__ sin_t, const float* __restrict__ cos_t,
    const float* __restrict__ w)
{
    const int s = blockIdx.x;
    const int h = blockIdx.y;
    const int d = threadIdx.x;
    float* row = X + (size_t)s * rowstride + h * DHEAD;
    float v = row[d];
    float ss = v * v;
#pragma unroll
    for (int o = 16; o > 0; o >>= 1) ss += __shfl_xor_sync(0xffffffffu, ss, o);
    __shared__ float wsum[4];
    if ((d & 31) == 0) wsum[d >> 5] = ss;
    __syncthreads();
    float tot = wsum[0] + wsum[1] + wsum[2] + wsum[3];
    float inv = rsqrtf(tot * (1.0f / 128.0f) + 1.1920928955078125e-07f);
    __shared__ float xn[128];
    float xv = v * inv * w[d];
    xn[d] = xv;
    __syncthreads();
    float rot = (d < 64) ? -xn[d + 64] : xn[d - 64];
    row[d] = cos_t[s * DHEAD + d] * xv + sin_t[s * DHEAD + d] * rot;
}

// Causal softmax over row (h,q): valid keys [0, q]; zero-fill up to the 128 boundary
// so the AV GEMM's diagonal block reads zeros in the masked remainder.
__global__ __launch_bounds__(256) void k_softmax(float* __restrict__ P)
{
    const int q = blockIdx.x;
    const int h = blockIdx.y;
    float* p = P + (size_t)h * SEQ * SEQ + (size_t)q * SEQ;
    const int n = q + 1;
    const int tid = threadIdx.x;
    const float scale = 0.08838834764831843f;   // 1/sqrt(128)
    __shared__ float red[8];

    float mx = -3.4e38f;
    for (int i = tid; i < n; i += 256) mx = fmaxf(mx, p[i]);
#pragma unroll
    for (int o = 16; o > 0; o >>= 1) mx = fmaxf(mx, __shfl_xor_sync(0xffffffffu, mx, o));
    if ((tid & 31) == 0) red[tid >> 5] = mx;
    __syncthreads();
    mx = red[0];
#pragma unroll
    for (int wq = 1; wq < 8; wq++) mx = fmaxf(mx, red[wq]);
    const float M = mx * scale;
    __syncthreads();

    float sum = 0.f;
    for (int i = tid; i < n; i += 256) {
        float e = expf(p[i] * scale - M);
        p[i] = e;
        sum += e;
    }
#pragma unroll
    for (int o = 16; o > 0; o >>= 1) sum += __shfl_xor_sync(0xffffffffu, sum, o);
    if ((tid & 31) == 0) red[tid >> 5] = sum;
    __syncthreads();
    sum = red[0] + red[1] + red[2] + red[3] + red[4] + red[5] + red[6] + red[7];
    const float rinv = 1.f / sum;
    for (int i = tid; i < n; i += 256) p[i] *= rinv;
    const int end = ((q >> 7) + 1) << 7;
    for (int i = n + tid; i < end; i += 256) p[i] = 0.f;
}

// ---------------------------------------------------------------------------
// Launch
// ---------------------------------------------------------------------------
extern "C" void kernel_launch(void* const* d_in, const int* in_sizes, int n_in,
                              void* d_out, int out_size)
{
    (void)in_sizes; (void)n_in; (void)out_size;
    const float* x     = (const float*)d_in[0];
    const float* sin_t = (const float*)d_in[1];
    const float* cos_t = (const float*)d_in[2];
    // d_in[3] = boolean causal mask: structure known, not needed
    const float* wq    = (const float*)d_in[4];
    const float* wk    = (const float*)d_in[5];
    const float* wv    = (const float*)d_in[6];
    const float* wo    = (const float*)d_in[7];
    const float* qnw   = (const float*)d_in[8];
    const float* knw   = (const float*)d_in[9];
    float* out = (float*)d_out;

    float *q, *k, *v, *ctx, *p;
    cudaGetSymbolAddress((void**)&q,   g_q);
    cudaGetSymbolAddress((void**)&k,   g_k);
    cudaGetSymbolAddress((void**)&v,   g_v);
    cudaGetSymbolAddress((void**)&ctx, g_ctx);
    cudaGetSymbolAddress((void**)&p,   g_p);

    // Projections: q = x*wq^T [2048x2048], k/v = x*w^T [2048x512]
    k_gemm_tn<<<dim3(HID / 128, SEQ / 128), 256>>>(x, HID, wq, HID, q, HID, HID);
    k_gemm_tn<<<dim3(KVW / 128, SEQ / 128), 256>>>(x, HID, wk, HID, k, KVW, HID);
    k_gemm_tn<<<dim3(KVW / 128, SEQ / 128), 256>>>(x, HID, wv, HID, v, KVW, HID);

    // RMSNorm + RoPE per head (k normalized once per kv-head; GQA repeat is a no-op for norm/rope)
    k_normrope<<<dim3(SEQ, NHEADS), 128>>>(q, HID, sin_t, cos_t, qnw);
    k_normrope<<<dim3(SEQ, NKVH),  128>>>(k, KVW, sin_t, cos_t, knw);

    // Attention: scores -> softmax -> ctx
    k_gemm_qk<<<dim3(SEQ / 128, SEQ / 128, NHEADS), 256>>>(q, k, p);
    k_softmax<<<dim3(SEQ, NHEADS), 256>>>(p);
    k_gemm_av<<<dim3(DHEAD / 128, SEQ / 128, NHEADS), 256>>>(p, v, ctx);

    // Output projection: out = ctx * wo^T
    k_gemm_tn<<<dim3(HID / 128, SEQ / 128), 256>>>(ctx, HID, wo, HID, out, HID, HID);
}

// round 2
// speedup vs baseline: 2.3660x; 2.3660x over previous
#include <cuda_runtime.h>
#include <math.h>
#include <stddef.h>
#include <stdint.h>

// Problem constants (B=1)
#define SEQ   2048
#define HID   2048
#define NHEADS 16
#define NKVH   4
#define DHEAD  128
#define KVW   (NKVH * DHEAD)      // 512
#define GQA_REP (NHEADS / NKVH)   // 4

// Scratch (module-scope device arrays: the sanctioned no-alloc workaround)
__device__ float g_q[SEQ * HID];                    // 16 MB
__device__ float g_k[SEQ * KVW];                    // 4 MB
__device__ float g_v[SEQ * KVW];                    // 4 MB
__device__ float g_ctx[SEQ * HID];                  // 16 MB
__device__ float g_p[(size_t)NHEADS * SEQ * SEQ];   // 256 MB attention probs

// ---------------------------------------------------------------------------
// tf32 helpers
// ---------------------------------------------------------------------------
__device__ __forceinline__ float tf32r(float x) {
    uint32_t u;
    asm("cvt.rna.tf32.f32 %0, %1;" : "=r"(u) : "f"(x));
    return __uint_as_float(u);
}
__device__ __forceinline__ float4 tf32r4(float4 v) {
    return make_float4(tf32r(v.x), tf32r(v.y), tf32r(v.z), tf32r(v.w));
}
__device__ __forceinline__ void mma_tf32(float c[4],
                                         uint32_t a0, uint32_t a1, uint32_t a2, uint32_t a3,
                                         uint32_t b0, uint32_t b1) {
    asm volatile(
        "mma.sync.aligned.m16n8k8.row.col.f32.tf32.tf32.f32 "
        "{%0,%1,%2,%3}, {%4,%5,%6,%7}, {%8,%9}, {%0,%1,%2,%3};"
        : "+f"(c[0]), "+f"(c[1]), "+f"(c[2]), "+f"(c[3])
        : "r"(a0), "r"(a1), "r"(a2), "r"(a3), "r"(b0), "r"(b1));
}

// ---------------------------------------------------------------------------
// TN GEMM (tensor core): C[bm:+128, bn:+128] = A[M,K] * B[N,K]^T
// A, B row-major K-contiguous. 256 threads = 8 warps (4x2 warp grid),
// warp tile 32x64 -> 2 m16 tiles x 8 n8 tiles. K chunk = 16 (2 k-steps).
// SMEM [row][k] with pad 20 -> conflict-free fragment gathers.
// ---------------------------------------------------------------------------
__device__ __forceinline__ void gemm_tn_tc(
    const float* __restrict__ A, int lda,
    const float* __restrict__ B, int ldb,
    float* __restrict__ C, int ldc,
    int K, int bm, int bn)
{
    __shared__ float As[128][20];
    __shared__ float Bs[128][20];
    const int tid  = threadIdx.x;
    const int lane = tid & 31;
    const int w    = tid >> 5;
    const int wm   = w >> 1;     // 0..3
    const int wn   = w & 1;      // 0..1
    const int lr   = tid >> 2;   // 0..63
    const int lc4  = (tid & 3) << 2;

    const float* Ap = A + (size_t)(bm + lr) * lda + lc4;
    const float* Bp = B + (size_t)(bn + lr) * ldb + lc4;

    float acc[2][8][4];
#pragma unroll
    for (int mt = 0; mt < 2; mt++)
#pragma unroll
        for (int nt = 0; nt < 8; nt++)
#pragma unroll
            for (int i = 0; i < 4; i++) acc[mt][nt][i] = 0.f;

    float4 pa0 = *(const float4*)Ap;
    float4 pa1 = *(const float4*)(Ap + (size_t)64 * lda);
    float4 pb0 = *(const float4*)Bp;
    float4 pb1 = *(const float4*)(Bp + (size_t)64 * ldb);

    const int ar = lane >> 2;       // 0..7
    const int ak = lane & 3;        // 0..3

    for (int k0 = 0; k0 < K; k0 += 16) {
        *(float4*)&As[lr][lc4]      = tf32r4(pa0);
        *(float4*)&As[lr + 64][lc4] = tf32r4(pa1);
        *(float4*)&Bs[lr][lc4]      = tf32r4(pb0);
        *(float4*)&Bs[lr + 64][lc4] = tf32r4(pb1);
        __syncthreads();
        if (k0 + 16 < K) {
            Ap += 16; Bp += 16;
            pa0 = *(const float4*)Ap;
            pa1 = *(const float4*)(Ap + (size_t)64 * lda);
            pb0 = *(const float4*)Bp;
            pb1 = *(const float4*)(Bp + (size_t)64 * ldb);
        }
#pragma unroll
        for (int ks = 0; ks < 16; ks += 8) {
            uint32_t afr[2][4];
#pragma unroll
            for (int mt = 0; mt < 2; mt++) {
                const int mb = wm * 32 + mt * 16;
                afr[mt][0] = __float_as_uint(As[mb + ar][ks + ak]);
                afr[mt][1] = __float_as_uint(As[mb + ar + 8][ks + ak]);
                afr[mt][2] = __float_as_uint(As[mb + ar][ks + ak + 4]);
                afr[mt][3] = __float_as_uint(As[mb + ar + 8][ks + ak + 4]);
            }
#pragma unroll
            for (int nt = 0; nt < 8; nt++) {
                const int nb = wn * 64 + nt * 8;
                uint32_t b0 = __float_as_uint(Bs[nb + ar][ks + ak]);
                uint32_t b1 = __float_as_uint(Bs[nb + ar][ks + ak + 4]);
                mma_tf32(acc[0][nt], afr[0][0], afr[0][1], afr[0][2], afr[0][3], b0, b1);
                mma_tf32(acc[1][nt], afr[1][0], afr[1][1], afr[1][2], afr[1][3], b0, b1);
            }
        }
        __syncthreads();
    }

    // Epilogue: c0,c1 at (row, col..col+1), c2,c3 at (row+8, ..)
#pragma unroll
    for (int mt = 0; mt < 2; mt++) {
        const int r0 = bm + wm * 32 + mt * 16 + ar;
#pragma unroll
        for (int nt = 0; nt < 8; nt++) {
            const int cidx = bn + wn * 64 + nt * 8 + 2 * ak;
            *(float2*)(C + (size_t)r0 * ldc + cidx)       = make_float2(acc[mt][nt][0], acc[mt][nt][1]);
            *(float2*)(C + (size_t)(r0 + 8) * ldc + cidx) = make_float2(acc[mt][nt][2], acc[mt][nt][3]);
        }
    }
}

// ---------------------------------------------------------------------------
// NN GEMM (tensor core): C = A[M,K] * B[K,N]  (B row-major, N-contiguous)
// Used for attn*V. A tile in [m][k] pad 20; B tile in [k][n] pad 136.
// ---------------------------------------------------------------------------
__device__ __forceinline__ void gemm_nn_tc(
    const float* __restrict__ A, int lda,
    const float* __restrict__ B, int ldb,
    float* __restrict__ C, int ldc,
    int K, int bm, int bn)
{
    __shared__ float As[128][20];
    __shared__ float Bs[16][136];
    const int tid  = threadIdx.x;
    const int lane = tid & 31;
    const int w    = tid >> 5;
    const int wm   = w >> 1;
    const int wn   = w & 1;
    const int lr   = tid >> 2;
    const int lc4  = (tid & 3) << 2;
    const int kr   = tid >> 4;          // 0..15
    const int nc   = (tid & 15) << 3;   // 0..120

    const float* Ap = A + (size_t)(bm + lr) * lda + lc4;
    const float* Bp = B + (size_t)kr * ldb + bn + nc;

    float acc[2][8][4];
#pragma unroll
    for (int mt = 0; mt < 2; mt++)
#pragma unroll
        for (int nt = 0; nt < 8; nt++)
#pragma unroll
            for (int i = 0; i < 4; i++) acc[mt][nt][i] = 0.f;

    const int ar = lane >> 2;
    const int ak = lane & 3;

    for (int k0 = 0; k0 < K; k0 += 16) {
        float4 a0 = *(const float4*)Ap;
        float4 a1 = *(const float4*)(Ap + (size_t)64 * lda);
        float4 b0 = *(const float4*)Bp;
        float4 b1 = *(const float4*)(Bp + 4);
        *(float4*)&As[lr][lc4]      = tf32r4(a0);
        *(float4*)&As[lr + 64][lc4] = tf32r4(a1);
        *(float4*)&Bs[kr][nc]       = tf32r4(b0);
        *(float4*)&Bs[kr][nc + 4]   = tf32r4(b1);
        __syncthreads();
#pragma unroll
        for (int ks = 0; ks < 16; ks += 8) {
            uint32_t afr[2][4];
#pragma unroll
            for (int mt = 0; mt < 2; mt++) {
                const int mb = wm * 32 + mt * 16;
                afr[mt][0] = __float_as_uint(As[mb + ar][ks + ak]);
                afr[mt][1] = __float_as_uint(As[mb + ar + 8][ks + ak]);
                afr[mt][2] = __float_as_uint(As[mb + ar][ks + ak + 4]);
                afr[mt][3] = __float_as_uint(As[mb + ar + 8][ks + ak + 4]);
            }
#pragma unroll
            for (int nt = 0; nt < 8; nt++) {
                const int nb = wn * 64 + nt * 8;
                uint32_t b0f = __float_as_uint(Bs[ks + ak][nb + ar]);
                uint32_t b1f = __float_as_uint(Bs[ks + ak + 4][nb + ar]);
                mma_tf32(acc[0][nt], afr[0][0], afr[0][1], afr[0][2], afr[0][3], b0f, b1f);
                mma_tf32(acc[1][nt], afr[1][0], afr[1][1], afr[1][2], afr[1][3], b0f, b1f);
            }
        }
        __syncthreads();
        Ap += 16;
        Bp += (size_t)16 * ldb;
    }

#pragma unroll
    for (int mt = 0; mt < 2; mt++) {
        const int r0 = bm + wm * 32 + mt * 16 + ar;
#pragma unroll
        for (int nt = 0; nt < 8; nt++) {
            const int cidx = bn + wn * 64 + nt * 8 + 2 * ak;
            *(float2*)(C + (size_t)r0 * ldc + cidx)       = make_float2(acc[mt][nt][0], acc[mt][nt][1]);
            *(float2*)(C + (size_t)(r0 + 8) * ldc + cidx) = make_float2(acc[mt][nt][2], acc[mt][nt][3]);
        }
    }
}

// ---------------------------------------------------------------------------
// Kernels
// ---------------------------------------------------------------------------
__global__ __launch_bounds__(256) void k_gemm_tn(
    const float* __restrict__ A, int lda,
    const float* __restrict__ B, int ldb,
    float* __restrict__ C, int ldc, int K)
{
    gemm_tn_tc(A, lda, B, ldb, C, ldc, K, blockIdx.y * 128, blockIdx.x * 128);
}

// scores[h][q][k] = dot(Q[q, h*128:...], K[k, (h/4)*128:...]); skip masked blocks
__global__ __launch_bounds__(256) void k_gemm_qk(
    const float* __restrict__ Q, const float* __restrict__ Kmat, float* __restrict__ P)
{
    if (blockIdx.x > blockIdx.y) return;   // strictly above diagonal: fully masked
    const int h = blockIdx.z;
    gemm_tn_tc(Q + h * DHEAD, HID,
               Kmat + (h / GQA_REP) * DHEAD, KVW,
               P + (size_t)h * SEQ * SEQ, SEQ,
               DHEAD, blockIdx.y * 128, blockIdx.x * 128);
}

// ctx[q][h*128+d] = sum_k P[h][q][k] * V[k][(h/4)*128+d]; causal K-loop limit
__global__ __launch_bounds__(256) void k_gemm_av(
    const float* __restrict__ P, const float* __restrict__ V, float* __restrict__ Ctx)
{
    const int h = blockIdx.z;
    const int bm = blockIdx.y * 128;
    gemm_nn_tc(P + (size_t)h * SEQ * SEQ, SEQ,
               V + (h / GQA_REP) * DHEAD, KVW,
               Ctx + h * DHEAD, HID,
               bm + 128, bm, blockIdx.x * 128);
}

// Fused per-(s,head) RMSNorm + RoPE, in place. 128 threads per row.
__global__ __launch_bounds__(128) void k_normrope(
    float* __restrict__ X, int rowstride,
    const float* __restrict__ sin_t, const float* __restrict__ cos_t,
    const float* __restrict__ w)
{
    const int s = blockIdx.x;
    const int h = blockIdx.y;
    const int d = threadIdx.x;
    float* row = X + (size_t)s * rowstride + h * DHEAD;
    float v = row[d];
    float ss = v * v;
#pragma unroll
    for (int o = 16; o > 0; o >>= 1) ss += __shfl_xor_sync(0xffffffffu, ss, o);
    __shared__ float wsum[4];
    if ((d & 31) == 0) wsum[d >> 5] = ss;
    __syncthreads();
    float tot = wsum[0] + wsum[1] + wsum[2] + wsum[3];
    float inv = rsqrtf(tot * (1.0f / 128.0f) + 1.1920928955078125e-07f);
    __shared__ float xn[128];
    float xv = v * inv * w[d];
    xn[d] = xv;
    __syncthreads();
    float rot = (d < 64) ? -xn[d + 64] : xn[d - 64];
    row[d] = cos_t[s * DHEAD + d] * xv + sin_t[s * DHEAD + d] * rot;
}

// Causal softmax over row (h,q): valid keys [0, q]; zero-fill to 128 boundary.
__global__ __launch_bounds__(256) void k_softmax(float* __restrict__ P)
{
    const int q = blockIdx.x;
    const int h = blockIdx.y;
    float* p = P + (size_t)h * SEQ * SEQ + (size_t)q * SEQ;
    const int n = q + 1;
    const int tid = threadIdx.x;
    const float scale = 0.08838834764831843f;   // 1/sqrt(128)
    __shared__ float red[8];

    float mx = -3.4e38f;
    for (int i = tid; i < n; i += 256) mx = fmaxf(mx, p[i]);
#pragma unroll
    for (int o = 16; o > 0; o >>= 1) mx = fmaxf(mx, __shfl_xor_sync(0xffffffffu, mx, o));
    if ((tid & 31) == 0) red[tid >> 5] = mx;
    __syncthreads();
    mx = red[0];
#pragma unroll
    for (int wq = 1; wq < 8; wq++) mx = fmaxf(mx, red[wq]);
    const float M = mx * scale;
    __syncthreads();

    float sum = 0.f;
    for (int i = tid; i < n; i += 256) {
        float e = expf(p[i] * scale - M);
        p[i] = e;
        sum += e;
    }
#pragma unroll
    for (int o = 16; o > 0; o >>= 1) sum += __shfl_xor_sync(0xffffffffu, sum, o);
    if ((tid & 31) == 0) red[tid >> 5] = sum;
    __syncthreads();
    sum = red[0] + red[1] + red[2] + red[3] + red[4] + red[5] + red[6] + red[7];
    const float rinv = 1.f / sum;
    for (int i = tid; i < n; i += 256) p[i] *= rinv;
    const int end = ((q >> 7) + 1) << 7;
    for (int i = n + tid; i < end; i += 256) p[i] = 0.f;
}

// ---------------------------------------------------------------------------
// Launch
// ---------------------------------------------------------------------------
extern "C" void kernel_launch(void* const* d_in, const int* in_sizes, int n_in,
                              void* d_out, int out_size)
{
    (void)in_sizes; (void)n_in; (void)out_size;
    const float* x     = (const float*)d_in[0];
    const float* sin_t = (const float*)d_in[1];
    const float* cos_t = (const float*)d_in[2];
    // d_in[3] = boolean causal mask: structure known, not needed
    const float* wq    = (const float*)d_in[4];
    const float* wk    = (const float*)d_in[5];
    const float* wv    = (const float*)d_in[6];
    const float* wo    = (const float*)d_in[7];
    const float* qnw   = (const float*)d_in[8];
    const float* knw   = (const float*)d_in[9];
    float* out = (float*)d_out;

    float *q, *k, *v, *ctx, *p;
    cudaGetSymbolAddress((void**)&q,   g_q);
    cudaGetSymbolAddress((void**)&k,   g_k);
    cudaGetSymbolAddress((void**)&v,   g_v);
    cudaGetSymbolAddress((void**)&ctx, g_ctx);
    cudaGetSymbolAddress((void**)&p,   g_p);

    // Projections: q = x*wq^T [2048x2048], k/v = x*w^T [2048x512]
    k_gemm_tn<<<dim3(HID / 128, SEQ / 128), 256>>>(x, HID, wq, HID, q, HID, HID);
    k_gemm_tn<<<dim3(KVW / 128, SEQ / 128), 256>>>(x, HID, wk, HID, k, KVW, HID);
    k_gemm_tn<<<dim3(KVW / 128, SEQ / 128), 256>>>(x, HID, wv, HID, v, KVW, HID);

    // RMSNorm + RoPE per head (k normalized once per kv-head)
    k_normrope<<<dim3(SEQ, NHEADS), 128>>>(q, HID, sin_t, cos_t, qnw);
    k_normrope<<<dim3(SEQ, NKVH),  128>>>(k, KVW, sin_t, cos_t, knw);

    // Attention: scores -> softmax -> ctx
    k_gemm_qk<<<dim3(SEQ / 128, SEQ / 128, NHEADS), 256>>>(q, k, p);
    k_softmax<<<dim3(SEQ, NHEADS), 256>>>(p);
    k_gemm_av<<<dim3(DHEAD / 128, SEQ / 128, NHEADS), 256>>>(p, v, ctx);

    // Output projection: out = ctx * wo^T
    k_gemm_tn<<<dim3(HID / 128, SEQ / 128), 256>>>(ctx, HID, wo, HID, out, HID, HID);
}

// round 3
// speedup vs baseline: 2.8721x; 1.2139x over previous
#include <cuda_runtime.h>
#include <math.h>
#include <stddef.h>
#include <stdint.h>

// Problem constants (B=1)
#define SEQ   2048
#define HID   2048
#define NHEADS 16
#define NKVH   4
#define DHEAD  128
#define KVW   (NKVH * DHEAD)      // 512
#define GQA_REP (NHEADS / NKVH)   // 4

// Scratch
__device__ float g_q[SEQ * HID];                    // 16 MB
__device__ float g_k[SEQ * KVW];                    // 4 MB
__device__ float g_v[SEQ * KVW];                    // 4 MB
__device__ float g_ctx[SEQ * HID];                  // 16 MB

// ---------------------------------------------------------------------------
// helpers
// ---------------------------------------------------------------------------
__device__ __forceinline__ float tf32r(float x) {
    uint32_t u;
    asm("cvt.rna.tf32.f32 %0, %1;" : "=r"(u) : "f"(x));
    return __uint_as_float(u);
}
__device__ __forceinline__ float4 tf32r4(float4 v) {
    return make_float4(tf32r(v.x), tf32r(v.y), tf32r(v.z), tf32r(v.w));
}
__device__ __forceinline__ float ex2(float x) {
    float y;
    asm("ex2.approx.ftz.f32 %0, %1;" : "=f"(y) : "f"(x));
    return y;
}
__device__ __forceinline__ void mma_tf32(float c[4],
                                         uint32_t a0, uint32_t a1, uint32_t a2, uint32_t a3,
                                         uint32_t b0, uint32_t b1) {
    asm volatile(
        "mma.sync.aligned.m16n8k8.row.col.f32.tf32.tf32.f32 "
        "{%0,%1,%2,%3}, {%4,%5,%6,%7}, {%8,%9}, {%0,%1,%2,%3};"
        : "+f"(c[0]), "+f"(c[1]), "+f"(c[2]), "+f"(c[3])
        : "r"(a0), "r"(a1), "r"(a2), "r"(a3), "r"(b0), "r"(b1));
}

// ---------------------------------------------------------------------------
// TN GEMM (tensor core): C[bm:+128, bn:+128] = A[M,K] * B[N,K]^T  (projections)
// ---------------------------------------------------------------------------
__device__ __forceinline__ void gemm_tn_tc(
    const float* __restrict__ A, int lda,
    const float* __restrict__ B, int ldb,
    float* __restrict__ C, int ldc,
    int K, int bm, int bn)
{
    __shared__ float As[128][20];
    __shared__ float Bs[128][20];
    const int tid  = threadIdx.x;
    const int lane = tid & 31;
    const int w    = tid >> 5;
    const int wm   = w >> 1;
    const int wn   = w & 1;
    const int lr   = tid >> 2;
    const int lc4  = (tid & 3) << 2;

    const float* Ap = A + (size_t)(bm + lr) * lda + lc4;
    const float* Bp = B + (size_t)(bn + lr) * ldb + lc4;

    float acc[2][8][4];
#pragma unroll
    for (int mt = 0; mt < 2; mt++)
#pragma unroll
        for (int nt = 0; nt < 8; nt++)
#pragma unroll
            for (int i = 0; i < 4; i++) acc[mt][nt][i] = 0.f;

    float4 pa0 = *(const float4*)Ap;
    float4 pa1 = *(const float4*)(Ap + (size_t)64 * lda);
    float4 pb0 = *(const float4*)Bp;
    float4 pb1 = *(const float4*)(Bp + (size_t)64 * ldb);

    const int ar = lane >> 2;
    const int ak = lane & 3;

    for (int k0 = 0; k0 < K; k0 += 16) {
        *(float4*)&As[lr][lc4]      = tf32r4(pa0);
        *(float4*)&As[lr + 64][lc4] = tf32r4(pa1);
        *(float4*)&Bs[lr][lc4]      = tf32r4(pb0);
        *(float4*)&Bs[lr + 64][lc4] = tf32r4(pb1);
        __syncthreads();
        if (k0 + 16 < K) {
            Ap += 16; Bp += 16;
            pa0 = *(const float4*)Ap;
            pa1 = *(const float4*)(Ap + (size_t)64 * lda);
            pb0 = *(const float4*)Bp;
            pb1 = *(const float4*)(Bp + (size_t)64 * ldb);
        }
#pragma unroll
        for (int ks = 0; ks < 16; ks += 8) {
            uint32_t afr[2][4];
#pragma unroll
            for (int mt = 0; mt < 2; mt++) {
                const int mb = wm * 32 + mt * 16;
                afr[mt][0] = __float_as_uint(As[mb + ar][ks + ak]);
                afr[mt][1] = __float_as_uint(As[mb + ar + 8][ks + ak]);
                afr[mt][2] = __float_as_uint(As[mb + ar][ks + ak + 4]);
                afr[mt][3] = __float_as_uint(As[mb + ar + 8][ks + ak + 4]);
            }
#pragma unroll
            for (int nt = 0; nt < 8; nt++) {
                const int nb = wn * 64 + nt * 8;
                uint32_t b0 = __float_as_uint(Bs[nb + ar][ks + ak]);
                uint32_t b1 = __float_as_uint(Bs[nb + ar][ks + ak + 4]);
                mma_tf32(acc[0][nt], afr[0][0], afr[0][1], afr[0][2], afr[0][3], b0, b1);
                mma_tf32(acc[1][nt], afr[1][0], afr[1][1], afr[1][2], afr[1][3], b0, b1);
            }
        }
        __syncthreads();
    }

#pragma unroll
    for (int mt = 0; mt < 2; mt++) {
        const int r0 = bm + wm * 32 + mt * 16 + ar;
#pragma unroll
        for (int nt = 0; nt < 8; nt++) {
            const int cidx = bn + wn * 64 + nt * 8 + 2 * ak;
            *(float2*)(C + (size_t)r0 * ldc + cidx)       = make_float2(acc[mt][nt][0], acc[mt][nt][1]);
            *(float2*)(C + (size_t)(r0 + 8) * ldc + cidx) = make_float2(acc[mt][nt][2], acc[mt][nt][3]);
        }
    }
}

__global__ __launch_bounds__(256) void k_gemm_tn(
    const float* __restrict__ A, int lda,
    const float* __restrict__ B, int ldb,
    float* __restrict__ C, int ldc, int K)
{
    gemm_tn_tc(A, lda, B, ldb, C, ldc, K, blockIdx.y * 128, blockIdx.x * 128);
}

// ---------------------------------------------------------------------------
// Fused flash attention: per CTA one (head, 64-row q-block).
// Online softmax, tf32 MMA for QK^T and PV; P reuses the K smem tile.
// ---------------------------------------------------------------------------
#define QS_OFF   0
#define KS_OFF   (64 * 132 * 4)               // 33792
#define VS_OFF   (KS_OFF + 64 * 132 * 4)      // 67584
#define RMX_OFF  (VS_OFF + 64 * 136 * 4)      // 102400
#define RSM_OFF  (RMX_OFF + 4 * 64 * 4)       // 103424
#define CRR_OFF  (RSM_OFF + 4 * 64 * 4)       // 104448
#define FLASH_SMEM (CRR_OFF + 64 * 4)         // 104704

__global__ __launch_bounds__(256, 2) void k_flash(
    const float* __restrict__ Qg, const float* __restrict__ Kg,
    const float* __restrict__ Vg, float* __restrict__ Ctx)
{
    extern __shared__ char smem[];
    float (*Qs)[132]    = (float(*)[132])(smem + QS_OFF);
    float (*Ks)[132]    = (float(*)[132])(smem + KS_OFF);   // doubles as P
    float (*Vs)[136]    = (float(*)[136])(smem + VS_OFF);
    float (*redmax)[64] = (float(*)[64])(smem + RMX_OFF);
    float (*redsum)[64] = (float(*)[64])(smem + RSM_OFF);
    float* corrs        = (float*)(smem + CRR_OFF);

    const int bid = blockIdx.x;
    const int h   = bid & 15;
    const int qi  = 31 - (bid >> 4);          // longest blocks scheduled first
    const int kvh = h >> 2;

    const int tid  = threadIdx.x;
    const int lane = tid & 31;
    const int w    = tid >> 5;
    const int wm   = w >> 2;                  // 0..1
    const int wn   = w & 3;                   // 0..3
    const int ar   = lane >> 2;               // 0..7
    const int ak   = lane & 3;                // 0..3
    const float C  = (float)(0.08838834764831843 * 1.4426950408889634); // scale*log2e

    // Q tile [64 rows x 128], tf32
    {
        const int r  = tid >> 2;
        const int c0 = (tid & 3) << 2;
        const float* qp = Qg + (size_t)(qi * 64 + r) * HID + h * DHEAD + c0;
#pragma unroll
        for (int i = 0; i < 8; i++)
            *(float4*)&Qs[r][c0 + 16 * i] = tf32r4(*(const float4*)(qp + 16 * i));
    }

    float o[2][4][4];
    float m_st[2][2], l_st[2][2];
#pragma unroll
    for (int mt = 0; mt < 2; mt++) {
#pragma unroll
        for (int nt = 0; nt < 4; nt++)
#pragma unroll
            for (int c = 0; c < 4; c++) o[mt][nt][c] = 0.f;
        m_st[mt][0] = m_st[mt][1] = -1e30f;
        l_st[mt][0] = l_st[mt][1] = 0.f;
    }

    const int nkb = qi + 1;
    for (int j = 0; j < nkb; j++) {
        __syncthreads();                       // prior PV frag reads / Q store done
        {
            const int r  = tid >> 2;
            const int c0 = (tid & 3) << 2;
            const float* kp = Kg + (size_t)(j * 64 + r) * KVW + kvh * DHEAD + c0;
            const float* vp = Vg + (size_t)(j * 64 + r) * KVW + kvh * DHEAD + c0;
#pragma unroll
            for (int i = 0; i < 8; i++) {
                *(float4*)&Ks[r][c0 + 16 * i] = tf32r4(*(const float4*)(kp + 16 * i));
                *(float4*)&Vs[r][c0 + 16 * i] = tf32r4(*(const float4*)(vp + 16 * i));
            }
        }
        __syncthreads();                       // K, V visible

        // S = Q*K^T  (64x64, K=128); warp tile 32x16
        float s[2][2][4];
#pragma unroll
        for (int mt = 0; mt < 2; mt++)
#pragma unroll
            for (int nt = 0; nt < 2; nt++)
#pragma unroll
                for (int c = 0; c < 4; c++) s[mt][nt][c] = 0.f;
#pragma unroll
        for (int ks = 0; ks < 128; ks += 8) {
            uint32_t a[2][4];
#pragma unroll
            for (int mt = 0; mt < 2; mt++) {
                const int mb = wm * 32 + mt * 16;
                a[mt][0] = __float_as_uint(Qs[mb + ar][ks + ak]);
                a[mt][1] = __float_as_uint(Qs[mb + ar + 8][ks + ak]);
                a[mt][2] = __float_as_uint(Qs[mb + ar][ks + ak + 4]);
                a[mt][3] = __float_as_uint(Qs[mb + ar + 8][ks + ak + 4]);
            }
#pragma unroll
            for (int nt = 0; nt < 2; nt++) {
                const int nb = wn * 16 + nt * 8;
                uint32_t b0 = __float_as_uint(Ks[nb + ar][ks + ak]);
                uint32_t b1 = __float_as_uint(Ks[nb + ar][ks + ak + 4]);
                mma_tf32(s[0][nt], a[0][0], a[0][1], a[0][2], a[0][3], b0, b1);
                mma_tf32(s[1][nt], a[1][0], a[1][1], a[1][2], a[1][3], b0, b1);
            }
        }

        // causal mask on the diagonal block (local row/col comparison)
        if (j == qi) {
#pragma unroll
            for (int mt = 0; mt < 2; mt++)
#pragma unroll
                for (int nt = 0; nt < 2; nt++) {
                    const int colb = wn * 16 + nt * 8 + 2 * ak;
#pragma unroll
                    for (int cc = 0; cc < 4; cc++) {
                        const int row_l = wm * 32 + mt * 16 + ar + (cc >> 1) * 8;
                        const int col_l = colb + (cc & 1);
                        if (col_l > row_l) s[mt][nt][cc] = -1e30f;
                    }
                }
        }

        // row max: thread-local -> 4-lane shfl -> cross-warp smem
#pragma unroll
        for (int mt = 0; mt < 2; mt++) {
            float r0m = fmaxf(fmaxf(s[mt][0][0], s[mt][0][1]), fmaxf(s[mt][1][0], s[mt][1][1]));
            float r1m = fmaxf(fmaxf(s[mt][0][2], s[mt][0][3]), fmaxf(s[mt][1][2], s[mt][1][3]));
            r0m = fmaxf(r0m, __shfl_xor_sync(0xffffffffu, r0m, 1));
            r0m = fmaxf(r0m, __shfl_xor_sync(0xffffffffu, r0m, 2));
            r1m = fmaxf(r1m, __shfl_xor_sync(0xffffffffu, r1m, 1));
            r1m = fmaxf(r1m, __shfl_xor_sync(0xffffffffu, r1m, 2));
            if (ak == 0) {
                redmax[wn][wm * 32 + mt * 16 + ar]     = r0m;
                redmax[wn][wm * 32 + mt * 16 + ar + 8] = r1m;
            }
        }
        __syncthreads();

        float m_new[2][2];
#pragma unroll
        for (int mt = 0; mt < 2; mt++)
#pragma unroll
            for (int hh = 0; hh < 2; hh++) {
                const int row = wm * 32 + mt * 16 + ar + hh * 8;
                float mr = fmaxf(fmaxf(redmax[0][row], redmax[1][row]),
                                 fmaxf(redmax[2][row], redmax[3][row]));
                m_new[mt][hh] = fmaxf(m_st[mt][hh], mr);
                if (wn == 0 && ak == 0)
                    corrs[row] = ex2((m_st[mt][hh] - m_new[mt][hh]) * C);
            }

        // p = 2^((s-m)*C); write P into Ks; row partial sums
        float psum[2][2];
        psum[0][0] = psum[0][1] = psum[1][0] = psum[1][1] = 0.f;
#pragma unroll
        for (int mt = 0; mt < 2; mt++)
#pragma unroll
            for (int nt = 0; nt < 2; nt++) {
                const int colb = wn * 16 + nt * 8 + 2 * ak;
                float p0 = ex2((s[mt][nt][0] - m_new[mt][0]) * C);
                float p1 = ex2((s[mt][nt][1] - m_new[mt][0]) * C);
                float p2 = ex2((s[mt][nt][2] - m_new[mt][1]) * C);
                float p3 = ex2((s[mt][nt][3] - m_new[mt][1]) * C);
                psum[mt][0] += p0 + p1;
                psum[mt][1] += p2 + p3;
                const int r0 = wm * 32 + mt * 16 + ar;
                *(float2*)&Ks[r0][colb]     = make_float2(tf32r(p0), tf32r(p1));
                *(float2*)&Ks[r0 + 8][colb] = make_float2(tf32r(p2), tf32r(p3));
            }
#pragma unroll
        for (int mt = 0; mt < 2; mt++) {
            psum[mt][0] += __shfl_xor_sync(0xffffffffu, psum[mt][0], 1);
            psum[mt][0] += __shfl_xor_sync(0xffffffffu, psum[mt][0], 2);
            psum[mt][1] += __shfl_xor_sync(0xffffffffu, psum[mt][1], 1);
            psum[mt][1] += __shfl_xor_sync(0xffffffffu, psum[mt][1], 2);
            if (ak == 0) {
                redsum[wn][wm * 32 + mt * 16 + ar]     = psum[mt][0];
                redsum[wn][wm * 32 + mt * 16 + ar + 8] = psum[mt][1];
            }
        }
        __syncthreads();                       // P, redsum, corrs ready

        // state update + O rescale
        float corr[2][2];
#pragma unroll
        for (int mt = 0; mt < 2; mt++)
#pragma unroll
            for (int hh = 0; hh < 2; hh++) {
                const int row = wm * 32 + mt * 16 + ar + hh * 8;
                float sm = (redsum[0][row] + redsum[1][row]) + (redsum[2][row] + redsum[3][row]);
                corr[mt][hh] = corrs[row];
                l_st[mt][hh] = l_st[mt][hh] * corr[mt][hh] + sm;
                m_st[mt][hh] = m_new[mt][hh];
            }
#pragma unroll
        for (int mt = 0; mt < 2; mt++)
#pragma unroll
            for (int nt = 0; nt < 4; nt++) {
                o[mt][nt][0] *= corr[mt][0];
                o[mt][nt][1] *= corr[mt][0];
                o[mt][nt][2] *= corr[mt][1];
                o[mt][nt][3] *= corr[mt][1];
            }

        // O += P * V  (64x128, K=64); warp tile 32x32
#pragma unroll
        for (int ks = 0; ks < 64; ks += 8) {
            uint32_t a[2][4];
#pragma unroll
            for (int mt = 0; mt < 2; mt++) {
                const int mb = wm * 32 + mt * 16;
                a[mt][0] = __float_as_uint(Ks[mb + ar][ks + ak]);
                a[mt][1] = __float_as_uint(Ks[mb + ar + 8][ks + ak]);
                a[mt][2] = __float_as_uint(Ks[mb + ar][ks + ak + 4]);
                a[mt][3] = __float_as_uint(Ks[mb + ar + 8][ks + ak + 4]);
            }
#pragma unroll
            for (int nt = 0; nt < 4; nt++) {
                const int nb = wn * 32 + nt * 8;
                uint32_t b0 = __float_as_uint(Vs[ks + ak][nb + ar]);
                uint32_t b1 = __float_as_uint(Vs[ks + ak + 4][nb + ar]);
                mma_tf32(o[0][nt], a[0][0], a[0][1], a[0][2], a[0][3], b0, b1);
                mma_tf32(o[1][nt], a[1][0], a[1][1], a[1][2], a[1][3], b0, b1);
            }
        }
    }

    // epilogue: normalize and store
#pragma unroll
    for (int mt = 0; mt < 2; mt++) {
        const int r0 = wm * 32 + mt * 16 + ar;
        const float i0 = 1.f / l_st[mt][0];
        const float i1 = 1.f / l_st[mt][1];
        float* c0p = Ctx + (size_t)(qi * 64 + r0) * HID + h * DHEAD;
        float* c1p = c0p + 8 * HID;
#pragma unroll
        for (int nt = 0; nt < 4; nt++) {
            const int cb = wn * 32 + nt * 8 + 2 * ak;
            *(float2*)(c0p + cb) = make_float2(o[mt][nt][0] * i0, o[mt][nt][1] * i0);
            *(float2*)(c1p + cb) = make_float2(o[mt][nt][2] * i1, o[mt][nt][3] * i1);
        }
    }
}

// ---------------------------------------------------------------------------
// Fused per-(s,head) RMSNorm + RoPE, in place.
// ---------------------------------------------------------------------------
__global__ __launch_bounds__(128) void k_normrope(
    float* __restrict__ X, int rowstride,
    const float* __restrict__ sin_t, const float* __restrict__ cos_t,
    const float* __restrict__ w)
{
    const int s = blockIdx.x;
    const int h = blockIdx.y;
    const int d = threadIdx.x;
    float* row = X + (size_t)s * rowstride + h * DHEAD;
    float v = row[d];
    float ss = v * v;
#pragma unroll
    for (int o = 16; o > 0; o >>= 1) ss += __shfl_xor_sync(0xffffffffu, ss, o);
    __shared__ float wsum[4];
    if ((d & 31) == 0) wsum[d >> 5] = ss;
    __syncthreads();
    float tot = wsum[0] + wsum[1] + wsum[2] + wsum[3];
    float inv = rsqrtf(tot * (1.0f / 128.0f) + 1.1920928955078125e-07f);
    __shared__ float xn[128];
    float xv = v * inv * w[d];
    xn[d] = xv;
    __syncthreads();
    float rot = (d < 64) ? -xn[d + 64] : xn[d - 64];
    row[d] = cos_t[s * DHEAD + d] * xv + sin_t[s * DHEAD + d] * rot;
}

// ---------------------------------------------------------------------------
// Launch
// ---------------------------------------------------------------------------
extern "C" void kernel_launch(void* const* d_in, const int* in_sizes, int n_in,
                              void* d_out, int out_size)
{
    (void)in_sizes; (void)n_in; (void)out_size;
    const float* x     = (const float*)d_in[0];
    const float* sin_t = (const float*)d_in[1];
    const float* cos_t = (const float*)d_in[2];
    // d_in[3] = boolean causal mask: structure known, not needed
    const float* wq    = (const float*)d_in[4];
    const float* wk    = (const float*)d_in[5];
    const float* wv    = (const float*)d_in[6];
    const float* wo    = (const float*)d_in[7];
    const float* qnw   = (const float*)d_in[8];
    const float* knw   = (const float*)d_in[9];
    float* out = (float*)d_out;

    float *q, *k, *v, *ctx;
    cudaGetSymbolAddress((void**)&q,   g_q);
    cudaGetSymbolAddress((void**)&k,   g_k);
    cudaGetSymbolAddress((void**)&v,   g_v);
    cudaGetSymbolAddress((void**)&ctx, g_ctx);

    cudaFuncSetAttribute(k_flash, cudaFuncAttributeMaxDynamicSharedMemorySize, FLASH_SMEM);

    // Projections
    k_gemm_tn<<<dim3(HID / 128, SEQ / 128), 256>>>(x, HID, wq, HID, q, HID, HID);
    k_gemm_tn<<<dim3(KVW / 128, SEQ / 128), 256>>>(x, HID, wk, HID, k, KVW, HID);
    k_gemm_tn<<<dim3(KVW / 128, SEQ / 128), 256>>>(x, HID, wv, HID, v, KVW, HID);

    // RMSNorm + RoPE
    k_normrope<<<dim3(SEQ, NHEADS), 128>>>(q, HID, sin_t, cos_t, qnw);
    k_normrope<<<dim3(SEQ, NKVH),  128>>>(k, KVW, sin_t, cos_t, knw);

    // Fused flash attention (512 CTAs = 32 q-blocks x 16 heads)
    k_flash<<<512, 256, FLASH_SMEM>>>(q, k, v, ctx);

    // Output projection
    k_gemm_tn<<<dim3(HID / 128, SEQ / 128), 256>>>(ctx, HID, wo, HID, out, HID, HID);
}

// round 4
// speedup vs baseline: 3.1105x; 1.0830x over previous
#include <cuda_runtime.h>
#include <math.h>
#include <stddef.h>
#include <stdint.h>

// Problem constants (B=1)
#define SEQ   2048
#define HID   2048
#define NHEADS 16
#define NKVH   4
#define DHEAD  128
#define KVW   (NKVH * DHEAD)      // 512
#define GQA_REP (NHEADS / NKVH)   // 4

// Scratch
__device__ float g_q[SEQ * HID];                    // 16 MB (raw q proj; norm+rope fused in flash)
__device__ float g_k[SEQ * KVW];                    // 4 MB
__device__ float g_v[SEQ * KVW];                    // 4 MB
__device__ float g_ctx[SEQ * HID];                  // 16 MB

// ---------------------------------------------------------------------------
// helpers
// ---------------------------------------------------------------------------
__device__ __forceinline__ float tf32r(float x) {
    uint32_t u;
    asm("cvt.rna.tf32.f32 %0, %1;" : "=r"(u) : "f"(x));
    return __uint_as_float(u);
}
__device__ __forceinline__ float4 tf32r4(float4 v) {
    return make_float4(tf32r(v.x), tf32r(v.y), tf32r(v.z), tf32r(v.w));
}
__device__ __forceinline__ float ex2(float x) {
    float y;
    asm("ex2.approx.ftz.f32 %0, %1;" : "=f"(y) : "f"(x));
    return y;
}
__device__ __forceinline__ void mma_tf32(float c[4],
                                         uint32_t a0, uint32_t a1, uint32_t a2, uint32_t a3,
                                         uint32_t b0, uint32_t b1) {
    asm volatile(
        "mma.sync.aligned.m16n8k8.row.col.f32.tf32.tf32.f32 "
        "{%0,%1,%2,%3}, {%4,%5,%6,%7}, {%8,%9}, {%0,%1,%2,%3};"
        : "+f"(c[0]), "+f"(c[1]), "+f"(c[2]), "+f"(c[3])
        : "r"(a0), "r"(a1), "r"(a2), "r"(a3), "r"(b0), "r"(b1));
}

// ---------------------------------------------------------------------------
// TN GEMM (tensor core, double-buffered smem, 1 sync per 16-K chunk):
// C[bm:+128, bn:+128] = A[M,K] * B[N,K]^T
// ---------------------------------------------------------------------------
__device__ __forceinline__ void gemm_tn_tc(
    const float* __restrict__ A, int lda,
    const float* __restrict__ B, int ldb,
    float* __restrict__ C, int ldc,
    int K, int bm, int bn)
{
    __shared__ float As[2][128][20];
    __shared__ float Bs[2][128][20];
    const int tid  = threadIdx.x;
    const int lane = tid & 31;
    const int w    = tid >> 5;
    const int wm   = w >> 1;
    const int wn   = w & 1;
    const int lr   = tid >> 2;
    const int lc4  = (tid & 3) << 2;

    const float* Ap = A + (size_t)(bm + lr) * lda + lc4;
    const float* Bp = B + (size_t)(bn + lr) * ldb + lc4;

    float acc[2][8][4];
#pragma unroll
    for (int mt = 0; mt < 2; mt++)
#pragma unroll
        for (int nt = 0; nt < 8; nt++)
#pragma unroll
            for (int i = 0; i < 4; i++) acc[mt][nt][i] = 0.f;

    const int ar = lane >> 2;
    const int ak = lane & 3;

    // chunk 0 -> buf 0
    {
        float4 a0 = *(const float4*)Ap;
        float4 a1 = *(const float4*)(Ap + (size_t)64 * lda);
        float4 b0 = *(const float4*)Bp;
        float4 b1 = *(const float4*)(Bp + (size_t)64 * ldb);
        *(float4*)&As[0][lr][lc4]      = tf32r4(a0);
        *(float4*)&As[0][lr + 64][lc4] = tf32r4(a1);
        *(float4*)&Bs[0][lr][lc4]      = tf32r4(b0);
        *(float4*)&Bs[0][lr + 64][lc4] = tf32r4(b1);
    }
    __syncthreads();

    int cur = 0;
    for (int k0 = 0; k0 < K; k0 += 16) {
        const bool has_next = (k0 + 16) < K;
        float4 pa0, pa1, pb0, pb1;
        if (has_next) {
            Ap += 16; Bp += 16;
            pa0 = *(const float4*)Ap;
            pa1 = *(const float4*)(Ap + (size_t)64 * lda);
            pb0 = *(const float4*)Bp;
            pb1 = *(const float4*)(Bp + (size_t)64 * ldb);
        }
        const float (*Ac)[20] = As[cur];
        const float (*Bc)[20] = Bs[cur];
#pragma unroll
        for (int ks = 0; ks < 16; ks += 8) {
            uint32_t afr[2][4];
#pragma unroll
            for (int mt = 0; mt < 2; mt++) {
                const int mb = wm * 32 + mt * 16;
                afr[mt][0] = __float_as_uint(Ac[mb + ar][ks + ak]);
                afr[mt][1] = __float_as_uint(Ac[mb + ar + 8][ks + ak]);
                afr[mt][2] = __float_as_uint(Ac[mb + ar][ks + ak + 4]);
                afr[mt][3] = __float_as_uint(Ac[mb + ar + 8][ks + ak + 4]);
            }
#pragma unroll
            for (int nt = 0; nt < 8; nt++) {
                const int nb = wn * 64 + nt * 8;
                uint32_t b0 = __float_as_uint(Bc[nb + ar][ks + ak]);
                uint32_t b1 = __float_as_uint(Bc[nb + ar][ks + ak + 4]);
                mma_tf32(acc[0][nt], afr[0][0], afr[0][1], afr[0][2], afr[0][3], b0, b1);
                mma_tf32(acc[1][nt], afr[1][0], afr[1][1], afr[1][2], afr[1][3], b0, b1);
            }
        }
        if (has_next) {
            const int nxt = cur ^ 1;
            *(float4*)&As[nxt][lr][lc4]      = tf32r4(pa0);
            *(float4*)&As[nxt][lr + 64][lc4] = tf32r4(pa1);
            *(float4*)&Bs[nxt][lr][lc4]      = tf32r4(pb0);
            *(float4*)&Bs[nxt][lr + 64][lc4] = tf32r4(pb1);
            __syncthreads();
        }
        cur ^= 1;
    }

#pragma unroll
    for (int mt = 0; mt < 2; mt++) {
        const int r0 = bm + wm * 32 + mt * 16 + ar;
#pragma unroll
        for (int nt = 0; nt < 8; nt++) {
            const int cidx = bn + wn * 64 + nt * 8 + 2 * ak;
            *(float2*)(C + (size_t)r0 * ldc + cidx)       = make_float2(acc[mt][nt][0], acc[mt][nt][1]);
            *(float2*)(C + (size_t)(r0 + 8) * ldc + cidx) = make_float2(acc[mt][nt][2], acc[mt][nt][3]);
        }
    }
}

__global__ __launch_bounds__(256, 2) void k_gemm_tn(
    const float* __restrict__ A, int lda,
    const float* __restrict__ B, int ldb,
    float* __restrict__ C, int ldc, int K)
{
    gemm_tn_tc(A, lda, B, ldb, C, ldc, K, blockIdx.y * 128, blockIdx.x * 128);
}

// ---------------------------------------------------------------------------
// Fused flash attention with Q RMSNorm+RoPE at load time.
// ---------------------------------------------------------------------------
#define QS_OFF   0
#define KS_OFF   (64 * 132 * 4)               // 33792
#define VS_OFF   (KS_OFF + 64 * 132 * 4)      // 67584
#define RMX_OFF  (VS_OFF + 64 * 136 * 4)      // 102400
#define RSM_OFF  (RMX_OFF + 4 * 64 * 4)       // 103424
#define CRR_OFF  (RSM_OFF + 4 * 64 * 4)       // 104448
#define FLASH_SMEM (CRR_OFF + 64 * 4)         // 104704

__global__ __launch_bounds__(256, 2) void k_flash(
    const float* __restrict__ Qg, const float* __restrict__ Kg,
    const float* __restrict__ Vg, float* __restrict__ Ctx,
    const float* __restrict__ sin_t, const float* __restrict__ cos_t,
    const float* __restrict__ qnw)
{
    extern __shared__ char smem[];
    float (*Qs)[132]    = (float(*)[132])(smem + QS_OFF);
    float (*Ks)[132]    = (float(*)[132])(smem + KS_OFF);   // doubles as P
    float (*Vs)[136]    = (float(*)[136])(smem + VS_OFF);
    float (*redmax)[64] = (float(*)[64])(smem + RMX_OFF);
    float (*redsum)[64] = (float(*)[64])(smem + RSM_OFF);
    float* corrs        = (float*)(smem + CRR_OFF);

    const int bid = blockIdx.x;
    const int h   = bid & 15;
    const int qi  = 31 - (bid >> 4);          // longest blocks first
    const int kvh = h >> 2;

    const int tid  = threadIdx.x;
    const int lane = tid & 31;
    const int w    = tid >> 5;
    const int wm   = w >> 2;
    const int wn   = w & 3;
    const int ar   = lane >> 2;
    const int ak   = lane & 3;
    const float C  = (float)(0.08838834764831843 * 1.4426950408889634); // scale*log2e

    // Q tile [64 x 128]: load raw q, fuse RMSNorm + RoPE, write tf32 to Qs.
    // Threads 4r..4r+3 cooperatively own row r; thread covers cols c0+16*i.
    {
        const int r  = tid >> 2;
        const int c0 = (tid & 3) << 2;
        const int s  = qi * 64 + r;
        const float* qp = Qg + (size_t)s * HID + h * DHEAD;
        float4 qa[8];
        float ss = 0.f;
#pragma unroll
        for (int i = 0; i < 8; i++) {
            qa[i] = *(const float4*)(qp + c0 + 16 * i);
            ss += qa[i].x * qa[i].x + qa[i].y * qa[i].y + qa[i].z * qa[i].z + qa[i].w * qa[i].w;
        }
        ss += __shfl_xor_sync(0xffffffffu, ss, 1);
        ss += __shfl_xor_sync(0xffffffffu, ss, 2);
        const float inv = rsqrtf(ss * (1.0f / 128.0f) + 1.1920928955078125e-07f);
        float4 xn[8];
#pragma unroll
        for (int i = 0; i < 8; i++) {
            float4 wv4 = *(const float4*)(qnw + c0 + 16 * i);
            xn[i] = make_float4(qa[i].x * inv * wv4.x, qa[i].y * inv * wv4.y,
                                qa[i].z * inv * wv4.z, qa[i].w * inv * wv4.w);
        }
        const float* sp = sin_t + (size_t)s * DHEAD;
        const float* cp = cos_t + (size_t)s * DHEAD;
#pragma unroll
        for (int i = 0; i < 8; i++) {
            const int c = c0 + 16 * i;
            float4 s4 = *(const float4*)(sp + c);
            float4 c4 = *(const float4*)(cp + c);
            float4 rot = (i < 4)
                ? make_float4(-xn[i + 4].x, -xn[i + 4].y, -xn[i + 4].z, -xn[i + 4].w)
                : xn[i - 4];
            float4 o4 = make_float4(c4.x * xn[i].x + s4.x * rot.x,
                                    c4.y * xn[i].y + s4.y * rot.y,
                                    c4.z * xn[i].z + s4.z * rot.z,
                                    c4.w * xn[i].w + s4.w * rot.w);
            *(float4*)&Qs[r][c] = tf32r4(o4);
        }
    }

    float o[2][4][4];
    float m_st[2][2], l_st[2][2];
#pragma unroll
    for (int mt = 0; mt < 2; mt++) {
#pragma unroll
        for (int nt = 0; nt < 4; nt++)
#pragma unroll
            for (int c = 0; c < 4; c++) o[mt][nt][c] = 0.f;
        m_st[mt][0] = m_st[mt][1] = -1e30f;
        l_st[mt][0] = l_st[mt][1] = 0.f;
    }

    const int nkb = qi + 1;
    for (int j = 0; j < nkb; j++) {
        __syncthreads();
        {
            const int r  = tid >> 2;
            const int c0 = (tid & 3) << 2;
            const float* kp = Kg + (size_t)(j * 64 + r) * KVW + kvh * DHEAD + c0;
            const float* vp = Vg + (size_t)(j * 64 + r) * KVW + kvh * DHEAD + c0;
#pragma unroll
            for (int i = 0; i < 8; i++) {
                *(float4*)&Ks[r][c0 + 16 * i] = tf32r4(*(const float4*)(kp + 16 * i));
                *(float4*)&Vs[r][c0 + 16 * i] = tf32r4(*(const float4*)(vp + 16 * i));
            }
        }
        __syncthreads();

        // S = Q*K^T
        float s[2][2][4];
#pragma unroll
        for (int mt = 0; mt < 2; mt++)
#pragma unroll
            for (int nt = 0; nt < 2; nt++)
#pragma unroll
                for (int c = 0; c < 4; c++) s[mt][nt][c] = 0.f;
#pragma unroll
        for (int ks = 0; ks < 128; ks += 8) {
            uint32_t a[2][4];
#pragma unroll
            for (int mt = 0; mt < 2; mt++) {
                const int mb = wm * 32 + mt * 16;
                a[mt][0] = __float_as_uint(Qs[mb + ar][ks + ak]);
                a[mt][1] = __float_as_uint(Qs[mb + ar + 8][ks + ak]);
                a[mt][2] = __float_as_uint(Qs[mb + ar][ks + ak + 4]);
                a[mt][3] = __float_as_uint(Qs[mb + ar + 8][ks + ak + 4]);
            }
#pragma unroll
            for (int nt = 0; nt < 2; nt++) {
                const int nb = wn * 16 + nt * 8;
                uint32_t b0 = __float_as_uint(Ks[nb + ar][ks + ak]);
                uint32_t b1 = __float_as_uint(Ks[nb + ar][ks + ak + 4]);
                mma_tf32(s[0][nt], a[0][0], a[0][1], a[0][2], a[0][3], b0, b1);
                mma_tf32(s[1][nt], a[1][0], a[1][1], a[1][2], a[1][3], b0, b1);
            }
        }

        if (j == qi) {
#pragma unroll
            for (int mt = 0; mt < 2; mt++)
#pragma unroll
                for (int nt = 0; nt < 2; nt++) {
                    const int colb = wn * 16 + nt * 8 + 2 * ak;
#pragma unroll
                    for (int cc = 0; cc < 4; cc++) {
                        const int row_l = wm * 32 + mt * 16 + ar + (cc >> 1) * 8;
                        const int col_l = colb + (cc & 1);
                        if (col_l > row_l) s[mt][nt][cc] = -1e30f;
                    }
                }
        }

#pragma unroll
        for (int mt = 0; mt < 2; mt++) {
            float r0m = fmaxf(fmaxf(s[mt][0][0], s[mt][0][1]), fmaxf(s[mt][1][0], s[mt][1][1]));
            float r1m = fmaxf(fmaxf(s[mt][0][2], s[mt][0][3]), fmaxf(s[mt][1][2], s[mt][1][3]));
            r0m = fmaxf(r0m, __shfl_xor_sync(0xffffffffu, r0m, 1));
            r0m = fmaxf(r0m, __shfl_xor_sync(0xffffffffu, r0m, 2));
            r1m = fmaxf(r1m, __shfl_xor_sync(0xffffffffu, r1m, 1));
            r1m = fmaxf(r1m, __shfl_xor_sync(0xffffffffu, r1m, 2));
            if (ak == 0) {
                redmax[wn][wm * 32 + mt * 16 + ar]     = r0m;
                redmax[wn][wm * 32 + mt * 16 + ar + 8] = r1m;
            }
        }
        __syncthreads();

        float m_new[2][2];
#pragma unroll
        for (int mt = 0; mt < 2; mt++)
#pragma unroll
            for (int hh = 0; hh < 2; hh++) {
                const int row = wm * 32 + mt * 16 + ar + hh * 8;
                float mr = fmaxf(fmaxf(redmax[0][row], redmax[1][row]),
                                 fmaxf(redmax[2][row], redmax[3][row]));
                m_new[mt][hh] = fmaxf(m_st[mt][hh], mr);
                if (wn == 0 && ak == 0)
                    corrs[row] = ex2((m_st[mt][hh] - m_new[mt][hh]) * C);
            }

        float psum[2][2];
        psum[0][0] = psum[0][1] = psum[1][0] = psum[1][1] = 0.f;
#pragma unroll
        for (int mt = 0; mt < 2; mt++)
#pragma unroll
            for (int nt = 0; nt < 2; nt++) {
                const int colb = wn * 16 + nt * 8 + 2 * ak;
                float p0 = ex2((s[mt][nt][0] - m_new[mt][0]) * C);
                float p1 = ex2((s[mt][nt][1] - m_new[mt][0]) * C);
                float p2 = ex2((s[mt][nt][2] - m_new[mt][1]) * C);
                float p3 = ex2((s[mt][nt][3] - m_new[mt][1]) * C);
                psum[mt][0] += p0 + p1;
                psum[mt][1] += p2 + p3;
                const int r0 = wm * 32 + mt * 16 + ar;
                *(float2*)&Ks[r0][colb]     = make_float2(tf32r(p0), tf32r(p1));
                *(float2*)&Ks[r0 + 8][colb] = make_float2(tf32r(p2), tf32r(p3));
            }
#pragma unroll
        for (int mt = 0; mt < 2; mt++) {
            psum[mt][0] += __shfl_xor_sync(0xffffffffu, psum[mt][0], 1);
            psum[mt][0] += __shfl_xor_sync(0xffffffffu, psum[mt][0], 2);
            psum[mt][1] += __shfl_xor_sync(0xffffffffu, psum[mt][1], 1);
            psum[mt][1] += __shfl_xor_sync(0xffffffffu, psum[mt][1], 2);
            if (ak == 0) {
                redsum[wn][wm * 32 + mt * 16 + ar]     = psum[mt][0];
                redsum[wn][wm * 32 + mt * 16 + ar + 8] = psum[mt][1];
            }
        }
        __syncthreads();

        float corr[2][2];
#pragma unroll
        for (int mt = 0; mt < 2; mt++)
#pragma unroll
            for (int hh = 0; hh < 2; hh++) {
                const int row = wm * 32 + mt * 16 + ar + hh * 8;
                float sm = (redsum[0][row] + redsum[1][row]) + (redsum[2][row] + redsum[3][row]);
                corr[mt][hh] = corrs[row];
                l_st[mt][hh] = l_st[mt][hh] * corr[mt][hh] + sm;
                m_st[mt][hh] = m_new[mt][hh];
            }
#pragma unroll
        for (int mt = 0; mt < 2; mt++)
#pragma unroll
            for (int nt = 0; nt < 4; nt++) {
                o[mt][nt][0] *= corr[mt][0];
                o[mt][nt][1] *= corr[mt][0];
                o[mt][nt][2] *= corr[mt][1];
                o[mt][nt][3] *= corr[mt][1];
            }

        // O += P * V
#pragma unroll
        for (int ks = 0; ks < 64; ks += 8) {
            uint32_t a[2][4];
#pragma unroll
            for (int mt = 0; mt < 2; mt++) {
                const int mb = wm * 32 + mt * 16;
                a[mt][0] = __float_as_uint(Ks[mb + ar][ks + ak]);
                a[mt][1] = __float_as_uint(Ks[mb + ar + 8][ks + ak]);
                a[mt][2] = __float_as_uint(Ks[mb + ar][ks + ak + 4]);
                a[mt][3] = __float_as_uint(Ks[mb + ar + 8][ks + ak + 4]);
            }
#pragma unroll
            for (int nt = 0; nt < 4; nt++) {
                const int nb = wn * 32 + nt * 8;
                uint32_t b0 = __float_as_uint(Vs[ks + ak][nb + ar]);
                uint32_t b1 = __float_as_uint(Vs[ks + ak + 4][nb + ar]);
                mma_tf32(o[0][nt], a[0][0], a[0][1], a[0][2], a[0][3], b0, b1);
                mma_tf32(o[1][nt], a[1][0], a[1][1], a[1][2], a[1][3], b0, b1);
            }
        }
    }

#pragma unroll
    for (int mt = 0; mt < 2; mt++) {
        const int r0 = wm * 32 + mt * 16 + ar;
        const float i0 = 1.f / l_st[mt][0];
        const float i1 = 1.f / l_st[mt][1];
        float* c0p = Ctx + (size_t)(qi * 64 + r0) * HID + h * DHEAD;
        float* c1p = c0p + 8 * HID;
#pragma unroll
        for (int nt = 0; nt < 4; nt++) {
            const int cb = wn * 32 + nt * 8 + 2 * ak;
            *(float2*)(c0p + cb) = make_float2(o[mt][nt][0] * i0, o[mt][nt][1] * i0);
            *(float2*)(c1p + cb) = make_float2(o[mt][nt][2] * i1, o[mt][nt][3] * i1);
        }
    }
}

// ---------------------------------------------------------------------------
// Per-(s,kvhead) RMSNorm + RoPE for K, in place.
// ---------------------------------------------------------------------------
__global__ __launch_bounds__(128) void k_normrope(
    float* __restrict__ X, int rowstride,
    const float* __restrict__ sin_t, const float* __restrict__ cos_t,
    const float* __restrict__ w)
{
    const int s = blockIdx.x;
    const int h = blockIdx.y;
    const int d = threadIdx.x;
    float* row = X + (size_t)s * rowstride + h * DHEAD;
    float v = row[d];
    float ss = v * v;
#pragma unroll
    for (int o = 16; o > 0; o >>= 1) ss += __shfl_xor_sync(0xffffffffu, ss, o);
    __shared__ float wsum[4];
    if ((d & 31) == 0) wsum[d >> 5] = ss;
    __syncthreads();
    float tot = wsum[0] + wsum[1] + wsum[2] + wsum[3];
    float inv = rsqrtf(tot * (1.0f / 128.0f) + 1.1920928955078125e-07f);
    __shared__ float xn[128];
    float xv = v * inv * w[d];
    xn[d] = xv;
    __syncthreads();
    float rot = (d < 64) ? -xn[d + 64] : xn[d - 64];
    row[d] = cos_t[s * DHEAD + d] * xv + sin_t[s * DHEAD + d] * rot;
}

// ---------------------------------------------------------------------------
// Launch
// ---------------------------------------------------------------------------
extern "C" void kernel_launch(void* const* d_in, const int* in_sizes, int n_in,
                              void* d_out, int out_size)
{
    (void)in_sizes; (void)n_in; (void)out_size;
    const float* x     = (const float*)d_in[0];
    const float* sin_t = (const float*)d_in[1];
    const float* cos_t = (const float*)d_in[2];
    // d_in[3] = boolean causal mask: structure known, not needed
    const float* wq    = (const float*)d_in[4];
    const float* wk    = (const float*)d_in[5];
    const float* wv    = (const float*)d_in[6];
    const float* wo    = (const float*)d_in[7];
    const float* qnw   = (const float*)d_in[8];
    const float* knw   = (const float*)d_in[9];
    float* out = (float*)d_out;

    float *q, *k, *v, *ctx;
    cudaGetSymbolAddress((void**)&q,   g_q);
    cudaGetSymbolAddress((void**)&k,   g_k);
    cudaGetSymbolAddress((void**)&v,   g_v);
    cudaGetSymbolAddress((void**)&ctx, g_ctx);

    cudaFuncSetAttribute(k_flash, cudaFuncAttributeMaxDynamicSharedMemorySize, FLASH_SMEM);

    // Projections
    k_gemm_tn<<<dim3(HID / 128, SEQ / 128), 256>>>(x, HID, wq, HID, q, HID, HID);
    k_gemm_tn<<<dim3(KVW / 128, SEQ / 128), 256>>>(x, HID, wk, HID, k, KVW, HID);
    k_gemm_tn<<<dim3(KVW / 128, SEQ / 128), 256>>>(x, HID, wv, HID, v, KVW, HID);

    // RMSNorm + RoPE for K only (Q's is fused into k_flash)
    k_normrope<<<dim3(SEQ, NKVH), 128>>>(k, KVW, sin_t, cos_t, knw);

    // Fused flash attention (512 CTAs = 32 q-blocks x 16 heads)
    k_flash<<<512, 256, FLASH_SMEM>>>(q, k, v, ctx, sin_t, cos_t, qnw);

    // Output projection
    k_gemm_tn<<<dim3(HID / 128, SEQ / 128), 256>>>(ctx, HID, wo, HID, out, HID, HID);
}

// round 5
// speedup vs baseline: 3.3727x; 1.0843x over previous
#include <cuda_runtime.h>
#include <math.h>
#include <stddef.h>
#include <stdint.h>

// Problem constants (B=1)
#define SEQ   2048
#define HID   2048
#define NHEADS 16
#define NKVH   4
#define DHEAD  128
#define KVW   (NKVH * DHEAD)      // 512
#define GQA_REP (NHEADS / NKVH)   // 4

// Scratch
__device__ float g_q[SEQ * HID];                    // raw q proj (norm+rope fused in flash)
__device__ float g_k[SEQ * KVW];
__device__ float g_v[SEQ * KVW];
__device__ float g_ctx[SEQ * HID];

// ---------------------------------------------------------------------------
// helpers
// ---------------------------------------------------------------------------
__device__ __forceinline__ float tf32r(float x) {
    uint32_t u;
    asm("cvt.rna.tf32.f32 %0, %1;" : "=r"(u) : "f"(x));
    return __uint_as_float(u);
}
__device__ __forceinline__ float4 tf32r4(float4 v) {
    return make_float4(tf32r(v.x), tf32r(v.y), tf32r(v.z), tf32r(v.w));
}
__device__ __forceinline__ float ex2(float x) {
    float y;
    asm("ex2.approx.ftz.f32 %0, %1;" : "=f"(y) : "f"(x));
    return y;
}
// 2^x on the FMA pipe (x <= 0, masked values reach ~-1e29 -> clamps to ~0)
__device__ __forceinline__ float exp2poly(float x) {
    const float MAGIC = 12582912.f;            // 2^23 + 2^22
    float t = fmaxf(x, -126.f);
    float r = t + MAGIC;
    float n = r - MAGIC;                        // rint(t)
    float f = t - n;                            // [-0.5, 0.5]
    float p = 1.3333558146e-3f;
    p = fmaf(p, f, 9.6181291076e-3f);
    p = fmaf(p, f, 5.5504108664e-2f);
    p = fmaf(p, f, 2.4022650696e-1f);
    p = fmaf(p, f, 6.9314718056e-1f);
    p = fmaf(p, f, 1.0f);
    int sb = (__float_as_int(r) << 23) + (127 << 23);
    return p * __int_as_float(sb);
}
__device__ __forceinline__ void mma_tf32(float c[4],
                                         uint32_t a0, uint32_t a1, uint32_t a2, uint32_t a3,
                                         uint32_t b0, uint32_t b1) {
    asm volatile(
        "mma.sync.aligned.m16n8k8.row.col.f32.tf32.tf32.f32 "
        "{%0,%1,%2,%3}, {%4,%5,%6,%7}, {%8,%9}, {%0,%1,%2,%3};"
        : "+f"(c[0]), "+f"(c[1]), "+f"(c[2]), "+f"(c[3])
        : "r"(a0), "r"(a1), "r"(a2), "r"(a3), "r"(b0), "r"(b1));
}
__device__ __forceinline__ void ldsm_x4(uint32_t& r0, uint32_t& r1, uint32_t& r2, uint32_t& r3,
                                        uint32_t addr) {
    asm volatile("ldmatrix.sync.aligned.m8n8.x4.shared.b16 {%0,%1,%2,%3}, [%4];"
                 : "=r"(r0), "=r"(r1), "=r"(r2), "=r"(r3) : "r"(addr));
}

// per-lane ldmatrix byte offsets (A-pattern: rows = m/n index of fragment owner)
// A x4: mat0 rows +0..7 col ks, mat1 rows+8, mat2 col ks+4, mat3 rows+8 col ks+4
__device__ __forceinline__ uint32_t ldsmA_off(int lane, int stride_bytes) {
    return (uint32_t)((lane & 15) * stride_bytes + (((lane >> 4) & 1) << 4));
}
// B x4 (2 n8-tiles): mat0 rows nb+0..7 col ks, mat1 same rows col ks+4,
//                    mat2 rows nb+8..15 col ks, mat3 rows+8 col ks+4
__device__ __forceinline__ uint32_t ldsmB_off(int lane, int stride_bytes) {
    int row = (lane & 7) + ((lane & 16) >> 1);
    return (uint32_t)(row * stride_bytes + (((lane >> 3) & 1) << 4));
}

// ---------------------------------------------------------------------------
// TN GEMM (tensor core, double-buffered, ldmatrix fragments):
// C[bm:+128, bn:+128] = A[M,K] * B[N,K]^T
// ---------------------------------------------------------------------------
#define PSTR 20                     // smem row stride (floats): 16 K + 4 pad
#define PSTRB (PSTR * 4)

__device__ __forceinline__ void gemm_tn_tc(
    const float* __restrict__ A, int lda,
    const float* __restrict__ B, int ldb,
    float* __restrict__ C, int ldc,
    int K, int bm, int bn)
{
    __shared__ float As[2][128][PSTR];
    __shared__ float Bs[2][128][PSTR];
    const int tid  = threadIdx.x;
    const int lane = tid & 31;
    const int w    = tid >> 5;
    const int wm   = w >> 1;
    const int wn   = w & 1;
    const int lr   = tid >> 2;
    const int lc4  = (tid & 3) << 2;

    const float* Ap = A + (size_t)(bm + lr) * lda + lc4;
    const float* Bp = B + (size_t)(bn + lr) * ldb + lc4;

    float acc[2][8][4];
#pragma unroll
    for (int mt = 0; mt < 2; mt++)
#pragma unroll
        for (int nt = 0; nt < 8; nt++)
#pragma unroll
            for (int i = 0; i < 4; i++) acc[mt][nt][i] = 0.f;

    const uint32_t as0 = (uint32_t)__cvta_generic_to_shared(&As[0][0][0]);
    const uint32_t as1 = (uint32_t)__cvta_generic_to_shared(&As[1][0][0]);
    const uint32_t bs0 = (uint32_t)__cvta_generic_to_shared(&Bs[0][0][0]);
    const uint32_t bs1 = (uint32_t)__cvta_generic_to_shared(&Bs[1][0][0]);
    const uint32_t aoff = ldsmA_off(lane, PSTRB) + (uint32_t)(wm * 32) * PSTRB;
    const uint32_t boff = ldsmB_off(lane, PSTRB) + (uint32_t)(wn * 64) * PSTRB;

    // chunk 0 -> buf 0
    {
        float4 a0 = *(const float4*)Ap;
        float4 a1 = *(const float4*)(Ap + (size_t)64 * lda);
        float4 b0 = *(const float4*)Bp;
        float4 b1 = *(const float4*)(Bp + (size_t)64 * ldb);
        *(float4*)&As[0][lr][lc4]      = tf32r4(a0);
        *(float4*)&As[0][lr + 64][lc4] = tf32r4(a1);
        *(float4*)&Bs[0][lr][lc4]      = tf32r4(b0);
        *(float4*)&Bs[0][lr + 64][lc4] = tf32r4(b1);
    }
    __syncthreads();

    int cur = 0;
    for (int k0 = 0; k0 < K; k0 += 16) {
        const bool has_next = (k0 + 16) < K;
        float4 pa0, pa1, pb0, pb1;
        if (has_next) {
            Ap += 16; Bp += 16;
            pa0 = *(const float4*)Ap;
            pa1 = *(const float4*)(Ap + (size_t)64 * lda);
            pb0 = *(const float4*)Bp;
            pb1 = *(const float4*)(Bp + (size_t)64 * ldb);
        }
        const uint32_t ab = (cur ? as1 : as0) + aoff;
        const uint32_t bb = (cur ? bs1 : bs0) + boff;
#pragma unroll
        for (int ks = 0; ks < 16; ks += 8) {
            uint32_t a[2][4];
            ldsm_x4(a[0][0], a[0][1], a[0][2], a[0][3], ab + ks * 4);
            ldsm_x4(a[1][0], a[1][1], a[1][2], a[1][3], ab + 16 * PSTRB + ks * 4);
#pragma unroll
            for (int pr = 0; pr < 4; pr++) {
                uint32_t b0, b1, b2, b3;
                ldsm_x4(b0, b1, b2, b3, bb + (uint32_t)pr * 16 * PSTRB + ks * 4);
                mma_tf32(acc[0][2 * pr],     a[0][0], a[0][1], a[0][2], a[0][3], b0, b1);
                mma_tf32(acc[1][2 * pr],     a[1][0], a[1][1], a[1][2], a[1][3], b0, b1);
                mma_tf32(acc[0][2 * pr + 1], a[0][0], a[0][1], a[0][2], a[0][3], b2, b3);
                mma_tf32(acc[1][2 * pr + 1], a[1][0], a[1][1], a[1][2], a[1][3], b2, b3);
            }
        }
        if (has_next) {
            const int nxt = cur ^ 1;
            *(float4*)&As[nxt][lr][lc4]      = tf32r4(pa0);
            *(float4*)&As[nxt][lr + 64][lc4] = tf32r4(pa1);
            *(float4*)&Bs[nxt][lr][lc4]      = tf32r4(pb0);
            *(float4*)&Bs[nxt][lr + 64][lc4] = tf32r4(pb1);
            __syncthreads();
        }
        cur ^= 1;
    }

    const int ar = lane >> 2;
    const int ak = lane & 3;
#pragma unroll
    for (int mt = 0; mt < 2; mt++) {
        const int r0 = bm + wm * 32 + mt * 16 + ar;
#pragma unroll
        for (int nt = 0; nt < 8; nt++) {
            const int cidx = bn + wn * 64 + nt * 8 + 2 * ak;
            *(float2*)(C + (size_t)r0 * ldc + cidx)       = make_float2(acc[mt][nt][0], acc[mt][nt][1]);
            *(float2*)(C + (size_t)(r0 + 8) * ldc + cidx) = make_float2(acc[mt][nt][2], acc[mt][nt][3]);
        }
    }
}

__global__ __launch_bounds__(256, 2) void k_gemm_tn(
    const float* __restrict__ A, int lda,
    const float* __restrict__ B, int ldb,
    float* __restrict__ C, int ldc, int K)
{
    gemm_tn_tc(A, lda, B, ldb, C, ldc, K, blockIdx.y * 128, blockIdx.x * 128);
}

// ---------------------------------------------------------------------------
// Fused flash attention with Q RMSNorm+RoPE at load time; ldmatrix fragments;
// hybrid MUFU/FMA-poly softmax exp.
// ---------------------------------------------------------------------------
#define FSTR 132                              // Qs/Ks row stride (floats)
#define FSTRB (FSTR * 4)
#define QS_OFF   0
#define KS_OFF   (64 * FSTR * 4)              // 33792
#define VS_OFF   (KS_OFF + 64 * FSTR * 4)     // 67584
#define RMX_OFF  (VS_OFF + 64 * 136 * 4)      // 102400
#define RSM_OFF  (RMX_OFF + 4 * 64 * 4)
#define CRR_OFF  (RSM_OFF + 4 * 64 * 4)
#define FLASH_SMEM (CRR_OFF + 64 * 4)         // 104704

__global__ __launch_bounds__(256, 2) void k_flash(
    const float* __restrict__ Qg, const float* __restrict__ Kg,
    const float* __restrict__ Vg, float* __restrict__ Ctx,
    const float* __restrict__ sin_t, const float* __restrict__ cos_t,
    const float* __restrict__ qnw)
{
    extern __shared__ char smem[];
    float (*Qs)[FSTR]   = (float(*)[FSTR])(smem + QS_OFF);
    float (*Ks)[FSTR]   = (float(*)[FSTR])(smem + KS_OFF);   // doubles as P
    float (*Vs)[136]    = (float(*)[136])(smem + VS_OFF);
    float (*redmax)[64] = (float(*)[64])(smem + RMX_OFF);
    float (*redsum)[64] = (float(*)[64])(smem + RSM_OFF);
    float* corrs        = (float*)(smem + CRR_OFF);

    const int bid = blockIdx.x;
    const int h   = bid & 15;
    const int qi  = 31 - (bid >> 4);          // longest blocks first
    const int kvh = h >> 2;

    const int tid  = threadIdx.x;
    const int lane = tid & 31;
    const int w    = tid >> 5;
    const int wm   = w >> 2;
    const int wn   = w & 3;
    const int ar   = lane >> 2;
    const int ak   = lane & 3;
    const float C  = (float)(0.08838834764831843 * 1.4426950408889634); // scale*log2e

    const uint32_t qsb = (uint32_t)__cvta_generic_to_shared(&Qs[0][0]);
    const uint32_t ksb = (uint32_t)__cvta_generic_to_shared(&Ks[0][0]);
    const uint32_t aoff = ldsmA_off(lane, FSTRB) + (uint32_t)(wm * 32) * FSTRB;
    const uint32_t boff = ldsmB_off(lane, FSTRB) + (uint32_t)(wn * 16) * FSTRB;

    // Q tile [64 x 128]: load raw q, fuse RMSNorm + RoPE, write tf32 to Qs.
    {
        const int r  = tid >> 2;
        const int c0 = (tid & 3) << 2;
        const int s  = qi * 64 + r;
        const float* qp = Qg + (size_t)s * HID + h * DHEAD;
        float4 qa[8];
        float ss = 0.f;
#pragma unroll
        for (int i = 0; i < 8; i++) {
            qa[i] = *(const float4*)(qp + c0 + 16 * i);
            ss += qa[i].x * qa[i].x + qa[i].y * qa[i].y + qa[i].z * qa[i].z + qa[i].w * qa[i].w;
        }
        ss += __shfl_xor_sync(0xffffffffu, ss, 1);
        ss += __shfl_xor_sync(0xffffffffu, ss, 2);
        const float inv = rsqrtf(ss * (1.0f / 128.0f) + 1.1920928955078125e-07f);
        float4 xn[8];
#pragma unroll
        for (int i = 0; i < 8; i++) {
            float4 wv4 = *(const float4*)(qnw + c0 + 16 * i);
            xn[i] = make_float4(qa[i].x * inv * wv4.x, qa[i].y * inv * wv4.y,
                                qa[i].z * inv * wv4.z, qa[i].w * inv * wv4.w);
        }
        const float* sp = sin_t + (size_t)s * DHEAD;
        const float* cp = cos_t + (size_t)s * DHEAD;
#pragma unroll
        for (int i = 0; i < 8; i++) {
            const int c = c0 + 16 * i;
            float4 s4 = *(const float4*)(sp + c);
            float4 c4 = *(const float4*)(cp + c);
            float4 rot = (i < 4)
                ? make_float4(-xn[i + 4].x, -xn[i + 4].y, -xn[i + 4].z, -xn[i + 4].w)
                : xn[i - 4];
            float4 o4 = make_float4(c4.x * xn[i].x + s4.x * rot.x,
                                    c4.y * xn[i].y + s4.y * rot.y,
                                    c4.z * xn[i].z + s4.z * rot.z,
                                    c4.w * xn[i].w + s4.w * rot.w);
            *(float4*)&Qs[r][c] = tf32r4(o4);
        }
    }

    float o[2][4][4];
    float m_st[2][2], l_st[2][2];
#pragma unroll
    for (int mt = 0; mt < 2; mt++) {
#pragma unroll
        for (int nt = 0; nt < 4; nt++)
#pragma unroll
            for (int c = 0; c < 4; c++) o[mt][nt][c] = 0.f;
        m_st[mt][0] = m_st[mt][1] = -1e30f;
        l_st[mt][0] = l_st[mt][1] = 0.f;
    }

    const int nkb = qi + 1;
    for (int j = 0; j < nkb; j++) {
        __syncthreads();
        {
            const int r  = tid >> 2;
            const int c0 = (tid & 3) << 2;
            const float* kp = Kg + (size_t)(j * 64 + r) * KVW + kvh * DHEAD + c0;
            const float* vp = Vg + (size_t)(j * 64 + r) * KVW + kvh * DHEAD + c0;
#pragma unroll
            for (int i = 0; i < 8; i++) {
                *(float4*)&Ks[r][c0 + 16 * i] = tf32r4(*(const float4*)(kp + 16 * i));
                *(float4*)&Vs[r][c0 + 16 * i] = tf32r4(*(const float4*)(vp + 16 * i));
            }
        }
        __syncthreads();

        // S = Q*K^T  (ldmatrix both operands)
        float s[2][2][4];
#pragma unroll
        for (int mt = 0; mt < 2; mt++)
#pragma unroll
            for (int nt = 0; nt < 2; nt++)
#pragma unroll
                for (int c = 0; c < 4; c++) s[mt][nt][c] = 0.f;
#pragma unroll
        for (int ks = 0; ks < 128; ks += 8) {
            uint32_t a[2][4];
            ldsm_x4(a[0][0], a[0][1], a[0][2], a[0][3], qsb + aoff + ks * 4);
            ldsm_x4(a[1][0], a[1][1], a[1][2], a[1][3], qsb + aoff + 16 * FSTRB + ks * 4);
            uint32_t b0, b1, b2, b3;
            ldsm_x4(b0, b1, b2, b3, ksb + boff + ks * 4);
            mma_tf32(s[0][0], a[0][0], a[0][1], a[0][2], a[0][3], b0, b1);
            mma_tf32(s[1][0], a[1][0], a[1][1], a[1][2], a[1][3], b0, b1);
            mma_tf32(s[0][1], a[0][0], a[0][1], a[0][2], a[0][3], b2, b3);
            mma_tf32(s[1][1], a[1][0], a[1][1], a[1][2], a[1][3], b2, b3);
        }

        if (j == qi) {
#pragma unroll
            for (int mt = 0; mt < 2; mt++)
#pragma unroll
                for (int nt = 0; nt < 2; nt++) {
                    const int colb = wn * 16 + nt * 8 + 2 * ak;
#pragma unroll
                    for (int cc = 0; cc < 4; cc++) {
                        const int row_l = wm * 32 + mt * 16 + ar + (cc >> 1) * 8;
                        const int col_l = colb + (cc & 1);
                        if (col_l > row_l) s[mt][nt][cc] = -1e30f;
                    }
                }
        }

#pragma unroll
        for (int mt = 0; mt < 2; mt++) {
            float r0m = fmaxf(fmaxf(s[mt][0][0], s[mt][0][1]), fmaxf(s[mt][1][0], s[mt][1][1]));
            float r1m = fmaxf(fmaxf(s[mt][0][2], s[mt][0][3]), fmaxf(s[mt][1][2], s[mt][1][3]));
            r0m = fmaxf(r0m, __shfl_xor_sync(0xffffffffu, r0m, 1));
            r0m = fmaxf(r0m, __shfl_xor_sync(0xffffffffu, r0m, 2));
            r1m = fmaxf(r1m, __shfl_xor_sync(0xffffffffu, r1m, 1));
            r1m = fmaxf(r1m, __shfl_xor_sync(0xffffffffu, r1m, 2));
            if (ak == 0) {
                redmax[wn][wm * 32 + mt * 16 + ar]     = r0m;
                redmax[wn][wm * 32 + mt * 16 + ar + 8] = r1m;
            }
        }
        __syncthreads();

        float m_new[2][2];
#pragma unroll
        for (int mt = 0; mt < 2; mt++)
#pragma unroll
            for (int hh = 0; hh < 2; hh++) {
                const int row = wm * 32 + mt * 16 + ar + hh * 8;
                float mr = fmaxf(fmaxf(redmax[0][row], redmax[1][row]),
                                 fmaxf(redmax[2][row], redmax[3][row]));
                m_new[mt][hh] = fmaxf(m_st[mt][hh], mr);
                if (wn == 0 && ak == 0)
                    corrs[row] = ex2((m_st[mt][hh] - m_new[mt][hh]) * C);
            }

        // p = 2^((s - m)*C): p0,p1 on FMA pipe (poly), p2,p3 on MUFU
        float psum[2][2];
        psum[0][0] = psum[0][1] = psum[1][0] = psum[1][1] = 0.f;
#pragma unroll
        for (int mt = 0; mt < 2; mt++) {
            const float mC0 = m_new[mt][0] * C;
            const float mC1 = m_new[mt][1] * C;
#pragma unroll
            for (int nt = 0; nt < 2; nt++) {
                const int colb = wn * 16 + nt * 8 + 2 * ak;
                float p0 = exp2poly(fmaf(s[mt][nt][0], C, -mC0));
                float p1 = exp2poly(fmaf(s[mt][nt][1], C, -mC0));
                float p2 = ex2(fmaf(s[mt][nt][2], C, -mC1));
                float p3 = ex2(fmaf(s[mt][nt][3], C, -mC1));
                psum[mt][0] += p0 + p1;
                psum[mt][1] += p2 + p3;
                const int r0 = wm * 32 + mt * 16 + ar;
                *(float2*)&Ks[r0][colb]     = make_float2(tf32r(p0), tf32r(p1));
                *(float2*)&Ks[r0 + 8][colb] = make_float2(tf32r(p2), tf32r(p3));
            }
        }
#pragma unroll
        for (int mt = 0; mt < 2; mt++) {
            psum[mt][0] += __shfl_xor_sync(0xffffffffu, psum[mt][0], 1);
            psum[mt][0] += __shfl_xor_sync(0xffffffffu, psum[mt][0], 2);
            psum[mt][1] += __shfl_xor_sync(0xffffffffu, psum[mt][1], 1);
            psum[mt][1] += __shfl_xor_sync(0xffffffffu, psum[mt][1], 2);
            if (ak == 0) {
                redsum[wn][wm * 32 + mt * 16 + ar]     = psum[mt][0];
                redsum[wn][wm * 32 + mt * 16 + ar + 8] = psum[mt][1];
            }
        }
        __syncthreads();

        float corr[2][2];
#pragma unroll
        for (int mt = 0; mt < 2; mt++)
#pragma unroll
            for (int hh = 0; hh < 2; hh++) {
                const int row = wm * 32 + mt * 16 + ar + hh * 8;
                float sm = (redsum[0][row] + redsum[1][row]) + (redsum[2][row] + redsum[3][row]);
                corr[mt][hh] = corrs[row];
                l_st[mt][hh] = l_st[mt][hh] * corr[mt][hh] + sm;
                m_st[mt][hh] = m_new[mt][hh];
            }
#pragma unroll
        for (int mt = 0; mt < 2; mt++)
#pragma unroll
            for (int nt = 0; nt < 4; nt++) {
                o[mt][nt][0] *= corr[mt][0];
                o[mt][nt][1] *= corr[mt][0];
                o[mt][nt][2] *= corr[mt][1];
                o[mt][nt][3] *= corr[mt][1];
            }

        // O += P * V  (P via ldmatrix, V scalar LDS)
#pragma unroll
        for (int ks = 0; ks < 64; ks += 8) {
            uint32_t a[2][4];
            ldsm_x4(a[0][0], a[0][1], a[0][2], a[0][3], ksb + aoff + ks * 4);
            ldsm_x4(a[1][0], a[1][1], a[1][2], a[1][3], ksb + aoff + 16 * FSTRB + ks * 4);
#pragma unroll
            for (int nt = 0; nt < 4; nt++) {
                const int nb = wn * 32 + nt * 8;
                uint32_t b0 = __float_as_uint(Vs[ks + ak][nb + ar]);
                uint32_t b1 = __float_as_uint(Vs[ks + ak + 4][nb + ar]);
                mma_tf32(o[0][nt], a[0][0], a[0][1], a[0][2], a[0][3], b0, b1);
                mma_tf32(o[1][nt], a[1][0], a[1][1], a[1][2], a[1][3], b0, b1);
            }
        }
    }

#pragma unroll
    for (int mt = 0; mt < 2; mt++) {
        const int r0 = wm * 32 + mt * 16 + ar;
        const float i0 = 1.f / l_st[mt][0];
        const float i1 = 1.f / l_st[mt][1];
        float* c0p = Ctx + (size_t)(qi * 64 + r0) * HID + h * DHEAD;
        float* c1p = c0p + 8 * HID;
#pragma unroll
        for (int nt = 0; nt < 4; nt++) {
            const int cb = wn * 32 + nt * 8 + 2 * ak;
            *(float2*)(c0p + cb) = make_float2(o[mt][nt][0] * i0, o[mt][nt][1] * i0);
            *(float2*)(c1p + cb) = make_float2(o[mt][nt][2] * i1, o[mt][nt][3] * i1);
        }
    }
}

// ---------------------------------------------------------------------------
// Per-(s,kvhead) RMSNorm + RoPE for K, in place.
// ---------------------------------------------------------------------------
__global__ __launch_bounds__(128) void k_normrope(
    float* __restrict__ X, int rowstride,
    const float* __restrict__ sin_t, const float* __restrict__ cos_t,
    const float* __restrict__ w)
{
    const int s = blockIdx.x;
    const int h = blockIdx.y;
    const int d = threadIdx.x;
    float* row = X + (size_t)s * rowstride + h * DHEAD;
    float v = row[d];
    float ss = v * v;
#pragma unroll
    for (int o = 16; o > 0; o >>= 1) ss += __shfl_xor_sync(0xffffffffu, ss, o);
    __shared__ float wsum[4];
    if ((d & 31) == 0) wsum[d >> 5] = ss;
    __syncthreads();
    float tot = wsum[0] + wsum[1] + wsum[2] + wsum[3];
    float inv = rsqrtf(tot * (1.0f / 128.0f) + 1.1920928955078125e-07f);
    __shared__ float xn[128];
    float xv = v * inv * w[d];
    xn[d] = xv;
    __syncthreads();
    float rot = (d < 64) ? -xn[d + 64] : xn[d - 64];
    row[d] = cos_t[s * DHEAD + d] * xv + sin_t[s * DHEAD + d] * rot;
}

// ---------------------------------------------------------------------------
// Launch
// ---------------------------------------------------------------------------
extern "C" void kernel_launch(void* const* d_in, const int* in_sizes, int n_in,
                              void* d_out, int out_size)
{
    (void)in_sizes; (void)n_in; (void)out_size;
    const float* x     = (const float*)d_in[0];
    const float* sin_t = (const float*)d_in[1];
    const float* cos_t = (const float*)d_in[2];
    const float* wq    = (const float*)d_in[4];
    const float* wk    = (const float*)d_in[5];
    const float* wv    = (const float*)d_in[6];
    const float* wo    = (const float*)d_in[7];
    const float* qnw   = (const float*)d_in[8];
    const float* knw   = (const float*)d_in[9];
    float* out = (float*)d_out;

    float *q, *k, *v, *ctx;
    cudaGetSymbolAddress((void**)&q,   g_q);
    cudaGetSymbolAddress((void**)&k,   g_k);
    cudaGetSymbolAddress((void**)&v,   g_v);
    cudaGetSymbolAddress((void**)&ctx, g_ctx);

    cudaFuncSetAttribute(k_flash, cudaFuncAttributeMaxDynamicSharedMemorySize, FLASH_SMEM);

    // Projections
    k_gemm_tn<<<dim3(HID / 128, SEQ / 128), 256>>>(x, HID, wq, HID, q, HID, HID);
    k_gemm_tn<<<dim3(KVW / 128, SEQ / 128), 256>>>(x, HID, wk, HID, k, KVW, HID);
    k_gemm_tn<<<dim3(KVW / 128, SEQ / 128), 256>>>(x, HID, wv, HID, v, KVW, HID);

    // RMSNorm + RoPE for K (Q's is fused into k_flash)
    k_normrope<<<dim3(SEQ, NKVH), 128>>>(k, KVW, sin_t, cos_t, knw);

    // Fused flash attention (512 CTAs = 32 q-blocks x 16 heads)
    k_flash<<<512, 256, FLASH_SMEM>>>(q, k, v, ctx, sin_t, cos_t, qnw);

    // Output projection
    k_gemm_tn<<<dim3(HID / 128, SEQ / 128), 256>>>(ctx, HID, wo, HID, out, HID, HID);
}

// round 7
// speedup vs baseline: 4.5672x; 1.3542x over previous
#include <cuda_runtime.h>
#include <cuda_fp16.h>
#include <math.h>
#include <stddef.h>
#include <stdint.h>

// Problem constants (B=1)
#define SEQ   2048
#define HID   2048
#define NHEADS 16
#define NKVH   4
#define DHEAD  128
#define KVW   (NKVH * DHEAD)      // 512
#define GQA_REP (NHEADS / NKVH)   // 4

// Scratch
__device__ float g_q[SEQ * HID];
__device__ float g_k[SEQ * KVW];
__device__ float g_v[SEQ * KVW];
__device__ float g_ctx[SEQ * HID];

// ---------------------------------------------------------------------------
// helpers
// ---------------------------------------------------------------------------
__device__ __forceinline__ float ex2(float x) {
    float y;
    asm("ex2.approx.ftz.f32 %0, %1;" : "=f"(y) : "f"(x));
    return y;
}
// 2^x on the FMA pipe (x <= 0; masked values clamp to ~0)
__device__ __forceinline__ float exp2poly(float x) {
    const float MAGIC = 12582912.f;            // 2^23 + 2^22
    float t = fmaxf(x, -126.f);
    float r = t + MAGIC;
    float n = r - MAGIC;
    float f = t - n;
    float p = 1.3333558146e-3f;
    p = fmaf(p, f, 9.6181291076e-3f);
    p = fmaf(p, f, 5.5504108664e-2f);
    p = fmaf(p, f, 2.4022650696e-1f);
    p = fmaf(p, f, 6.9314718056e-1f);
    p = fmaf(p, f, 1.0f);
    int sb = (__float_as_int(r) << 23) + (127 << 23);
    return p * __int_as_float(sb);
}
// fp16 MMA m16n8k16, fp32 accumulate
__device__ __forceinline__ void mma_f16(float c[4],
                                        uint32_t a0, uint32_t a1, uint32_t a2, uint32_t a3,
                                        uint32_t b0, uint32_t b1) {
    asm volatile(
        "mma.sync.aligned.m16n8k16.row.col.f32.f16.f16.f32 "
        "{%0,%1,%2,%3}, {%4,%5,%6,%7}, {%8,%9}, {%0,%1,%2,%3};"
        : "+f"(c[0]), "+f"(c[1]), "+f"(c[2]), "+f"(c[3])
        : "r"(a0), "r"(a1), "r"(a2), "r"(a3), "r"(b0), "r"(b1));
}
__device__ __forceinline__ void ldsm_x4(uint32_t& r0, uint32_t& r1, uint32_t& r2, uint32_t& r3,
                                        uint32_t addr) {
    asm volatile("ldmatrix.sync.aligned.m8n8.x4.shared.b16 {%0,%1,%2,%3}, [%4];"
                 : "=r"(r0), "=r"(r1), "=r"(r2), "=r"(r3) : "r"(addr));
}
__device__ __forceinline__ void ldsm_x4t(uint32_t& r0, uint32_t& r1, uint32_t& r2, uint32_t& r3,
                                         uint32_t addr) {
    asm volatile("ldmatrix.sync.aligned.m8n8.x4.trans.shared.b16 {%0,%1,%2,%3}, [%4];"
                 : "=r"(r0), "=r"(r1), "=r"(r2), "=r"(r3) : "r"(addr));
}
// A x4: mats = (rows 0-7, k0-7), (rows 8-15, k0-7), (rows 0-7, k8-15), (rows 8-15, k8-15)
__device__ __forceinline__ uint32_t ldsmA_off(int lane, int stride_bytes) {
    return (uint32_t)((lane & 15) * stride_bytes + (((lane >> 4) & 1) << 4));
}
// B x4 (2 n8-tiles x k16): (n0-7,k0-7),(n0-7,k8-15),(n8-15,k0-7),(n8-15,k8-15)
__device__ __forceinline__ uint32_t ldsmB_off(int lane, int stride_bytes) {
    int row = (lane & 7) + ((lane & 16) >> 1);
    return (uint32_t)(row * stride_bytes + (((lane >> 3) & 1) << 4));
}
__device__ __forceinline__ __half2 fh2(float x, float y) { return __floats2half2_rn(x, y); }

// ---------------------------------------------------------------------------
// TN GEMM (fp16 mma, fp32 accum, double-buffered): C = A[M,K] * B[N,K]^T
// 16-K chunks; smem stride 24 halves (48 B -> perfect bank permutation).
// ---------------------------------------------------------------------------
#define GSTR  24
#define GSTRB (GSTR * 2)

__global__ __launch_bounds__(256, 2) void k_gemm_tn(
    const float* __restrict__ A, int lda,
    const float* __restrict__ B, int ldb,
    float* __restrict__ C, int ldc, int K)
{
    __shared__ __half As[2][128][GSTR];
    __shared__ __half Bs[2][128][GSTR];
    const int tid  = threadIdx.x;
    const int lane = tid & 31;
    const int w    = tid >> 5;
    const int wm   = w >> 1;
    const int wn   = w & 1;
    const int bm   = blockIdx.y * 128;
    const int bn   = blockIdx.x * 128;

    float acc[2][8][4];
#pragma unroll
    for (int mt = 0; mt < 2; mt++)
#pragma unroll
        for (int nt = 0; nt < 8; nt++)
#pragma unroll
            for (int i = 0; i < 4; i++) acc[mt][nt][i] = 0.f;

    // per-thread load coords: 2 quads for A, 2 for B per chunk
    const int r0c = tid >> 2;                 // j=tid: row, 4 quads/row
    const int c0c = (tid & 3) << 2;
    const int r1c = (tid + 256) >> 2;
    const int c1c = ((tid + 256) & 3) << 2;

    const uint32_t as0 = (uint32_t)__cvta_generic_to_shared(&As[0][0][0]);
    const uint32_t as1 = (uint32_t)__cvta_generic_to_shared(&As[1][0][0]);
    const uint32_t bs0 = (uint32_t)__cvta_generic_to_shared(&Bs[0][0][0]);
    const uint32_t bs1 = (uint32_t)__cvta_generic_to_shared(&Bs[1][0][0]);
    const uint32_t aoff = ldsmA_off(lane, GSTRB) + (uint32_t)(wm * 32) * GSTRB;
    const uint32_t boff = ldsmB_off(lane, GSTRB) + (uint32_t)(wn * 64) * GSTRB;

    // chunk 0 -> buf 0
    {
        float4 a0 = *(const float4*)(A + (size_t)(bm + r0c) * lda + c0c);
        float4 a1 = *(const float4*)(A + (size_t)(bm + r1c) * lda + c1c);
        float4 b0 = *(const float4*)(B + (size_t)(bn + r0c) * ldb + c0c);
        float4 b1 = *(const float4*)(B + (size_t)(bn + r1c) * ldb + c1c);
        *(__half2*)&As[0][r0c][c0c]     = fh2(a0.x, a0.y);
        *(__half2*)&As[0][r0c][c0c + 2] = fh2(a0.z, a0.w);
        *(__half2*)&As[0][r1c][c1c]     = fh2(a1.x, a1.y);
        *(__half2*)&As[0][r1c][c1c + 2] = fh2(a1.z, a1.w);
        *(__half2*)&Bs[0][r0c][c0c]     = fh2(b0.x, b0.y);
        *(__half2*)&Bs[0][r0c][c0c + 2] = fh2(b0.z, b0.w);
        *(__half2*)&Bs[0][r1c][c1c]     = fh2(b1.x, b1.y);
        *(__half2*)&Bs[0][r1c][c1c + 2] = fh2(b1.z, b1.w);
    }
    __syncthreads();

    int cur = 0;
    for (int k0 = 0; k0 < K; k0 += 16) {
        const bool has_next = (k0 + 16) < K;
        float4 pa0, pa1, pb0, pb1;
        if (has_next) {
            const int kn = k0 + 16;
            pa0 = *(const float4*)(A + (size_t)(bm + r0c) * lda + kn + c0c);
            pa1 = *(const float4*)(A + (size_t)(bm + r1c) * lda + kn + c1c);
            pb0 = *(const float4*)(B + (size_t)(bn + r0c) * ldb + kn + c0c);
            pb1 = *(const float4*)(B + (size_t)(bn + r1c) * ldb + kn + c1c);
        }
        const uint32_t ab = (cur ? as1 : as0) + aoff;
        const uint32_t bb = (cur ? bs1 : bs0) + boff;
        uint32_t a[2][4];
        ldsm_x4(a[0][0], a[0][1], a[0][2], a[0][3], ab);
        ldsm_x4(a[1][0], a[1][1], a[1][2], a[1][3], ab + 16 * GSTRB);
#pragma unroll
        for (int pr = 0; pr < 4; pr++) {
            uint32_t b0, b1, b2, b3;
            ldsm_x4(b0, b1, b2, b3, bb + (uint32_t)pr * 16 * GSTRB);
            mma_f16(acc[0][2 * pr],     a[0][0], a[0][1], a[0][2], a[0][3], b0, b1);
            mma_f16(acc[1][2 * pr],     a[1][0], a[1][1], a[1][2], a[1][3], b0, b1);
            mma_f16(acc[0][2 * pr + 1], a[0][0], a[0][1], a[0][2], a[0][3], b2, b3);
            mma_f16(acc[1][2 * pr + 1], a[1][0], a[1][1], a[1][2], a[1][3], b2, b3);
        }
        if (has_next) {
            const int nxt = cur ^ 1;
            *(__half2*)&As[nxt][r0c][c0c]     = fh2(pa0.x, pa0.y);
            *(__half2*)&As[nxt][r0c][c0c + 2] = fh2(pa0.z, pa0.w);
            *(__half2*)&As[nxt][r1c][c1c]     = fh2(pa1.x, pa1.y);
            *(__half2*)&As[nxt][r1c][c1c + 2] = fh2(pa1.z, pa1.w);
            *(__half2*)&Bs[nxt][r0c][c0c]     = fh2(pb0.x, pb0.y);
            *(__half2*)&Bs[nxt][r0c][c0c + 2] = fh2(pb0.z, pb0.w);
            *(__half2*)&Bs[nxt][r1c][c1c]     = fh2(pb1.x, pb1.y);
            *(__half2*)&Bs[nxt][r1c][c1c + 2] = fh2(pb1.z, pb1.w);
            __syncthreads();
        }
        cur ^= 1;
    }

    const int ar = lane >> 2;
    const int ak = lane & 3;
#pragma unroll
    for (int mt = 0; mt < 2; mt++) {
        const int r0 = bm + wm * 32 + mt * 16 + ar;
#pragma unroll
        for (int nt = 0; nt < 8; nt++) {
            const int cidx = bn + wn * 64 + nt * 8 + 2 * ak;
            *(float2*)(C + (size_t)r0 * ldc + cidx)       = make_float2(acc[mt][nt][0], acc[mt][nt][1]);
            *(float2*)(C + (size_t)(r0 + 8) * ldc + cidx) = make_float2(acc[mt][nt][2], acc[mt][nt][3]);
        }
    }
}

// ---------------------------------------------------------------------------
// Fused flash attention (fp16 mma): Q RMSNorm+RoPE fused at load, hybrid exp.
// SMEM tiles are half: stride 136 halves (272 B, conflict-free for ldmatrix).
// ---------------------------------------------------------------------------
#define FSTR  136
#define FSTRB (FSTR * 2)
#define QS_OFF   0
#define KS_OFF   (64 * FSTRB)                 // 17408
#define VS_OFF   (KS_OFF + 64 * FSTRB)        // 34816
#define RMX_OFF  (VS_OFF + 64 * FSTRB)        // 52224
#define RSM_OFF  (RMX_OFF + 4 * 64 * 4)       // 53248
#define CRR_OFF  (RSM_OFF + 4 * 64 * 4)       // 54272
#define FLASH_SMEM (CRR_OFF + 64 * 4)         // 54528

__global__ __launch_bounds__(256, 2) void k_flash(
    const float* __restrict__ Qg, const float* __restrict__ Kg,
    const float* __restrict__ Vg, float* __restrict__ Ctx,
    const float* __restrict__ sin_t, const float* __restrict__ cos_t,
    const float* __restrict__ qnw)
{
    extern __shared__ char smem[];
    __half (*Qs)[FSTR]  = (__half(*)[FSTR])(smem + QS_OFF);
    __half (*Ks)[FSTR]  = (__half(*)[FSTR])(smem + KS_OFF);   // doubles as P
    __half (*Vs)[FSTR]  = (__half(*)[FSTR])(smem + VS_OFF);
    float (*redmax)[64] = (float(*)[64])(smem + RMX_OFF);
    float (*redsum)[64] = (float(*)[64])(smem + RSM_OFF);
    float* corrs        = (float*)(smem + CRR_OFF);

    const int bid = blockIdx.x;
    const int h   = bid & 15;
    const int qi  = 31 - (bid >> 4);          // longest blocks first
    const int kvh = h >> 2;

    const int tid  = threadIdx.x;
    const int lane = tid & 31;
    const int w    = tid >> 5;
    const int wm   = w >> 2;
    const int wn   = w & 3;
    const int ar   = lane >> 2;
    const int ak   = lane & 3;
    const float C  = (float)(0.08838834764831843 * 1.4426950408889634);

    const uint32_t qsb = (uint32_t)__cvta_generic_to_shared(&Qs[0][0]);
    const uint32_t ksb = (uint32_t)__cvta_generic_to_shared(&Ks[0][0]);
    const uint32_t vsb = (uint32_t)__cvta_generic_to_shared(&Vs[0][0]);
    const uint32_t aoff = ldsmA_off(lane, FSTRB) + (uint32_t)(wm * 32) * FSTRB;
    const uint32_t boff = ldsmB_off(lane, FSTRB) + (uint32_t)(wn * 16) * FSTRB;
    // V (trans) per-lane offset: group g=lane>>3: row += (g&1)*8, col += (g>>1)*8
    const uint32_t voff = (uint32_t)(((lane & 7) + ((lane >> 3) & 1) * 8) * FSTRB
                                     + (((lane >> 4) & 1) * 8 + wn * 32) * 2);

    // Q tile [64 x 128]: raw q -> RMSNorm -> RoPE -> half.
    {
        const int r  = tid >> 2;
        const int c0 = (tid & 3) << 2;
        const int s  = qi * 64 + r;
        const float* qp = Qg + (size_t)s * HID + h * DHEAD;
        float4 qa[8];
        float ss = 0.f;
#pragma unroll
        for (int i = 0; i < 8; i++) {
            qa[i] = *(const float4*)(qp + c0 + 16 * i);
            ss += qa[i].x * qa[i].x + qa[i].y * qa[i].y + qa[i].z * qa[i].z + qa[i].w * qa[i].w;
        }
        ss += __shfl_xor_sync(0xffffffffu, ss, 1);
        ss += __shfl_xor_sync(0xffffffffu, ss, 2);
        const float inv = rsqrtf(ss * (1.0f / 128.0f) + 1.1920928955078125e-07f);
        float4 xn[8];
#pragma unroll
        for (int i = 0; i < 8; i++) {
            float4 wv4 = *(const float4*)(qnw + c0 + 16 * i);
            xn[i] = make_float4(qa[i].x * inv * wv4.x, qa[i].y * inv * wv4.y,
                                qa[i].z * inv * wv4.z, qa[i].w * inv * wv4.w);
        }
        const float* sp = sin_t + (size_t)s * DHEAD;
        const float* cp = cos_t + (size_t)s * DHEAD;
#pragma unroll
        for (int i = 0; i < 8; i++) {
            const int c = c0 + 16 * i;
            float4 s4 = *(const float4*)(sp + c);
            float4 c4 = *(const float4*)(cp + c);
            float4 rot = (i < 4)
                ? make_float4(-xn[i + 4].x, -xn[i + 4].y, -xn[i + 4].z, -xn[i + 4].w)
                : xn[i - 4];
            *(__half2*)&Qs[r][c]     = fh2(c4.x * xn[i].x + s4.x * rot.x,
                                           c4.y * xn[i].y + s4.y * rot.y);
            *(__half2*)&Qs[r][c + 2] = fh2(c4.z * xn[i].z + s4.z * rot.z,
                                           c4.w * xn[i].w + s4.w * rot.w);
        }
    }

    float o[2][4][4];
    float m_st[2][2], l_st[2][2];
#pragma unroll
    for (int mt = 0; mt < 2; mt++) {
#pragma unroll
        for (int nt = 0; nt < 4; nt++)
#pragma unroll
            for (int c = 0; c < 4; c++) o[mt][nt][c] = 0.f;
        m_st[mt][0] = m_st[mt][1] = -1e30f;
        l_st[mt][0] = l_st[mt][1] = 0.f;
    }

    const int nkb = qi + 1;
    for (int j = 0; j < nkb; j++) {
        __syncthreads();
        {
            const int r  = tid >> 2;
            const int c0 = (tid & 3) << 2;
            const float* kp = Kg + (size_t)(j * 64 + r) * KVW + kvh * DHEAD + c0;
            const float* vp = Vg + (size_t)(j * 64 + r) * KVW + kvh * DHEAD + c0;
#pragma unroll
            for (int i = 0; i < 8; i++) {
                float4 kv = *(const float4*)(kp + 16 * i);
                float4 vv = *(const float4*)(vp + 16 * i);
                const int c = c0 + 16 * i;
                *(__half2*)&Ks[r][c]     = fh2(kv.x, kv.y);
                *(__half2*)&Ks[r][c + 2] = fh2(kv.z, kv.w);
                *(__half2*)&Vs[r][c]     = fh2(vv.x, vv.y);
                *(__half2*)&Vs[r][c + 2] = fh2(vv.z, vv.w);
            }
        }
        __syncthreads();

        // S = Q*K^T  (64x64, K=128): 8 k16 steps
        float s[2][2][4];
#pragma unroll
        for (int mt = 0; mt < 2; mt++)
#pragma unroll
            for (int nt = 0; nt < 2; nt++)
#pragma unroll
                for (int c = 0; c < 4; c++) s[mt][nt][c] = 0.f;
#pragma unroll
        for (int ks = 0; ks < 128; ks += 16) {
            uint32_t a[2][4];
            ldsm_x4(a[0][0], a[0][1], a[0][2], a[0][3], qsb + aoff + ks * 2);
            ldsm_x4(a[1][0], a[1][1], a[1][2], a[1][3], qsb + aoff + 16 * FSTRB + ks * 2);
            uint32_t b0, b1, b2, b3;
            ldsm_x4(b0, b1, b2, b3, ksb + boff + ks * 2);
            mma_f16(s[0][0], a[0][0], a[0][1], a[0][2], a[0][3], b0, b1);
            mma_f16(s[1][0], a[1][0], a[1][1], a[1][2], a[1][3], b0, b1);
            mma_f16(s[0][1], a[0][0], a[0][1], a[0][2], a[0][3], b2, b3);
            mma_f16(s[1][1], a[1][0], a[1][1], a[1][2], a[1][3], b2, b3);
        }

        if (j == qi) {
#pragma unroll
            for (int mt = 0; mt < 2; mt++)
#pragma unroll
                for (int nt = 0; nt < 2; nt++) {
                    const int colb = wn * 16 + nt * 8 + 2 * ak;
#pragma unroll
                    for (int cc = 0; cc < 4; cc++) {
                        const int row_l = wm * 32 + mt * 16 + ar + (cc >> 1) * 8;
                        const int col_l = colb + (cc & 1);
                        if (col_l > row_l) s[mt][nt][cc] = -1e30f;
                    }
                }
        }

#pragma unroll
        for (int mt = 0; mt < 2; mt++) {
            float r0m = fmaxf(fmaxf(s[mt][0][0], s[mt][0][1]), fmaxf(s[mt][1][0], s[mt][1][1]));
            float r1m = fmaxf(fmaxf(s[mt][0][2], s[mt][0][3]), fmaxf(s[mt][1][2], s[mt][1][3]));
            r0m = fmaxf(r0m, __shfl_xor_sync(0xffffffffu, r0m, 1));
            r0m = fmaxf(r0m, __shfl_xor_sync(0xffffffffu, r0m, 2));
            r1m = fmaxf(r1m, __shfl_xor_sync(0xffffffffu, r1m, 1));
            r1m = fmaxf(r1m, __shfl_xor_sync(0xffffffffu, r1m, 2));
            if (ak == 0) {
                redmax[wn][wm * 32 + mt * 16 + ar]     = r0m;
                redmax[wn][wm * 32 + mt * 16 + ar + 8] = r1m;
            }
        }
        __syncthreads();

        float m_new[2][2];
#pragma unroll
        for (int mt = 0; mt < 2; mt++)
#pragma unroll
            for (int hh = 0; hh < 2; hh++) {
                const int row = wm * 32 + mt * 16 + ar + hh * 8;
                float mr = fmaxf(fmaxf(redmax[0][row], redmax[1][row]),
                                 fmaxf(redmax[2][row], redmax[3][row]));
                m_new[mt][hh] = fmaxf(m_st[mt][hh], mr);
                if (wn == 0 && ak == 0)
                    corrs[row] = ex2((m_st[mt][hh] - m_new[mt][hh]) * C);
            }

        // p = 2^((s-m)*C): p0,p1 via FMA poly; p2,p3 via MUFU. Write P as half.
        float psum[2][2];
        psum[0][0] = psum[0][1] = psum[1][0] = psum[1][1] = 0.f;
#pragma unroll
        for (int mt = 0; mt < 2; mt++) {
            const float mC0 = m_new[mt][0] * C;
            const float mC1 = m_new[mt][1] * C;
#pragma unroll
            for (int nt = 0; nt < 2; nt++) {
                const int colb = wn * 16 + nt * 8 + 2 * ak;
                float p0 = exp2poly(fmaf(s[mt][nt][0], C, -mC0));
                float p1 = exp2poly(fmaf(s[mt][nt][1], C, -mC0));
                float p2 = ex2(fmaf(s[mt][nt][2], C, -mC1));
                float p3 = ex2(fmaf(s[mt][nt][3], C, -mC1));
                psum[mt][0] += p0 + p1;
                psum[mt][1] += p2 + p3;
                const int r0 = wm * 32 + mt * 16 + ar;
                *(__half2*)&Ks[r0][colb]     = fh2(p0, p1);
                *(__half2*)&Ks[r0 + 8][colb] = fh2(p2, p3);
            }
        }
#pragma unroll
        for (int mt = 0; mt < 2; mt++) {
            psum[mt][0] += __shfl_xor_sync(0xffffffffu, psum[mt][0], 1);
            psum[mt][0] += __shfl_xor_sync(0xffffffffu, psum[mt][0], 2);
            psum[mt][1] += __shfl_xor_sync(0xffffffffu, psum[mt][1], 1);
            psum[mt][1] += __shfl_xor_sync(0xffffffffu, psum[mt][1], 2);
            if (ak == 0) {
                redsum[wn][wm * 32 + mt * 16 + ar]     = psum[mt][0];
                redsum[wn][wm * 32 + mt * 16 + ar + 8] = psum[mt][1];
            }
        }
        __syncthreads();

        float corr[2][2];
#pragma unroll
        for (int mt = 0; mt < 2; mt++)
#pragma unroll
            for (int hh = 0; hh < 2; hh++) {
                const int row = wm * 32 + mt * 16 + ar + hh * 8;
                float sm = (redsum[0][row] + redsum[1][row]) + (redsum[2][row] + redsum[3][row]);
                corr[mt][hh] = corrs[row];
                l_st[mt][hh] = l_st[mt][hh] * corr[mt][hh] + sm;
                m_st[mt][hh] = m_new[mt][hh];
            }
#pragma unroll
        for (int mt = 0; mt < 2; mt++)
#pragma unroll
            for (int nt = 0; nt < 4; nt++) {
                o[mt][nt][0] *= corr[mt][0];
                o[mt][nt][1] *= corr[mt][0];
                o[mt][nt][2] *= corr[mt][1];
                o[mt][nt][3] *= corr[mt][1];
            }

        // O += P * V  (64x128, K=64): 4 k16 steps; V via ldmatrix.trans
#pragma unroll
        for (int ks = 0; ks < 64; ks += 16) {
            uint32_t a[2][4];
            ldsm_x4(a[0][0], a[0][1], a[0][2], a[0][3], ksb + aoff + ks * 2);
            ldsm_x4(a[1][0], a[1][1], a[1][2], a[1][3], ksb + aoff + 16 * FSTRB + ks * 2);
#pragma unroll
            for (int half_n = 0; half_n < 2; half_n++) {
                uint32_t b0, b1, b2, b3;   // 2 n8-tiles per trans x4
                ldsm_x4t(b0, b1, b2, b3, vsb + voff + (uint32_t)ks * FSTRB + half_n * 32);
                mma_f16(o[0][2 * half_n],     a[0][0], a[0][1], a[0][2], a[0][3], b0, b1);
                mma_f16(o[1][2 * half_n],     a[1][0], a[1][1], a[1][2], a[1][3], b0, b1);
                mma_f16(o[0][2 * half_n + 1], a[0][0], a[0][1], a[0][2], a[0][3], b2, b3);
                mma_f16(o[1][2 * half_n + 1], a[1][0], a[1][1], a[1][2], a[1][3], b2, b3);
            }
        }
    }

#pragma unroll
    for (int mt = 0; mt < 2; mt++) {
        const int r0 = wm * 32 + mt * 16 + ar;
        const float i0 = 1.f / l_st[mt][0];
        const float i1 = 1.f / l_st[mt][1];
        float* c0p = Ctx + (size_t)(qi * 64 + r0) * HID + h * DHEAD;
        float* c1p = c0p + 8 * HID;
#pragma unroll
        for (int nt = 0; nt < 4; nt++) {
            const int cb = wn * 32 + nt * 8 + 2 * ak;
            *(float2*)(c0p + cb) = make_float2(o[mt][nt][0] * i0, o[mt][nt][1] * i0);
            *(float2*)(c1p + cb) = make_float2(o[mt][nt][2] * i1, o[mt][nt][3] * i1);
        }
    }
}

// ---------------------------------------------------------------------------
// Per-(s,kvhead) RMSNorm + RoPE for K, in place (fp32).
// ---------------------------------------------------------------------------
__global__ __launch_bounds__(128) void k_normrope(
    float* __restrict__ X, int rowstride,
    const float* __restrict__ sin_t, const float* __restrict__ cos_t,
    const float* __restrict__ w)
{
    const int s = blockIdx.x;
    const int h = blockIdx.y;
    const int d = threadIdx.x;
    float* row = X + (size_t)s * rowstride + h * DHEAD;
    float v = row[d];
    float ss = v * v;
#pragma unroll
    for (int o = 16; o > 0; o >>= 1) ss += __shfl_xor_sync(0xffffffffu, ss, o);
    __shared__ float wsum[4];
    if ((d & 31) == 0) wsum[d >> 5] = ss;
    __syncthreads();
    float tot = wsum[0] + wsum[1] + wsum[2] + wsum[3];
    float inv = rsqrtf(tot * (1.0f / 128.0f) + 1.1920928955078125e-07f);
    __shared__ float xn[128];
    float xv = v * inv * w[d];
    xn[d] = xv;
    __syncthreads();
    float rot = (d < 64) ? -xn[d + 64] : xn[d - 64];
    row[d] = cos_t[s * DHEAD + d] * xv + sin_t[s * DHEAD + d] * rot;
}

// ---------------------------------------------------------------------------
// Launch
// ---------------------------------------------------------------------------
extern "C" void kernel_launch(void* const* d_in, const int* in_sizes, int n_in,
                              void* d_out, int out_size)
{
    (void)in_sizes; (void)n_in; (void)out_size;
    const float* x     = (const float*)d_in[0];
    const float* sin_t = (const float*)d_in[1];
    const float* cos_t = (const float*)d_in[2];
    const float* wq    = (const float*)d_in[4];
    const float* wk    = (const float*)d_in[5];
    const float* wv    = (const float*)d_in[6];
    const float* wo    = (const float*)d_in[7];
    const float* qnw   = (const float*)d_in[8];
    const float* knw   = (const float*)d_in[9];
    float* out = (float*)d_out;

    float *q, *k, *v, *ctx;
    cudaGetSymbolAddress((void**)&q,   g_q);
    cudaGetSymbolAddress((void**)&k,   g_k);
    cudaGetSymbolAddress((void**)&v,   g_v);
    cudaGetSymbolAddress((void**)&ctx, g_ctx);

    cudaFuncSetAttribute(k_flash, cudaFuncAttributeMaxDynamicSharedMemorySize, FLASH_SMEM);

    // Projections (fp16 mma)
    k_gemm_tn<<<dim3(HID / 128, SEQ / 128), 256>>>(x, HID, wq, HID, q, HID, HID);
    k_gemm_tn<<<dim3(KVW / 128, SEQ / 128), 256>>>(x, HID, wk, HID, k, KVW, HID);
    k_gemm_tn<<<dim3(KVW / 128, SEQ / 128), 256>>>(x, HID, wv, HID, v, KVW, HID);

    // RMSNorm + RoPE for K (Q's is fused into k_flash)
    k_normrope<<<dim3(SEQ, NKVH), 128>>>(k, KVW, sin_t, cos_t, knw);

    // Fused flash attention
    k_flash<<<512, 256, FLASH_SMEM>>>(q, k, v, ctx, sin_t, cos_t, qnw);

    // Output projection
    k_gemm_tn<<<dim3(HID / 128, SEQ / 128), 256>>>(ctx, HID, wo, HID, out, HID, HID);
}

// round 8
// speedup vs baseline: 5.5969x; 1.2255x over previous
#include <cuda_runtime.h>
#include <cuda_fp16.h>
#include <math.h>
#include <stddef.h>
#include <stdint.h>

// Problem constants (B=1)
#define SEQ   2048
#define HID   2048
#define NHEADS 16
#define NKVH   4
#define DHEAD  128
#define KVW   (NKVH * DHEAD)      // 512
#define GQA_REP (NHEADS / NKVH)   // 4

// Scratch
__device__ float g_q[SEQ * HID];
__device__ float g_k[SEQ * KVW];
__device__ float g_v[SEQ * KVW];
__device__ float g_ctx[SEQ * HID];

// ---------------------------------------------------------------------------
// helpers
// ---------------------------------------------------------------------------
__device__ __forceinline__ float ex2(float x) {
    float y;
    asm("ex2.approx.ftz.f32 %0, %1;" : "=f"(y) : "f"(x));
    return y;
}
__device__ __forceinline__ float exp2poly(float x) {
    const float MAGIC = 12582912.f;            // 2^23 + 2^22
    float t = fmaxf(x, -126.f);
    float r = t + MAGIC;
    float n = r - MAGIC;
    float f = t - n;
    float p = 1.3333558146e-3f;
    p = fmaf(p, f, 9.6181291076e-3f);
    p = fmaf(p, f, 5.5504108664e-2f);
    p = fmaf(p, f, 2.4022650696e-1f);
    p = fmaf(p, f, 6.9314718056e-1f);
    p = fmaf(p, f, 1.0f);
    int sb = (__float_as_int(r) << 23) + (127 << 23);
    return p * __int_as_float(sb);
}
__device__ __forceinline__ void mma_f16(float c[4],
                                        uint32_t a0, uint32_t a1, uint32_t a2, uint32_t a3,
                                        uint32_t b0, uint32_t b1) {
    asm volatile(
        "mma.sync.aligned.m16n8k16.row.col.f32.f16.f16.f32 "
        "{%0,%1,%2,%3}, {%4,%5,%6,%7}, {%8,%9}, {%0,%1,%2,%3};"
        : "+f"(c[0]), "+f"(c[1]), "+f"(c[2]), "+f"(c[3])
        : "r"(a0), "r"(a1), "r"(a2), "r"(a3), "r"(b0), "r"(b1));
}
__device__ __forceinline__ void ldsm_x4(uint32_t& r0, uint32_t& r1, uint32_t& r2, uint32_t& r3,
                                        uint32_t addr) {
    asm volatile("ldmatrix.sync.aligned.m8n8.x4.shared.b16 {%0,%1,%2,%3}, [%4];"
                 : "=r"(r0), "=r"(r1), "=r"(r2), "=r"(r3) : "r"(addr));
}
__device__ __forceinline__ void ldsm_x4t(uint32_t& r0, uint32_t& r1, uint32_t& r2, uint32_t& r3,
                                         uint32_t addr) {
    asm volatile("ldmatrix.sync.aligned.m8n8.x4.trans.shared.b16 {%0,%1,%2,%3}, [%4];"
                 : "=r"(r0), "=r"(r1), "=r"(r2), "=r"(r3) : "r"(addr));
}
__device__ __forceinline__ uint32_t ldsmA_off(int lane, int stride_bytes) {
    return (uint32_t)((lane & 15) * stride_bytes + (((lane >> 4) & 1) << 4));
}
__device__ __forceinline__ uint32_t ldsmB_off(int lane, int stride_bytes) {
    int row = (lane & 7) + ((lane & 16) >> 1);
    return (uint32_t)(row * stride_bytes + (((lane >> 3) & 1) << 4));
}
__device__ __forceinline__ __half2 fh2(float x, float y) { return __floats2half2_rn(x, y); }

// ---------------------------------------------------------------------------
// TN GEMM body (fp16 mma, fp32 accum, double-buffered): C = A[M,K]*B[N,K]^T
// ---------------------------------------------------------------------------
#define GSTR  24
#define GSTRB (GSTR * 2)

__device__ __forceinline__ void gemm_tn_body(
    const float* __restrict__ A, int lda,
    const float* __restrict__ B, int ldb,
    float* __restrict__ C, int ldc,
    int K, int bm, int bn)
{
    __shared__ __half As[2][128][GSTR];
    __shared__ __half Bs[2][128][GSTR];
    const int tid  = threadIdx.x;
    const int lane = tid & 31;
    const int w    = tid >> 5;
    const int wm   = w >> 1;
    const int wn   = w & 1;

    float acc[2][8][4];
#pragma unroll
    for (int mt = 0; mt < 2; mt++)
#pragma unroll
        for (int nt = 0; nt < 8; nt++)
#pragma unroll
            for (int i = 0; i < 4; i++) acc[mt][nt][i] = 0.f;

    const int r0c = tid >> 2;
    const int c0c = (tid & 3) << 2;
    const int r1c = (tid + 256) >> 2;
    const int c1c = ((tid + 256) & 3) << 2;

    const uint32_t as0 = (uint32_t)__cvta_generic_to_shared(&As[0][0][0]);
    const uint32_t as1 = (uint32_t)__cvta_generic_to_shared(&As[1][0][0]);
    const uint32_t bs0 = (uint32_t)__cvta_generic_to_shared(&Bs[0][0][0]);
    const uint32_t bs1 = (uint32_t)__cvta_generic_to_shared(&Bs[1][0][0]);
    const uint32_t aoff = ldsmA_off(lane, GSTRB) + (uint32_t)(wm * 32) * GSTRB;
    const uint32_t boff = ldsmB_off(lane, GSTRB) + (uint32_t)(wn * 64) * GSTRB;

    {
        float4 a0 = *(const float4*)(A + (size_t)(bm + r0c) * lda + c0c);
        float4 a1 = *(const float4*)(A + (size_t)(bm + r1c) * lda + c1c);
        float4 b0 = *(const float4*)(B + (size_t)(bn + r0c) * ldb + c0c);
        float4 b1 = *(const float4*)(B + (size_t)(bn + r1c) * ldb + c1c);
        *(__half2*)&As[0][r0c][c0c]     = fh2(a0.x, a0.y);
        *(__half2*)&As[0][r0c][c0c + 2] = fh2(a0.z, a0.w);
        *(__half2*)&As[0][r1c][c1c]     = fh2(a1.x, a1.y);
        *(__half2*)&As[0][r1c][c1c + 2] = fh2(a1.z, a1.w);
        *(__half2*)&Bs[0][r0c][c0c]     = fh2(b0.x, b0.y);
        *(__half2*)&Bs[0][r0c][c0c + 2] = fh2(b0.z, b0.w);
        *(__half2*)&Bs[0][r1c][c1c]     = fh2(b1.x, b1.y);
        *(__half2*)&Bs[0][r1c][c1c + 2] = fh2(b1.z, b1.w);
    }
    __syncthreads();

    int cur = 0;
    for (int k0 = 0; k0 < K; k0 += 16) {
        const bool has_next = (k0 + 16) < K;
        float4 pa0, pa1, pb0, pb1;
        if (has_next) {
            const int kn = k0 + 16;
            pa0 = *(const float4*)(A + (size_t)(bm + r0c) * lda + kn + c0c);
            pa1 = *(const float4*)(A + (size_t)(bm + r1c) * lda + kn + c1c);
            pb0 = *(const float4*)(B + (size_t)(bn + r0c) * ldb + kn + c0c);
            pb1 = *(const float4*)(B + (size_t)(bn + r1c) * ldb + kn + c1c);
        }
        const uint32_t ab = (cur ? as1 : as0) + aoff;
        const uint32_t bb = (cur ? bs1 : bs0) + boff;
        uint32_t a[2][4];
        ldsm_x4(a[0][0], a[0][1], a[0][2], a[0][3], ab);
        ldsm_x4(a[1][0], a[1][1], a[1][2], a[1][3], ab + 16 * GSTRB);
#pragma unroll
        for (int pr = 0; pr < 4; pr++) {
            uint32_t b0, b1, b2, b3;
            ldsm_x4(b0, b1, b2, b3, bb + (uint32_t)pr * 16 * GSTRB);
            mma_f16(acc[0][2 * pr],     a[0][0], a[0][1], a[0][2], a[0][3], b0, b1);
            mma_f16(acc[1][2 * pr],     a[1][0], a[1][1], a[1][2], a[1][3], b0, b1);
            mma_f16(acc[0][2 * pr + 1], a[0][0], a[0][1], a[0][2], a[0][3], b2, b3);
            mma_f16(acc[1][2 * pr + 1], a[1][0], a[1][1], a[1][2], a[1][3], b2, b3);
        }
        if (has_next) {
            const int nxt = cur ^ 1;
            *(__half2*)&As[nxt][r0c][c0c]     = fh2(pa0.x, pa0.y);
            *(__half2*)&As[nxt][r0c][c0c + 2] = fh2(pa0.z, pa0.w);
            *(__half2*)&As[nxt][r1c][c1c]     = fh2(pa1.x, pa1.y);
            *(__half2*)&As[nxt][r1c][c1c + 2] = fh2(pa1.z, pa1.w);
            *(__half2*)&Bs[nxt][r0c][c0c]     = fh2(pb0.x, pb0.y);
            *(__half2*)&Bs[nxt][r0c][c0c + 2] = fh2(pb0.z, pb0.w);
            *(__half2*)&Bs[nxt][r1c][c1c]     = fh2(pb1.x, pb1.y);
            *(__half2*)&Bs[nxt][r1c][c1c + 2] = fh2(pb1.z, pb1.w);
            __syncthreads();
        }
        cur ^= 1;
    }

    const int ar = lane >> 2;
    const int ak = lane & 3;
#pragma unroll
    for (int mt = 0; mt < 2; mt++) {
        const int r0 = bm + wm * 32 + mt * 16 + ar;
#pragma unroll
        for (int nt = 0; nt < 8; nt++) {
            const int cidx = bn + wn * 64 + nt * 8 + 2 * ak;
            *(float2*)(C + (size_t)r0 * ldc + cidx)       = make_float2(acc[mt][nt][0], acc[mt][nt][1]);
            *(float2*)(C + (size_t)(r0 + 8) * ldc + cidx) = make_float2(acc[mt][nt][2], acc[mt][nt][3]);
        }
    }
}

// Fused QKV projection: one launch covering 3072 output cols (wq|wk|wv)
__global__ __launch_bounds__(256, 2) void k_gemm_qkv(
    const float* __restrict__ x,
    const float* __restrict__ wq, const float* __restrict__ wk,
    const float* __restrict__ wv,
    float* __restrict__ q, float* __restrict__ k, float* __restrict__ v)
{
    const int bnx = blockIdx.x * 128;
    const float* B; float* C; int ldc; int bn;
    if (bnx < HID)            { B = wq; C = q; ldc = HID; bn = bnx; }
    else if (bnx < HID + KVW) { B = wk; C = k; ldc = KVW; bn = bnx - HID; }
    else                      { B = wv; C = v; ldc = KVW; bn = bnx - HID - KVW; }
    gemm_tn_body(x, HID, B, HID, C, ldc, HID, blockIdx.y * 128, bn);
}

__global__ __launch_bounds__(256, 2) void k_gemm_tn(
    const float* __restrict__ A, int lda,
    const float* __restrict__ B, int ldb,
    float* __restrict__ C, int ldc, int K)
{
    gemm_tn_body(A, lda, B, ldb, C, ldc, K, blockIdx.y * 128, blockIdx.x * 128);
}

// ---------------------------------------------------------------------------
// Fused flash attention (fp16 mma, BK=128): Q RMSNorm+RoPE fused at load,
// hybrid exp, 128-key blocks halve per-iteration sync/reduction overhead.
// ---------------------------------------------------------------------------
#define FSTR  136
#define FSTRB (FSTR * 2)
#define QS_OFF   0
#define KS_OFF   (64 * FSTRB)                    // 17408
#define VS_OFF   (KS_OFF + 128 * FSTRB)          // 52224
#define RMX_OFF  (VS_OFF + 128 * FSTRB)          // 87040
#define RSM_OFF  (RMX_OFF + 4 * 64 * 4)          // 88064
#define CRR_OFF  (RSM_OFF + 4 * 64 * 4)          // 89088
#define FLASH_SMEM (CRR_OFF + 64 * 4)            // 89344

__global__ __launch_bounds__(256, 2) void k_flash(
    const float* __restrict__ Qg, const float* __restrict__ Kg,
    const float* __restrict__ Vg, float* __restrict__ Ctx,
    const float* __restrict__ sin_t, const float* __restrict__ cos_t,
    const float* __restrict__ qnw)
{
    extern __shared__ char smem[];
    __half (*Qs)[FSTR]  = (__half(*)[FSTR])(smem + QS_OFF);
    __half (*Ks)[FSTR]  = (__half(*)[FSTR])(smem + KS_OFF);   // K tile; rows 0..63 reused as P
    __half (*Vs)[FSTR]  = (__half(*)[FSTR])(smem + VS_OFF);
    float (*redmax)[64] = (float(*)[64])(smem + RMX_OFF);
    float (*redsum)[64] = (float(*)[64])(smem + RSM_OFF);
    float* corrs        = (float*)(smem + CRR_OFF);

    const int bid = blockIdx.x;
    const int h   = bid & 15;
    const int qi  = 31 - (bid >> 4);          // longest blocks first
    const int kvh = h >> 2;

    const int tid  = threadIdx.x;
    const int lane = tid & 31;
    const int w    = tid >> 5;
    const int wm   = w >> 2;                  // 0..1 (32 rows)
    const int wn   = w & 3;                   // 0..3 (32 cols)
    const int ar   = lane >> 2;
    const int ak   = lane & 3;
    const float C  = (float)(0.08838834764831843 * 1.4426950408889634);

    const uint32_t qsb = (uint32_t)__cvta_generic_to_shared(&Qs[0][0]);
    const uint32_t ksb = (uint32_t)__cvta_generic_to_shared(&Ks[0][0]);
    const uint32_t vsb = (uint32_t)__cvta_generic_to_shared(&Vs[0][0]);
    const uint32_t aoff  = ldsmA_off(lane, FSTRB) + (uint32_t)(wm * 32) * FSTRB;
    const uint32_t boff  = ldsmB_off(lane, FSTRB) + (uint32_t)(wn * 32) * FSTRB;
    const uint32_t voff  = (uint32_t)(((lane & 7) + ((lane >> 3) & 1) * 8) * FSTRB
                                      + (((lane >> 4) & 1) * 8 + wn * 32) * 2);

    // Q tile [64 x 128]: raw q -> RMSNorm -> RoPE -> half.
    {
        const int r  = tid >> 2;
        const int c0 = (tid & 3) << 2;
        const int s  = qi * 64 + r;
        const float* qp = Qg + (size_t)s * HID + h * DHEAD;
        float4 qa[8];
        float ss = 0.f;
#pragma unroll
        for (int i = 0; i < 8; i++) {
            qa[i] = *(const float4*)(qp + c0 + 16 * i);
            ss += qa[i].x * qa[i].x + qa[i].y * qa[i].y + qa[i].z * qa[i].z + qa[i].w * qa[i].w;
        }
        ss += __shfl_xor_sync(0xffffffffu, ss, 1);
        ss += __shfl_xor_sync(0xffffffffu, ss, 2);
        const float inv = rsqrtf(ss * (1.0f / 128.0f) + 1.1920928955078125e-07f);
        float4 xn[8];
#pragma unroll
        for (int i = 0; i < 8; i++) {
            float4 wv4 = *(const float4*)(qnw + c0 + 16 * i);
            xn[i] = make_float4(qa[i].x * inv * wv4.x, qa[i].y * inv * wv4.y,
                                qa[i].z * inv * wv4.z, qa[i].w * inv * wv4.w);
        }
        const float* sp = sin_t + (size_t)s * DHEAD;
        const float* cp = cos_t + (size_t)s * DHEAD;
#pragma unroll
        for (int i = 0; i < 8; i++) {
            const int c = c0 + 16 * i;
            float4 s4 = *(const float4*)(sp + c);
            float4 c4 = *(const float4*)(cp + c);
            float4 rot = (i < 4)
                ? make_float4(-xn[i + 4].x, -xn[i + 4].y, -xn[i + 4].z, -xn[i + 4].w)
                : xn[i - 4];
            *(__half2*)&Qs[r][c]     = fh2(c4.x * xn[i].x + s4.x * rot.x,
                                           c4.y * xn[i].y + s4.y * rot.y);
            *(__half2*)&Qs[r][c + 2] = fh2(c4.z * xn[i].z + s4.z * rot.z,
                                           c4.w * xn[i].w + s4.w * rot.w);
        }
    }

    float o[2][4][4];
    float m_st[2][2], l_st[2][2];
#pragma unroll
    for (int mt = 0; mt < 2; mt++) {
#pragma unroll
        for (int nt = 0; nt < 4; nt++)
#pragma unroll
            for (int c = 0; c < 4; c++) o[mt][nt][c] = 0.f;
        m_st[mt][0] = m_st[mt][1] = -1e30f;
        l_st[mt][0] = l_st[mt][1] = 0.f;
    }

    const int nj = (qi >> 1) + 1;             // 128-key blocks
    for (int j = 0; j < nj; j++) {
        __syncthreads();
        {   // load K,V tiles [128 x 128] -> half
            const int r  = tid >> 1;          // 128 rows, 2 threads/row
            const int c0 = (tid & 1) << 2;
            const float* kp = Kg + (size_t)(j * 128 + r) * KVW + kvh * DHEAD + c0;
            const float* vp = Vg + (size_t)(j * 128 + r) * KVW + kvh * DHEAD + c0;
#pragma unroll
            for (int i = 0; i < 16; i++) {
                float4 kv = *(const float4*)(kp + 8 * i);
                float4 vv = *(const float4*)(vp + 8 * i);
                const int c = c0 + 8 * i;
                *(__half2*)&Ks[r][c]     = fh2(kv.x, kv.y);
                *(__half2*)&Ks[r][c + 2] = fh2(kv.z, kv.w);
                *(__half2*)&Vs[r][c]     = fh2(vv.x, vv.y);
                *(__half2*)&Vs[r][c + 2] = fh2(vv.z, vv.w);
            }
        }
        __syncthreads();

        // S = Q*K^T  (64 x 128, K=128): 8 k16 steps; warp tile 32x32
        float s[2][4][4];
#pragma unroll
        for (int mt = 0; mt < 2; mt++)
#pragma unroll
            for (int nt = 0; nt < 4; nt++)
#pragma unroll
                for (int c = 0; c < 4; c++) s[mt][nt][c] = 0.f;
#pragma unroll
        for (int ks = 0; ks < 128; ks += 16) {
            uint32_t a[2][4];
            ldsm_x4(a[0][0], a[0][1], a[0][2], a[0][3], qsb + aoff + ks * 2);
            ldsm_x4(a[1][0], a[1][1], a[1][2], a[1][3], qsb + aoff + 16 * FSTRB + ks * 2);
#pragma unroll
            for (int pr = 0; pr < 2; pr++) {
                uint32_t b0, b1, b2, b3;
                ldsm_x4(b0, b1, b2, b3, ksb + boff + (uint32_t)pr * 16 * FSTRB + ks * 2);
                mma_f16(s[0][2 * pr],     a[0][0], a[0][1], a[0][2], a[0][3], b0, b1);
                mma_f16(s[1][2 * pr],     a[1][0], a[1][1], a[1][2], a[1][3], b0, b1);
                mma_f16(s[0][2 * pr + 1], a[0][0], a[0][1], a[0][2], a[0][3], b2, b3);
                mma_f16(s[1][2 * pr + 1], a[1][0], a[1][1], a[1][2], a[1][3], b2, b3);
            }
        }

        // causal mask: only the last block can straddle the diagonal
        if (j == nj - 1) {
            const int col0 = j * 128;
            const int row0 = qi * 64;
#pragma unroll
            for (int mt = 0; mt < 2; mt++)
#pragma unroll
                for (int nt = 0; nt < 4; nt++) {
                    const int colb = col0 + wn * 32 + nt * 8 + 2 * ak;
#pragma unroll
                    for (int cc = 0; cc < 4; cc++) {
                        const int row_g = row0 + wm * 32 + mt * 16 + ar + (cc >> 1) * 8;
                        const int col_g = colb + (cc & 1);
                        if (col_g > row_g) s[mt][nt][cc] = -1e30f;
                    }
                }
        }

        // row max: thread-local over 4 nt tiles -> 4-lane shfl -> cross-warp smem
#pragma unroll
        for (int mt = 0; mt < 2; mt++) {
            float r0m = fmaxf(fmaxf(s[mt][0][0], s[mt][0][1]), fmaxf(s[mt][1][0], s[mt][1][1]));
            r0m = fmaxf(r0m, fmaxf(fmaxf(s[mt][2][0], s[mt][2][1]), fmaxf(s[mt][3][0], s[mt][3][1])));
            float r1m = fmaxf(fmaxf(s[mt][0][2], s[mt][0][3]), fmaxf(s[mt][1][2], s[mt][1][3]));
            r1m = fmaxf(r1m, fmaxf(fmaxf(s[mt][2][2], s[mt][2][3]), fmaxf(s[mt][3][2], s[mt][3][3])));
            r0m = fmaxf(r0m, __shfl_xor_sync(0xffffffffu, r0m, 1));
            r0m = fmaxf(r0m, __shfl_xor_sync(0xffffffffu, r0m, 2));
            r1m = fmaxf(r1m, __shfl_xor_sync(0xffffffffu, r1m, 1));
            r1m = fmaxf(r1m, __shfl_xor_sync(0xffffffffu, r1m, 2));
            if (ak == 0) {
                redmax[wn][wm * 32 + mt * 16 + ar]     = r0m;
                redmax[wn][wm * 32 + mt * 16 + ar + 8] = r1m;
            }
        }
        __syncthreads();

        float m_new[2][2];
#pragma unroll
        for (int mt = 0; mt < 2; mt++)
#pragma unroll
            for (int hh = 0; hh < 2; hh++) {
                const int row = wm * 32 + mt * 16 + ar + hh * 8;
                float mr = fmaxf(fmaxf(redmax[0][row], redmax[1][row]),
                                 fmaxf(redmax[2][row], redmax[3][row]));
                m_new[mt][hh] = fmaxf(m_st[mt][hh], mr);
                if (wn == 0 && ak == 0)
                    corrs[row] = ex2((m_st[mt][hh] - m_new[mt][hh]) * C);
            }

        // p = 2^((s-m)*C): rows r0 via FMA poly, rows r0+8 via MUFU. P -> Ks rows 0..63.
        float psum[2][2];
        psum[0][0] = psum[0][1] = psum[1][0] = psum[1][1] = 0.f;
#pragma unroll
        for (int mt = 0; mt < 2; mt++) {
            const float mC0 = m_new[mt][0] * C;
            const float mC1 = m_new[mt][1] * C;
#pragma unroll
            for (int nt = 0; nt < 4; nt++) {
                const int colb = wn * 32 + nt * 8 + 2 * ak;
                float p0 = exp2poly(fmaf(s[mt][nt][0], C, -mC0));
                float p1 = exp2poly(fmaf(s[mt][nt][1], C, -mC0));
                float p2 = ex2(fmaf(s[mt][nt][2], C, -mC1));
                float p3 = ex2(fmaf(s[mt][nt][3], C, -mC1));
                psum[mt][0] += p0 + p1;
                psum[mt][1] += p2 + p3;
                const int r0 = wm * 32 + mt * 16 + ar;
                *(__half2*)&Ks[r0][colb]     = fh2(p0, p1);
                *(__half2*)&Ks[r0 + 8][colb] = fh2(p2, p3);
            }
        }
#pragma unroll
        for (int mt = 0; mt < 2; mt++) {
            psum[mt][0] += __shfl_xor_sync(0xffffffffu, psum[mt][0], 1);
            psum[mt][0] += __shfl_xor_sync(0xffffffffu, psum[mt][0], 2);
            psum[mt][1] += __shfl_xor_sync(0xffffffffu, psum[mt][1], 1);
            psum[mt][1] += __shfl_xor_sync(0xffffffffu, psum[mt][1], 2);
            if (ak == 0) {
                redsum[wn][wm * 32 + mt * 16 + ar]     = psum[mt][0];
                redsum[wn][wm * 32 + mt * 16 + ar + 8] = psum[mt][1];
            }
        }
        __syncthreads();

        float corr[2][2];
#pragma unroll
        for (int mt = 0; mt < 2; mt++)
#pragma unroll
            for (int hh = 0; hh < 2; hh++) {
                const int row = wm * 32 + mt * 16 + ar + hh * 8;
                float sm = (redsum[0][row] + redsum[1][row]) + (redsum[2][row] + redsum[3][row]);
                corr[mt][hh] = corrs[row];
                l_st[mt][hh] = l_st[mt][hh] * corr[mt][hh] + sm;
                m_st[mt][hh] = m_new[mt][hh];
            }
#pragma unroll
        for (int mt = 0; mt < 2; mt++)
#pragma unroll
            for (int nt = 0; nt < 4; nt++) {
                o[mt][nt][0] *= corr[mt][0];
                o[mt][nt][1] *= corr[mt][0];
                o[mt][nt][2] *= corr[mt][1];
                o[mt][nt][3] *= corr[mt][1];
            }

        // O += P * V  (64x128, K=128): 8 k16 steps; V via ldmatrix.trans
#pragma unroll
        for (int ks = 0; ks < 128; ks += 16) {
            uint32_t a[2][4];
            ldsm_x4(a[0][0], a[0][1], a[0][2], a[0][3], ksb + aoff + ks * 2);
            ldsm_x4(a[1][0], a[1][1], a[1][2], a[1][3], ksb + aoff + 16 * FSTRB + ks * 2);
#pragma unroll
            for (int half_n = 0; half_n < 2; half_n++) {
                uint32_t b0, b1, b2, b3;
                ldsm_x4t(b0, b1, b2, b3, vsb + voff + (uint32_t)ks * FSTRB + half_n * 32);
                mma_f16(o[0][2 * half_n],     a[0][0], a[0][1], a[0][2], a[0][3], b0, b1);
                mma_f16(o[1][2 * half_n],     a[1][0], a[1][1], a[1][2], a[1][3], b0, b1);
                mma_f16(o[0][2 * half_n + 1], a[0][0], a[0][1], a[0][2], a[0][3], b2, b3);
                mma_f16(o[1][2 * half_n + 1], a[1][0], a[1][1], a[1][2], a[1][3], b2, b3);
            }
        }
    }

#pragma unroll
    for (int mt = 0; mt < 2; mt++) {
        const int r0 = wm * 32 + mt * 16 + ar;
        const float i0 = 1.f / l_st[mt][0];
        const float i1 = 1.f / l_st[mt][1];
        float* c0p = Ctx + (size_t)(qi * 64 + r0) * HID + h * DHEAD;
        float* c1p = c0p + 8 * HID;
#pragma unroll
        for (int nt = 0; nt < 4; nt++) {
            const int cb = wn * 32 + nt * 8 + 2 * ak;
            *(float2*)(c0p + cb) = make_float2(o[mt][nt][0] * i0, o[mt][nt][1] * i0);
            *(float2*)(c1p + cb) = make_float2(o[mt][nt][2] * i1, o[mt][nt][3] * i1);
        }
    }
}

// ---------------------------------------------------------------------------
// Per-(s,kvhead) RMSNorm + RoPE for K, in place (fp32).
// ---------------------------------------------------------------------------
__global__ __launch_bounds__(128) void k_normrope(
    float* __restrict__ X, int rowstride,
    const float* __restrict__ sin_t, const float* __restrict__ cos_t,
    const float* __restrict__ w)
{
    const int s = blockIdx.x;
    const int h = blockIdx.y;
    const int d = threadIdx.x;
    float* row = X + (size_t)s * rowstride + h * DHEAD;
    float v = row[d];
    float ss = v * v;
#pragma unroll
    for (int o = 16; o > 0; o >>= 1) ss += __shfl_xor_sync(0xffffffffu, ss, o);
    __shared__ float wsum[4];
    if ((d & 31) == 0) wsum[d >> 5] = ss;
    __syncthreads();
    float tot = wsum[0] + wsum[1] + wsum[2] + wsum[3];
    float inv = rsqrtf(tot * (1.0f / 128.0f) + 1.1920928955078125e-07f);
    __shared__ float xn[128];
    float xv = v * inv * w[d];
    xn[d] = xv;
    __syncthreads();
    float rot = (d < 64) ? -xn[d + 64] : xn[d - 64];
    row[d] = cos_t[s * DHEAD + d] * xv + sin_t[s * DHEAD + d] * rot;
}

// ---------------------------------------------------------------------------
// Launch
// ---------------------------------------------------------------------------
extern "C" void kernel_launch(void* const* d_in, const int* in_sizes, int n_in,
                              void* d_out, int out_size)
{
    (void)in_sizes; (void)n_in; (void)out_size;
    const float* x     = (const float*)d_in[0];
    const float* sin_t = (const float*)d_in[1];
    const float* cos_t = (const float*)d_in[2];
    const float* wq    = (const float*)d_in[4];
    const float* wk    = (const float*)d_in[5];
    const float* wv    = (const float*)d_in[6];
    const float* wo    = (const float*)d_in[7];
    const float* qnw   = (const float*)d_in[8];
    const float* knw   = (const float*)d_in[9];
    float* out = (float*)d_out;

    float *q, *k, *v, *ctx;
    cudaGetSymbolAddress((void**)&q,   g_q);
    cudaGetSymbolAddress((void**)&k,   g_k);
    cudaGetSymbolAddress((void**)&v,   g_v);
    cudaGetSymbolAddress((void**)&ctx, g_ctx);

    cudaFuncSetAttribute(k_flash, cudaFuncAttributeMaxDynamicSharedMemorySize, FLASH_SMEM);

    // Fused QKV projection (one launch, 384 CTAs)
    k_gemm_qkv<<<dim3((HID + 2 * KVW) / 128, SEQ / 128), 256>>>(x, wq, wk, wv, q, k, v);

    // RMSNorm + RoPE for K (Q's is fused into k_flash)
    k_normrope<<<dim3(SEQ, NKVH), 128>>>(k, KVW, sin_t, cos_t, knw);

    // Fused flash attention (BK=128)
    k_flash<<<512, 256, FLASH_SMEM>>>(q, k, v, ctx, sin_t, cos_t, qnw);

    // Output projection
    k_gemm_tn<<<dim3(HID / 128, SEQ / 128), 256>>>(ctx, HID, wo, HID, out, HID, HID);
}

// round 9
// speedup vs baseline: 8.1506x; 1.4563x over previous
#include <cuda_runtime.h>
#include <cuda_fp16.h>
#include <math.h>
#include <stddef.h>
#include <stdint.h>

// Problem constants (B=1)
#define SEQ   2048
#define HID   2048
#define NHEADS 16
#define NKVH   4
#define DHEAD  128
#define KVW   (NKVH * DHEAD)      // 512
#define GQA_REP (NHEADS / NKVH)   // 4

// fp16 scratch
__device__ __half g_xh [SEQ * HID];
__device__ __half g_wqh[HID * HID];
__device__ __half g_wkh[KVW * HID];
__device__ __half g_wvh[KVW * HID];
__device__ __half g_woh[HID * HID];
__device__ __half g_qh [SEQ * HID];
__device__ __half g_kh [SEQ * KVW];
__device__ __half g_vh [SEQ * KVW];
__device__ __half g_ctxh[SEQ * HID];

// ---------------------------------------------------------------------------
// helpers
// ---------------------------------------------------------------------------
__device__ __forceinline__ float ex2(float x) {
    float y;
    asm("ex2.approx.ftz.f32 %0, %1;" : "=f"(y) : "f"(x));
    return y;
}
__device__ __forceinline__ float exp2poly(float x) {
    const float MAGIC = 12582912.f;
    float t = fmaxf(x, -126.f);
    float r = t + MAGIC;
    float n = r - MAGIC;
    float f = t - n;
    float p = 1.3333558146e-3f;
    p = fmaf(p, f, 9.6181291076e-3f);
    p = fmaf(p, f, 5.5504108664e-2f);
    p = fmaf(p, f, 2.4022650696e-1f);
    p = fmaf(p, f, 6.9314718056e-1f);
    p = fmaf(p, f, 1.0f);
    int sb = (__float_as_int(r) << 23) + (127 << 23);
    return p * __int_as_float(sb);
}
__device__ __forceinline__ void mma_f16(float c[4],
                                        uint32_t a0, uint32_t a1, uint32_t a2, uint32_t a3,
                                        uint32_t b0, uint32_t b1) {
    asm volatile(
        "mma.sync.aligned.m16n8k16.row.col.f32.f16.f16.f32 "
        "{%0,%1,%2,%3}, {%4,%5,%6,%7}, {%8,%9}, {%0,%1,%2,%3};"
        : "+f"(c[0]), "+f"(c[1]), "+f"(c[2]), "+f"(c[3])
        : "r"(a0), "r"(a1), "r"(a2), "r"(a3), "r"(b0), "r"(b1));
}
__device__ __forceinline__ void ldsm_x4(uint32_t& r0, uint32_t& r1, uint32_t& r2, uint32_t& r3,
                                        uint32_t addr) {
    asm volatile("ldmatrix.sync.aligned.m8n8.x4.shared.b16 {%0,%1,%2,%3}, [%4];"
                 : "=r"(r0), "=r"(r1), "=r"(r2), "=r"(r3) : "r"(addr));
}
__device__ __forceinline__ void ldsm_x4t(uint32_t& r0, uint32_t& r1, uint32_t& r2, uint32_t& r3,
                                         uint32_t addr) {
    asm volatile("ldmatrix.sync.aligned.m8n8.x4.trans.shared.b16 {%0,%1,%2,%3}, [%4];"
                 : "=r"(r0), "=r"(r1), "=r"(r2), "=r"(r3) : "r"(addr));
}
__device__ __forceinline__ uint32_t ldsmA_off(int lane, int stride_bytes) {
    return (uint32_t)((lane & 15) * stride_bytes + (((lane >> 4) & 1) << 4));
}
__device__ __forceinline__ uint32_t ldsmB_off(int lane, int stride_bytes) {
    int row = (lane & 7) + ((lane & 16) >> 1);
    return (uint32_t)(row * stride_bytes + (((lane >> 3) & 1) << 4));
}
__device__ __forceinline__ __half2 fh2(float x, float y) { return __floats2half2_rn(x, y); }

#define CP16(s, g)  asm volatile("cp.async.cg.shared.global [%0], [%1], 16;" :: "r"(s), "l"(g))
#define CPCOMMIT()  asm volatile("cp.async.commit_group;")
#define CPWAIT(n)   asm volatile("cp.async.wait_group " #n ";")

// ---------------------------------------------------------------------------
// fp32 -> fp16 convert (exact grid: n/2048 blocks, 8 elems/thread)
// ---------------------------------------------------------------------------
__global__ __launch_bounds__(256) void k_cvt(const float* __restrict__ s,
                                             __half* __restrict__ d) {
    const int i = (blockIdx.x * 256 + threadIdx.x) * 8;
    float4 a = *(const float4*)(s + i);
    float4 b = *(const float4*)(s + i + 4);
    __half2 h0 = fh2(a.x, a.y), h1 = fh2(a.z, a.w);
    __half2 h2 = fh2(b.x, b.y), h3 = fh2(b.z, b.w);
    uint4 u;
    u.x = *(uint32_t*)&h0; u.y = *(uint32_t*)&h1;
    u.z = *(uint32_t*)&h2; u.w = *(uint32_t*)&h3;
    *(uint4*)(d + i) = u;
}

// ---------------------------------------------------------------------------
// TN GEMM (fp16 in via cp.async 4-stage pipeline): C = A[M,K]*B[N,K]^T
// ---------------------------------------------------------------------------
#define GSTR  24
#define GSTRB (GSTR * 2)
#define NSTG  4
#define STGB  (128 * GSTRB)       // 6144 bytes per stage per operand

template <bool HALF_OUT>
__device__ __forceinline__ void gemm_tn_f16(
    const __half* __restrict__ A, int lda,
    const __half* __restrict__ B, int ldb,
    void* __restrict__ Cv, int ldc,
    int K, int bm, int bn)
{
    __shared__ __half As[NSTG][128][GSTR];
    __shared__ __half Bs[NSTG][128][GSTR];
    const int tid  = threadIdx.x;
    const int lane = tid & 31;
    const int w    = tid >> 5;
    const int wm   = w >> 1;
    const int wn   = w & 1;

    float acc[2][8][4];
#pragma unroll
    for (int mt = 0; mt < 2; mt++)
#pragma unroll
        for (int nt = 0; nt < 8; nt++)
#pragma unroll
            for (int i = 0; i < 4; i++) acc[mt][nt][i] = 0.f;

    const int lrow = tid >> 1;              // 0..127
    const int lch  = (tid & 1) << 3;        // 0 or 8 halves
    const __half* Ag = A + (size_t)(bm + lrow) * lda + lch;
    const __half* Bg = B + (size_t)(bn + lrow) * ldb + lch;
    const uint32_t sA = (uint32_t)__cvta_generic_to_shared(&As[0][0][0]) + lrow * GSTRB + lch * 2;
    const uint32_t sB = (uint32_t)__cvta_generic_to_shared(&Bs[0][0][0]) + lrow * GSTRB + lch * 2;

    const uint32_t asb = (uint32_t)__cvta_generic_to_shared(&As[0][0][0]);
    const uint32_t bsb = (uint32_t)__cvta_generic_to_shared(&Bs[0][0][0]);
    const uint32_t aoff = ldsmA_off(lane, GSTRB) + (uint32_t)(wm * 32) * GSTRB;
    const uint32_t boff = ldsmB_off(lane, GSTRB) + (uint32_t)(wn * 64) * GSTRB;

    const int nch = K >> 4;
    // prologue: stages 0..2
#pragma unroll
    for (int s = 0; s < NSTG - 1; s++) {
        CP16(sA + s * STGB, Ag + s * 16);
        CP16(sB + s * STGB, Bg + s * 16);
        CPCOMMIT();
    }

    for (int i = 0; i < nch; i++) {
        CPWAIT(2);
        __syncthreads();
        const int nc = i + NSTG - 1;
        if (nc < nch) {
            const uint32_t stg = (uint32_t)(nc & (NSTG - 1)) * STGB;
            CP16(sA + stg, Ag + nc * 16);
            CP16(sB + stg, Bg + nc * 16);
        }
        CPCOMMIT();

        const uint32_t st = (uint32_t)(i & (NSTG - 1)) * STGB;
        const uint32_t ab = asb + st + aoff;
        const uint32_t bb = bsb + st + boff;
        uint32_t a[2][4];
        ldsm_x4(a[0][0], a[0][1], a[0][2], a[0][3], ab);
        ldsm_x4(a[1][0], a[1][1], a[1][2], a[1][3], ab + 16 * GSTRB);
#pragma unroll
        for (int pr = 0; pr < 4; pr++) {
            uint32_t b0, b1, b2, b3;
            ldsm_x4(b0, b1, b2, b3, bb + (uint32_t)pr * 16 * GSTRB);
            mma_f16(acc[0][2 * pr],     a[0][0], a[0][1], a[0][2], a[0][3], b0, b1);
            mma_f16(acc[1][2 * pr],     a[1][0], a[1][1], a[1][2], a[1][3], b0, b1);
            mma_f16(acc[0][2 * pr + 1], a[0][0], a[0][1], a[0][2], a[0][3], b2, b3);
            mma_f16(acc[1][2 * pr + 1], a[1][0], a[1][1], a[1][2], a[1][3], b2, b3);
        }
    }

    const int ar = lane >> 2;
    const int ak = lane & 3;
#pragma unroll
    for (int mt = 0; mt < 2; mt++) {
        const int r0 = bm + wm * 32 + mt * 16 + ar;
#pragma unroll
        for (int nt = 0; nt < 8; nt++) {
            const int cidx = bn + wn * 64 + nt * 8 + 2 * ak;
            if (HALF_OUT) {
                __half* C = (__half*)Cv;
                *(__half2*)(C + (size_t)r0 * ldc + cidx)       = fh2(acc[mt][nt][0], acc[mt][nt][1]);
                *(__half2*)(C + (size_t)(r0 + 8) * ldc + cidx) = fh2(acc[mt][nt][2], acc[mt][nt][3]);
            } else {
                float* C = (float*)Cv;
                *(float2*)(C + (size_t)r0 * ldc + cidx)       = make_float2(acc[mt][nt][0], acc[mt][nt][1]);
                *(float2*)(C + (size_t)(r0 + 8) * ldc + cidx) = make_float2(acc[mt][nt][2], acc[mt][nt][3]);
            }
        }
    }
}

// Fused QKV projection (3072 output cols, fp16 out)
__global__ __launch_bounds__(256, 2) void k_gemm_qkv(
    const __half* __restrict__ x,
    const __half* __restrict__ wq, const __half* __restrict__ wk,
    const __half* __restrict__ wv,
    __half* __restrict__ q, __half* __restrict__ k, __half* __restrict__ v)
{
    const int bnx = blockIdx.x * 128;
    const __half* B; __half* C; int ldc; int bn;
    if (bnx < HID)            { B = wq; C = q; ldc = HID; bn = bnx; }
    else if (bnx < HID + KVW) { B = wk; C = k; ldc = KVW; bn = bnx - HID; }
    else                      { B = wv; C = v; ldc = KVW; bn = bnx - HID - KVW; }
    gemm_tn_f16<true>(x, HID, B, HID, C, ldc, HID, blockIdx.y * 128, bn);
}

// Output projection (fp32 out)
__global__ __launch_bounds__(256, 2) void k_gemm_o(
    const __half* __restrict__ A, const __half* __restrict__ B,
    float* __restrict__ C)
{
    gemm_tn_f16<false>(A, HID, B, HID, C, HID, HID, blockIdx.y * 128, blockIdx.x * 128);
}

// ---------------------------------------------------------------------------
// Fused flash attention (fp16 mma, BK=128, cp.async K/V loads, fp16 I/O)
// ---------------------------------------------------------------------------
#define FSTR  136
#define FSTRB (FSTR * 2)
#define QS_OFF   0
#define KS_OFF   (64 * FSTRB)
#define VS_OFF   (KS_OFF + 128 * FSTRB)
#define RMX_OFF  (VS_OFF + 128 * FSTRB)
#define RSM_OFF  (RMX_OFF + 4 * 64 * 4)
#define CRR_OFF  (RSM_OFF + 4 * 64 * 4)
#define FLASH_SMEM (CRR_OFF + 64 * 4)            // 89344

__global__ __launch_bounds__(256, 2) void k_flash(
    const __half* __restrict__ Qg, const __half* __restrict__ Kg,
    const __half* __restrict__ Vg, __half* __restrict__ Ctx,
    const float* __restrict__ sin_t, const float* __restrict__ cos_t,
    const float* __restrict__ qnw)
{
    extern __shared__ char smem[];
    __half (*Qs)[FSTR]  = (__half(*)[FSTR])(smem + QS_OFF);
    __half (*Ks)[FSTR]  = (__half(*)[FSTR])(smem + KS_OFF);   // rows 0..63 reused as P
    float (*redmax)[64] = (float(*)[64])(smem + RMX_OFF);
    float (*redsum)[64] = (float(*)[64])(smem + RSM_OFF);
    float* corrs        = (float*)(smem + CRR_OFF);

    const int bid = blockIdx.x;
    const int h   = bid & 15;
    const int qi  = 31 - (bid >> 4);
    const int kvh = h >> 2;

    const int tid  = threadIdx.x;
    const int lane = tid & 31;
    const int w    = tid >> 5;
    const int wm   = w >> 2;
    const int wn   = w & 3;
    const int ar   = lane >> 2;
    const int ak   = lane & 3;
    const float C  = (float)(0.08838834764831843 * 1.4426950408889634);

    const uint32_t qsb = (uint32_t)__cvta_generic_to_shared(&Qs[0][0]);
    const uint32_t ksb = (uint32_t)__cvta_generic_to_shared(&Ks[0][0]);
    const uint32_t vsb = (uint32_t)__cvta_generic_to_shared(smem + VS_OFF);
    const uint32_t aoff = ldsmA_off(lane, FSTRB) + (uint32_t)(wm * 32) * FSTRB;
    const uint32_t boff = ldsmB_off(lane, FSTRB) + (uint32_t)(wn * 32) * FSTRB;
    const uint32_t voff = (uint32_t)(((lane & 7) + ((lane >> 3) & 1) * 8) * FSTRB
                                     + (((lane >> 4) & 1) * 8 + wn * 32) * 2);

    // Q tile [64 x 128]: fp16 q -> fp32 RMSNorm + RoPE -> fp16 smem
    {
        const int r  = tid >> 2;
        const int c0 = (tid & 3) << 2;
        const int s  = qi * 64 + r;
        const __half* qp = Qg + (size_t)s * HID + h * DHEAD;
        float4 qa[8];
        float ss = 0.f;
#pragma unroll
        for (int i = 0; i < 8; i++) {
            const __half2* ph = (const __half2*)(qp + c0 + 16 * i);
            float2 f01 = __half22float2(ph[0]);
            float2 f23 = __half22float2(ph[1]);
            qa[i] = make_float4(f01.x, f01.y, f23.x, f23.y);
            ss += qa[i].x * qa[i].x + qa[i].y * qa[i].y + qa[i].z * qa[i].z + qa[i].w * qa[i].w;
        }
        ss += __shfl_xor_sync(0xffffffffu, ss, 1);
        ss += __shfl_xor_sync(0xffffffffu, ss, 2);
        const float inv = rsqrtf(ss * (1.0f / 128.0f) + 1.1920928955078125e-07f);
        float4 xn[8];
#pragma unroll
        for (int i = 0; i < 8; i++) {
            float4 wv4 = *(const float4*)(qnw + c0 + 16 * i);
            xn[i] = make_float4(qa[i].x * inv * wv4.x, qa[i].y * inv * wv4.y,
                                qa[i].z * inv * wv4.z, qa[i].w * inv * wv4.w);
        }
        const float* sp = sin_t + (size_t)s * DHEAD;
        const float* cp = cos_t + (size_t)s * DHEAD;
#pragma unroll
        for (int i = 0; i < 8; i++) {
            const int c = c0 + 16 * i;
            float4 s4 = *(const float4*)(sp + c);
            float4 c4 = *(const float4*)(cp + c);
            float4 rot = (i < 4)
                ? make_float4(-xn[i + 4].x, -xn[i + 4].y, -xn[i + 4].z, -xn[i + 4].w)
                : xn[i - 4];
            *(__half2*)&Qs[r][c]     = fh2(c4.x * xn[i].x + s4.x * rot.x,
                                           c4.y * xn[i].y + s4.y * rot.y);
            *(__half2*)&Qs[r][c + 2] = fh2(c4.z * xn[i].z + s4.z * rot.z,
                                           c4.w * xn[i].w + s4.w * rot.w);
        }
    }

    float o[2][4][4];
    float m_st[2][2], l_st[2][2];
#pragma unroll
    for (int mt = 0; mt < 2; mt++) {
#pragma unroll
        for (int nt = 0; nt < 4; nt++)
#pragma unroll
            for (int c = 0; c < 4; c++) o[mt][nt][c] = 0.f;
        m_st[mt][0] = m_st[mt][1] = -1e30f;
        l_st[mt][0] = l_st[mt][1] = 0.f;
    }

    const int nj = (qi >> 1) + 1;
    for (int j = 0; j < nj; j++) {
        __syncthreads();
        {   // cp.async K,V tiles [128 x 128] fp16
            const __half* kb = Kg + (size_t)(j * 128) * KVW + kvh * DHEAD;
            const __half* vb = Vg + (size_t)(j * 128) * KVW + kvh * DHEAD;
#pragma unroll
            for (int it = 0; it < 8; it++) {
                const int idx = tid + 256 * it;
                const int r   = idx >> 4;
                const int ch  = (idx & 15) << 3;
                CP16(ksb + r * FSTRB + ch * 2, kb + (size_t)r * KVW + ch);
                CP16(vsb + r * FSTRB + ch * 2, vb + (size_t)r * KVW + ch);
            }
            CPCOMMIT();
            CPWAIT(0);
        }
        __syncthreads();

        // S = Q*K^T  (64 x 128, K=128)
        float s[2][4][4];
#pragma unroll
        for (int mt = 0; mt < 2; mt++)
#pragma unroll
            for (int nt = 0; nt < 4; nt++)
#pragma unroll
                for (int c = 0; c < 4; c++) s[mt][nt][c] = 0.f;
#pragma unroll
        for (int ks = 0; ks < 128; ks += 16) {
            uint32_t a[2][4];
            ldsm_x4(a[0][0], a[0][1], a[0][2], a[0][3], qsb + aoff + ks * 2);
            ldsm_x4(a[1][0], a[1][1], a[1][2], a[1][3], qsb + aoff + 16 * FSTRB + ks * 2);
#pragma unroll
            for (int pr = 0; pr < 2; pr++) {
                uint32_t b0, b1, b2, b3;
                ldsm_x4(b0, b1, b2, b3, ksb + boff + (uint32_t)pr * 16 * FSTRB + ks * 2);
                mma_f16(s[0][2 * pr],     a[0][0], a[0][1], a[0][2], a[0][3], b0, b1);
                mma_f16(s[1][2 * pr],     a[1][0], a[1][1], a[1][2], a[1][3], b0, b1);
                mma_f16(s[0][2 * pr + 1], a[0][0], a[0][1], a[0][2], a[0][3], b2, b3);
                mma_f16(s[1][2 * pr + 1], a[1][0], a[1][1], a[1][2], a[1][3], b2, b3);
            }
        }

        if (j == nj - 1) {
            const int col0 = j * 128;
            const int row0 = qi * 64;
#pragma unroll
            for (int mt = 0; mt < 2; mt++)
#pragma unroll
                for (int nt = 0; nt < 4; nt++) {
                    const int colb = col0 + wn * 32 + nt * 8 + 2 * ak;
#pragma unroll
                    for (int cc = 0; cc < 4; cc++) {
                        const int row_g = row0 + wm * 32 + mt * 16 + ar + (cc >> 1) * 8;
                        const int col_g = colb + (cc & 1);
                        if (col_g > row_g) s[mt][nt][cc] = -1e30f;
                    }
                }
        }

#pragma unroll
        for (int mt = 0; mt < 2; mt++) {
            float r0m = fmaxf(fmaxf(s[mt][0][0], s[mt][0][1]), fmaxf(s[mt][1][0], s[mt][1][1]));
            r0m = fmaxf(r0m, fmaxf(fmaxf(s[mt][2][0], s[mt][2][1]), fmaxf(s[mt][3][0], s[mt][3][1])));
            float r1m = fmaxf(fmaxf(s[mt][0][2], s[mt][0][3]), fmaxf(s[mt][1][2], s[mt][1][3]));
            r1m = fmaxf(r1m, fmaxf(fmaxf(s[mt][2][2], s[mt][2][3]), fmaxf(s[mt][3][2], s[mt][3][3])));
            r0m = fmaxf(r0m, __shfl_xor_sync(0xffffffffu, r0m, 1));
            r0m = fmaxf(r0m, __shfl_xor_sync(0xffffffffu, r0m, 2));
            r1m = fmaxf(r1m, __shfl_xor_sync(0xffffffffu, r1m, 1));
            r1m = fmaxf(r1m, __shfl_xor_sync(0xffffffffu, r1m, 2));
            if (ak == 0) {
                redmax[wn][wm * 32 + mt * 16 + ar]     = r0m;
                redmax[wn][wm * 32 + mt * 16 + ar + 8] = r1m;
            }
        }
        __syncthreads();

        float m_new[2][2];
#pragma unroll
        for (int mt = 0; mt < 2; mt++)
#pragma unroll
            for (int hh = 0; hh < 2; hh++) {
                const int row = wm * 32 + mt * 16 + ar + hh * 8;
                float mr = fmaxf(fmaxf(redmax[0][row], redmax[1][row]),
                                 fmaxf(redmax[2][row], redmax[3][row]));
                m_new[mt][hh] = fmaxf(m_st[mt][hh], mr);
                if (wn == 0 && ak == 0)
                    corrs[row] = ex2((m_st[mt][hh] - m_new[mt][hh]) * C);
            }

        float psum[2][2];
        psum[0][0] = psum[0][1] = psum[1][0] = psum[1][1] = 0.f;
#pragma unroll
        for (int mt = 0; mt < 2; mt++) {
            const float mC0 = m_new[mt][0] * C;
            const float mC1 = m_new[mt][1] * C;
#pragma unroll
            for (int nt = 0; nt < 4; nt++) {
                const int colb = wn * 32 + nt * 8 + 2 * ak;
                float p0 = exp2poly(fmaf(s[mt][nt][0], C, -mC0));
                float p1 = exp2poly(fmaf(s[mt][nt][1], C, -mC0));
                float p2 = ex2(fmaf(s[mt][nt][2], C, -mC1));
                float p3 = ex2(fmaf(s[mt][nt][3], C, -mC1));
                psum[mt][0] += p0 + p1;
                psum[mt][1] += p2 + p3;
                const int r0 = wm * 32 + mt * 16 + ar;
                *(__half2*)&Ks[r0][colb]     = fh2(p0, p1);
                *(__half2*)&Ks[r0 + 8][colb] = fh2(p2, p3);
            }
        }
#pragma unroll
        for (int mt = 0; mt < 2; mt++) {
            psum[mt][0] += __shfl_xor_sync(0xffffffffu, psum[mt][0], 1);
            psum[mt][0] += __shfl_xor_sync(0xffffffffu, psum[mt][0], 2);
            psum[mt][1] += __shfl_xor_sync(0xffffffffu, psum[mt][1], 1);
            psum[mt][1] += __shfl_xor_sync(0xffffffffu, psum[mt][1], 2);
            if (ak == 0) {
                redsum[wn][wm * 32 + mt * 16 + ar]     = psum[mt][0];
                redsum[wn][wm * 32 + mt * 16 + ar + 8] = psum[mt][1];
            }
        }
        __syncthreads();

        float corr[2][2];
#pragma unroll
        for (int mt = 0; mt < 2; mt++)
#pragma unroll
            for (int hh = 0; hh < 2; hh++) {
                const int row = wm * 32 + mt * 16 + ar + hh * 8;
                float sm = (redsum[0][row] + redsum[1][row]) + (redsum[2][row] + redsum[3][row]);
                corr[mt][hh] = corrs[row];
                l_st[mt][hh] = l_st[mt][hh] * corr[mt][hh] + sm;
                m_st[mt][hh] = m_new[mt][hh];
            }
#pragma unroll
        for (int mt = 0; mt < 2; mt++)
#pragma unroll
            for (int nt = 0; nt < 4; nt++) {
                o[mt][nt][0] *= corr[mt][0];
                o[mt][nt][1] *= corr[mt][0];
                o[mt][nt][2] *= corr[mt][1];
                o[mt][nt][3] *= corr[mt][1];
            }

        // O += P * V  (64x128, K=128); V via ldmatrix.trans
#pragma unroll
        for (int ks = 0; ks < 128; ks += 16) {
            uint32_t a[2][4];
            ldsm_x4(a[0][0], a[0][1], a[0][2], a[0][3], ksb + aoff + ks * 2);
            ldsm_x4(a[1][0], a[1][1], a[1][2], a[1][3], ksb + aoff + 16 * FSTRB + ks * 2);
#pragma unroll
            for (int half_n = 0; half_n < 2; half_n++) {
                uint32_t b0, b1, b2, b3;
                ldsm_x4t(b0, b1, b2, b3, vsb + voff + (uint32_t)ks * FSTRB + half_n * 32);
                mma_f16(o[0][2 * half_n],     a[0][0], a[0][1], a[0][2], a[0][3], b0, b1);
                mma_f16(o[1][2 * half_n],     a[1][0], a[1][1], a[1][2], a[1][3], b0, b1);
                mma_f16(o[0][2 * half_n + 1], a[0][0], a[0][1], a[0][2], a[0][3], b2, b3);
                mma_f16(o[1][2 * half_n + 1], a[1][0], a[1][1], a[1][2], a[1][3], b2, b3);
            }
        }
    }

    // epilogue: normalize, write ctx as fp16
#pragma unroll
    for (int mt = 0; mt < 2; mt++) {
        const int r0 = wm * 32 + mt * 16 + ar;
        const float i0 = 1.f / l_st[mt][0];
        const float i1 = 1.f / l_st[mt][1];
        __half* c0p = Ctx + (size_t)(qi * 64 + r0) * HID + h * DHEAD;
        __half* c1p = c0p + 8 * HID;
#pragma unroll
        for (int nt = 0; nt < 4; nt++) {
            const int cb = wn * 32 + nt * 8 + 2 * ak;
            *(__half2*)(c0p + cb) = fh2(o[mt][nt][0] * i0, o[mt][nt][1] * i0);
            *(__half2*)(c1p + cb) = fh2(o[mt][nt][2] * i1, o[mt][nt][3] * i1);
        }
    }
}

// ---------------------------------------------------------------------------
// Per-(s,kvhead) RMSNorm + RoPE for K, in place on fp16.
// ---------------------------------------------------------------------------
__global__ __launch_bounds__(128) void k_normrope_h(
    __half* __restrict__ X, int rowstride,
    const float* __restrict__ sin_t, const float* __restrict__ cos_t,
    const float* __restrict__ w)
{
    const int s = blockIdx.x;
    const int h = blockIdx.y;
    const int d = threadIdx.x;
    __half* row = X + (size_t)s * rowstride + h * DHEAD;
    float v = __half2float(row[d]);
    float ss = v * v;
#pragma unroll
    for (int o = 16; o > 0; o >>= 1) ss += __shfl_xor_sync(0xffffffffu, ss, o);
    __shared__ float wsum[4];
    if ((d & 31) == 0) wsum[d >> 5] = ss;
    __syncthreads();
    float tot = wsum[0] + wsum[1] + wsum[2] + wsum[3];
    float inv = rsqrtf(tot * (1.0f / 128.0f) + 1.1920928955078125e-07f);
    __shared__ float xn[128];
    float xv = v * inv * w[d];
    xn[d] = xv;
    __syncthreads();
    float rot = (d < 64) ? -xn[d + 64] : xn[d - 64];
    row[d] = __float2half(cos_t[s * DHEAD + d] * xv + sin_t[s * DHEAD + d] * rot);
}

// ---------------------------------------------------------------------------
// Launch
// ---------------------------------------------------------------------------
extern "C" void kernel_launch(void* const* d_in, const int* in_sizes, int n_in,
                              void* d_out, int out_size)
{
    (void)in_sizes; (void)n_in; (void)out_size;
    const float* x     = (const float*)d_in[0];
    const float* sin_t = (const float*)d_in[1];
    const float* cos_t = (const float*)d_in[2];
    const float* wq    = (const float*)d_in[4];
    const float* wk    = (const float*)d_in[5];
    const float* wv    = (const float*)d_in[6];
    const float* wo    = (const float*)d_in[7];
    const float* qnw   = (const float*)d_in[8];
    const float* knw   = (const float*)d_in[9];
    float* out = (float*)d_out;

    __half *xh, *wqh, *wkh, *wvh, *woh, *qh, *kh, *vh, *ctxh;
    cudaGetSymbolAddress((void**)&xh,   g_xh);
    cudaGetSymbolAddress((void**)&wqh,  g_wqh);
    cudaGetSymbolAddress((void**)&wkh,  g_wkh);
    cudaGetSymbolAddress((void**)&wvh,  g_wvh);
    cudaGetSymbolAddress((void**)&woh,  g_woh);
    cudaGetSymbolAddress((void**)&qh,   g_qh);
    cudaGetSymbolAddress((void**)&kh,   g_kh);
    cudaGetSymbolAddress((void**)&vh,   g_vh);
    cudaGetSymbolAddress((void**)&ctxh, g_ctxh);

    cudaFuncSetAttribute(k_flash, cudaFuncAttributeMaxDynamicSharedMemorySize, FLASH_SMEM);

    // fp32 -> fp16 conversions (exact grids: n/2048 blocks)
    k_cvt<<<SEQ * HID / 2048, 256>>>(x,  xh);
    k_cvt<<<HID * HID / 2048, 256>>>(wq, wqh);
    k_cvt<<<KVW * HID / 2048, 256>>>(wk, wkh);
    k_cvt<<<KVW * HID / 2048, 256>>>(wv, wvh);
    k_cvt<<<HID * HID / 2048, 256>>>(wo, woh);

    // Fused QKV projection (fp16 in/out)
    k_gemm_qkv<<<dim3((HID + 2 * KVW) / 128, SEQ / 128), 256>>>(xh, wqh, wkh, wvh, qh, kh, vh);

    // RMSNorm + RoPE for K
    k_normrope_h<<<dim3(SEQ, NKVH), 128>>>(kh, KVW, sin_t, cos_t, knw);

    // Fused flash attention (fp16 q/k/v, fp16 ctx out)
    k_flash<<<512, 256, FLASH_SMEM>>>(qh, kh, vh, ctxh, sin_t, cos_t, qnw);

    // Output projection (fp16 in, fp32 out)
    k_gemm_o<<<dim3(HID / 128, SEQ / 128), 256>>>(ctxh, woh, out);
}

// round 10
// speedup vs baseline: 8.3614x; 1.0259x over previous
#include <cuda_runtime.h>
#include <cuda_fp16.h>
#include <math.h>
#include <stddef.h>
#include <stdint.h>

// Problem constants (B=1)
#define SEQ   2048
#define HID   2048
#define NHEADS 16
#define NKVH   4
#define DHEAD  128
#define KVW   (NKVH * DHEAD)      // 512
#define GQA_REP (NHEADS / NKVH)   // 4

// fp16 scratch
__device__ __half g_xh [SEQ * HID];
__device__ __half g_wqh[HID * HID];
__device__ __half g_wkh[KVW * HID];
__device__ __half g_wvh[KVW * HID];
__device__ __half g_woh[HID * HID];
__device__ __half g_qh [SEQ * HID];
__device__ __half g_kh [SEQ * KVW];
__device__ __half g_vh [SEQ * KVW];
__device__ __half g_ctxh[SEQ * HID];

// ---------------------------------------------------------------------------
// helpers
// ---------------------------------------------------------------------------
__device__ __forceinline__ float ex2(float x) {
    float y;
    asm("ex2.approx.ftz.f32 %0, %1;" : "=f"(y) : "f"(x));
    return y;
}
__device__ __forceinline__ float exp2poly(float x) {
    const float MAGIC = 12582912.f;
    float t = fmaxf(x, -126.f);
    float r = t + MAGIC;
    float n = r - MAGIC;
    float f = t - n;
    float p = 1.3333558146e-3f;
    p = fmaf(p, f, 9.6181291076e-3f);
    p = fmaf(p, f, 5.5504108664e-2f);
    p = fmaf(p, f, 2.4022650696e-1f);
    p = fmaf(p, f, 6.9314718056e-1f);
    p = fmaf(p, f, 1.0f);
    int sb = (__float_as_int(r) << 23) + (127 << 23);
    return p * __int_as_float(sb);
}
__device__ __forceinline__ void mma_f16(float c[4],
                                        uint32_t a0, uint32_t a1, uint32_t a2, uint32_t a3,
                                        uint32_t b0, uint32_t b1) {
    asm volatile(
        "mma.sync.aligned.m16n8k16.row.col.f32.f16.f16.f32 "
        "{%0,%1,%2,%3}, {%4,%5,%6,%7}, {%8,%9}, {%0,%1,%2,%3};"
        : "+f"(c[0]), "+f"(c[1]), "+f"(c[2]), "+f"(c[3])
        : "r"(a0), "r"(a1), "r"(a2), "r"(a3), "r"(b0), "r"(b1));
}
__device__ __forceinline__ void ldsm_x4(uint32_t& r0, uint32_t& r1, uint32_t& r2, uint32_t& r3,
                                        uint32_t addr) {
    asm volatile("ldmatrix.sync.aligned.m8n8.x4.shared.b16 {%0,%1,%2,%3}, [%4];"
                 : "=r"(r0), "=r"(r1), "=r"(r2), "=r"(r3) : "r"(addr));
}
__device__ __forceinline__ void ldsm_x4t(uint32_t& r0, uint32_t& r1, uint32_t& r2, uint32_t& r3,
                                         uint32_t addr) {
    asm volatile("ldmatrix.sync.aligned.m8n8.x4.trans.shared.b16 {%0,%1,%2,%3}, [%4];"
                 : "=r"(r0), "=r"(r1), "=r"(r2), "=r"(r3) : "r"(addr));
}
__device__ __forceinline__ uint32_t ldsmA_off(int lane, int stride_bytes) {
    return (uint32_t)((lane & 15) * stride_bytes + (((lane >> 4) & 1) << 4));
}
__device__ __forceinline__ uint32_t ldsmB_off(int lane, int stride_bytes) {
    int row = (lane & 7) + ((lane & 16) >> 1);
    return (uint32_t)(row * stride_bytes + (((lane >> 3) & 1) << 4));
}
__device__ __forceinline__ __half2 fh2(float x, float y) { return __floats2half2_rn(x, y); }

#define CP16(s, g)  asm volatile("cp.async.cg.shared.global [%0], [%1], 16;" :: "r"(s), "l"(g))
#define CPCOMMIT()  asm volatile("cp.async.commit_group;")
#define CPWAIT(n)   asm volatile("cp.async.wait_group " #n ";")

// ---------------------------------------------------------------------------
// Fused fp32 -> fp16 convert for all 5 tensors (one launch, region dispatch)
// blocks: x 2048 | wq 2048 | wk 512 | wv 512 | wo 2048  (8 elems/thread)
// ---------------------------------------------------------------------------
__global__ __launch_bounds__(256) void k_cvt_all(
    const float* __restrict__ x,  const float* __restrict__ wq,
    const float* __restrict__ wk, const float* __restrict__ wv,
    const float* __restrict__ wo)
{
    const int b = blockIdx.x;
    const float* s; __half* d; int base;
    if (b < 2048)      { s = x;  d = g_xh;  base = b; }
    else if (b < 4096) { s = wq; d = g_wqh; base = b - 2048; }
    else if (b < 4608) { s = wk; d = g_wkh; base = b - 4096; }
    else if (b < 5120) { s = wv; d = g_wvh; base = b - 4608; }
    else               { s = wo; d = g_woh; base = b - 5120; }
    const int i = (base * 256 + threadIdx.x) * 8;
    float4 a = *(const float4*)(s + i);
    float4 c = *(const float4*)(s + i + 4);
    __half2 h0 = fh2(a.x, a.y), h1 = fh2(a.z, a.w);
    __half2 h2 = fh2(c.x, c.y), h3 = fh2(c.z, c.w);
    uint4 u;
    u.x = *(uint32_t*)&h0; u.y = *(uint32_t*)&h1;
    u.z = *(uint32_t*)&h2; u.w = *(uint32_t*)&h3;
    *(uint4*)(d + i) = u;
}

// ---------------------------------------------------------------------------
// TN GEMM (fp16 in via cp.async 4-stage pipeline): C = A[M,K]*B[N,K]^T
// ---------------------------------------------------------------------------
#define GSTR  24
#define GSTRB (GSTR * 2)
#define NSTG  4
#define STGB  (128 * GSTRB)

template <bool HALF_OUT>
__device__ __forceinline__ void gemm_tn_f16(
    const __half* __restrict__ A, int lda,
    const __half* __restrict__ B, int ldb,
    void* __restrict__ Cv, int ldc,
    int K, int bm, int bn)
{
    __shared__ __half As[NSTG][128][GSTR];
    __shared__ __half Bs[NSTG][128][GSTR];
    const int tid  = threadIdx.x;
    const int lane = tid & 31;
    const int w    = tid >> 5;
    const int wm   = w >> 1;
    const int wn   = w & 1;

    float acc[2][8][4];
#pragma unroll
    for (int mt = 0; mt < 2; mt++)
#pragma unroll
        for (int nt = 0; nt < 8; nt++)
#pragma unroll
            for (int i = 0; i < 4; i++) acc[mt][nt][i] = 0.f;

    const int lrow = tid >> 1;
    const int lch  = (tid & 1) << 3;
    const __half* Ag = A + (size_t)(bm + lrow) * lda + lch;
    const __half* Bg = B + (size_t)(bn + lrow) * ldb + lch;
    const uint32_t sA = (uint32_t)__cvta_generic_to_shared(&As[0][0][0]) + lrow * GSTRB + lch * 2;
    const uint32_t sB = (uint32_t)__cvta_generic_to_shared(&Bs[0][0][0]) + lrow * GSTRB + lch * 2;

    const uint32_t asb = (uint32_t)__cvta_generic_to_shared(&As[0][0][0]);
    const uint32_t bsb = (uint32_t)__cvta_generic_to_shared(&Bs[0][0][0]);
    const uint32_t aoff = ldsmA_off(lane, GSTRB) + (uint32_t)(wm * 32) * GSTRB;
    const uint32_t boff = ldsmB_off(lane, GSTRB) + (uint32_t)(wn * 64) * GSTRB;

    const int nch = K >> 4;
#pragma unroll
    for (int s = 0; s < NSTG - 1; s++) {
        CP16(sA + s * STGB, Ag + s * 16);
        CP16(sB + s * STGB, Bg + s * 16);
        CPCOMMIT();
    }

    for (int i = 0; i < nch; i++) {
        CPWAIT(2);
        __syncthreads();
        const int nc = i + NSTG - 1;
        if (nc < nch) {
            const uint32_t stg = (uint32_t)(nc & (NSTG - 1)) * STGB;
            CP16(sA + stg, Ag + nc * 16);
            CP16(sB + stg, Bg + nc * 16);
        }
        CPCOMMIT();

        const uint32_t st = (uint32_t)(i & (NSTG - 1)) * STGB;
        const uint32_t ab = asb + st + aoff;
        const uint32_t bb = bsb + st + boff;
        uint32_t a[2][4];
        ldsm_x4(a[0][0], a[0][1], a[0][2], a[0][3], ab);
        ldsm_x4(a[1][0], a[1][1], a[1][2], a[1][3], ab + 16 * GSTRB);
#pragma unroll
        for (int pr = 0; pr < 4; pr++) {
            uint32_t b0, b1, b2, b3;
            ldsm_x4(b0, b1, b2, b3, bb + (uint32_t)pr * 16 * GSTRB);
            mma_f16(acc[0][2 * pr],     a[0][0], a[0][1], a[0][2], a[0][3], b0, b1);
            mma_f16(acc[1][2 * pr],     a[1][0], a[1][1], a[1][2], a[1][3], b0, b1);
            mma_f16(acc[0][2 * pr + 1], a[0][0], a[0][1], a[0][2], a[0][3], b2, b3);
            mma_f16(acc[1][2 * pr + 1], a[1][0], a[1][1], a[1][2], a[1][3], b2, b3);
        }
    }

    const int ar = lane >> 2;
    const int ak = lane & 3;
#pragma unroll
    for (int mt = 0; mt < 2; mt++) {
        const int r0 = bm + wm * 32 + mt * 16 + ar;
#pragma unroll
        for (int nt = 0; nt < 8; nt++) {
            const int cidx = bn + wn * 64 + nt * 8 + 2 * ak;
            if (HALF_OUT) {
                __half* C = (__half*)Cv;
                *(__half2*)(C + (size_t)r0 * ldc + cidx)       = fh2(acc[mt][nt][0], acc[mt][nt][1]);
                *(__half2*)(C + (size_t)(r0 + 8) * ldc + cidx) = fh2(acc[mt][nt][2], acc[mt][nt][3]);
            } else {
                float* C = (float*)Cv;
                *(float2*)(C + (size_t)r0 * ldc + cidx)       = make_float2(acc[mt][nt][0], acc[mt][nt][1]);
                *(float2*)(C + (size_t)(r0 + 8) * ldc + cidx) = make_float2(acc[mt][nt][2], acc[mt][nt][3]);
            }
        }
    }
}

__global__ __launch_bounds__(256, 2) void k_gemm_qkv(
    const __half* __restrict__ x,
    const __half* __restrict__ wq, const __half* __restrict__ wk,
    const __half* __restrict__ wv,
    __half* __restrict__ q, __half* __restrict__ k, __half* __restrict__ v)
{
    const int bnx = blockIdx.x * 128;
    const __half* B; __half* C; int ldc; int bn;
    if (bnx < HID)            { B = wq; C = q; ldc = HID; bn = bnx; }
    else if (bnx < HID + KVW) { B = wk; C = k; ldc = KVW; bn = bnx - HID; }
    else                      { B = wv; C = v; ldc = KVW; bn = bnx - HID - KVW; }
    gemm_tn_f16<true>(x, HID, B, HID, C, ldc, HID, blockIdx.y * 128, bn);
}

__global__ __launch_bounds__(256, 2) void k_gemm_o(
    const __half* __restrict__ A, const __half* __restrict__ B,
    float* __restrict__ C)
{
    gemm_tn_f16<false>(A, HID, B, HID, C, HID, HID, blockIdx.y * 128, blockIdx.x * 128);
}

// ---------------------------------------------------------------------------
// Fused flash attention (fp16 mma, BK=128): split K/V commit groups so the V
// transfer hides behind QK-MMA + softmax; poly/MUFU exp rebalanced 11:5.
// ---------------------------------------------------------------------------
#define FSTR  136
#define FSTRB (FSTR * 2)
#define QS_OFF   0
#define KS_OFF   (64 * FSTRB)
#define VS_OFF   (KS_OFF + 128 * FSTRB)
#define RMX_OFF  (VS_OFF + 128 * FSTRB)
#define RSM_OFF  (RMX_OFF + 4 * 64 * 4)
#define CRR_OFF  (RSM_OFF + 4 * 64 * 4)
#define FLASH_SMEM (CRR_OFF + 64 * 4)            // 89344

__global__ __launch_bounds__(256, 2) void k_flash(
    const __half* __restrict__ Qg, const __half* __restrict__ Kg,
    const __half* __restrict__ Vg, __half* __restrict__ Ctx,
    const float* __restrict__ sin_t, const float* __restrict__ cos_t,
    const float* __restrict__ qnw)
{
    extern __shared__ char smem[];
    __half (*Qs)[FSTR]  = (__half(*)[FSTR])(smem + QS_OFF);
    __half (*Ks)[FSTR]  = (__half(*)[FSTR])(smem + KS_OFF);   // rows 0..63 reused as P
    float (*redmax)[64] = (float(*)[64])(smem + RMX_OFF);
    float (*redsum)[64] = (float(*)[64])(smem + RSM_OFF);
    float* corrs        = (float*)(smem + CRR_OFF);

    const int bid = blockIdx.x;
    const int h   = bid & 15;
    const int qi  = 31 - (bid >> 4);
    const int kvh = h >> 2;

    const int tid  = threadIdx.x;
    const int lane = tid & 31;
    const int w    = tid >> 5;
    const int wm   = w >> 2;
    const int wn   = w & 3;
    const int ar   = lane >> 2;
    const int ak   = lane & 3;
    const float C  = (float)(0.08838834764831843 * 1.4426950408889634);

    const uint32_t qsb = (uint32_t)__cvta_generic_to_shared(&Qs[0][0]);
    const uint32_t ksb = (uint32_t)__cvta_generic_to_shared(&Ks[0][0]);
    const uint32_t vsb = (uint32_t)__cvta_generic_to_shared(smem + VS_OFF);
    const uint32_t aoff = ldsmA_off(lane, FSTRB) + (uint32_t)(wm * 32) * FSTRB;
    const uint32_t boff = ldsmB_off(lane, FSTRB) + (uint32_t)(wn * 32) * FSTRB;
    const uint32_t voff = (uint32_t)(((lane & 7) + ((lane >> 3) & 1) * 8) * FSTRB
                                     + (((lane >> 4) & 1) * 8 + wn * 32) * 2);

    // Q tile [64 x 128]: fp16 q -> fp32 RMSNorm + RoPE -> fp16 smem
    {
        const int r  = tid >> 2;
        const int c0 = (tid & 3) << 2;
        const int s  = qi * 64 + r;
        const __half* qp = Qg + (size_t)s * HID + h * DHEAD;
        float4 qa[8];
        float ss = 0.f;
#pragma unroll
        for (int i = 0; i < 8; i++) {
            const __half2* ph = (const __half2*)(qp + c0 + 16 * i);
            float2 f01 = __half22float2(ph[0]);
            float2 f23 = __half22float2(ph[1]);
            qa[i] = make_float4(f01.x, f01.y, f23.x, f23.y);
            ss += qa[i].x * qa[i].x + qa[i].y * qa[i].y + qa[i].z * qa[i].z + qa[i].w * qa[i].w;
        }
        ss += __shfl_xor_sync(0xffffffffu, ss, 1);
        ss += __shfl_xor_sync(0xffffffffu, ss, 2);
        const float inv = rsqrtf(ss * (1.0f / 128.0f) + 1.1920928955078125e-07f);
        float4 xn[8];
#pragma unroll
        for (int i = 0; i < 8; i++) {
            float4 wv4 = *(const float4*)(qnw + c0 + 16 * i);
            xn[i] = make_float4(qa[i].x * inv * wv4.x, qa[i].y * inv * wv4.y,
                                qa[i].z * inv * wv4.z, qa[i].w * inv * wv4.w);
        }
        const float* sp = sin_t + (size_t)s * DHEAD;
        const float* cp = cos_t + (size_t)s * DHEAD;
#pragma unroll
        for (int i = 0; i < 8; i++) {
            const int c = c0 + 16 * i;
            float4 s4 = *(const float4*)(sp + c);
            float4 c4 = *(const float4*)(cp + c);
            float4 rot = (i < 4)
                ? make_float4(-xn[i + 4].x, -xn[i + 4].y, -xn[i + 4].z, -xn[i + 4].w)
                : xn[i - 4];
            *(__half2*)&Qs[r][c]     = fh2(c4.x * xn[i].x + s4.x * rot.x,
                                           c4.y * xn[i].y + s4.y * rot.y);
            *(__half2*)&Qs[r][c + 2] = fh2(c4.z * xn[i].z + s4.z * rot.z,
                                           c4.w * xn[i].w + s4.w * rot.w);
        }
    }

    float o[2][4][4];
    float m_st[2][2], l_st[2][2];
#pragma unroll
    for (int mt = 0; mt < 2; mt++) {
#pragma unroll
        for (int nt = 0; nt < 4; nt++)
#pragma unroll
            for (int c = 0; c < 4; c++) o[mt][nt][c] = 0.f;
        m_st[mt][0] = m_st[mt][1] = -1e30f;
        l_st[mt][0] = l_st[mt][1] = 0.f;
    }

    const int nj = (qi >> 1) + 1;
    for (int j = 0; j < nj; j++) {
        __syncthreads();                     // prev iteration's P/V reads done
        {   // K tile group, then V tile group (separate commits)
            const __half* kb = Kg + (size_t)(j * 128) * KVW + kvh * DHEAD;
            const __half* vb = Vg + (size_t)(j * 128) * KVW + kvh * DHEAD;
#pragma unroll
            for (int it = 0; it < 8; it++) {
                const int idx = tid + 256 * it;
                const int r   = idx >> 4;
                const int ch  = (idx & 15) << 3;
                CP16(ksb + r * FSTRB + ch * 2, kb + (size_t)r * KVW + ch);
            }
            CPCOMMIT();
#pragma unroll
            for (int it = 0; it < 8; it++) {
                const int idx = tid + 256 * it;
                const int r   = idx >> 4;
                const int ch  = (idx & 15) << 3;
                CP16(vsb + r * FSTRB + ch * 2, vb + (size_t)r * KVW + ch);
            }
            CPCOMMIT();
            CPWAIT(1);                       // K arrived; V still in flight
        }
        __syncthreads();

        // S = Q*K^T  (64 x 128, K=128)
        float s[2][4][4];
#pragma unroll
        for (int mt = 0; mt < 2; mt++)
#pragma unroll
            for (int nt = 0; nt < 4; nt++)
#pragma unroll
                for (int c = 0; c < 4; c++) s[mt][nt][c] = 0.f;
#pragma unroll
        for (int ks = 0; ks < 128; ks += 16) {
            uint32_t a[2][4];
            ldsm_x4(a[0][0], a[0][1], a[0][2], a[0][3], qsb + aoff + ks * 2);
            ldsm_x4(a[1][0], a[1][1], a[1][2], a[1][3], qsb + aoff + 16 * FSTRB + ks * 2);
#pragma unroll
            for (int pr = 0; pr < 2; pr++) {
                uint32_t b0, b1, b2, b3;
                ldsm_x4(b0, b1, b2, b3, ksb + boff + (uint32_t)pr * 16 * FSTRB + ks * 2);
                mma_f16(s[0][2 * pr],     a[0][0], a[0][1], a[0][2], a[0][3], b0, b1);
                mma_f16(s[1][2 * pr],     a[1][0], a[1][1], a[1][2], a[1][3], b0, b1);
                mma_f16(s[0][2 * pr + 1], a[0][0], a[0][1], a[0][2], a[0][3], b2, b3);
                mma_f16(s[1][2 * pr + 1], a[1][0], a[1][1], a[1][2], a[1][3], b2, b3);
            }
        }

        if (j == nj - 1) {
            const int col0 = j * 128;
            const int row0 = qi * 64;
#pragma unroll
            for (int mt = 0; mt < 2; mt++)
#pragma unroll
                for (int nt = 0; nt < 4; nt++) {
                    const int colb = col0 + wn * 32 + nt * 8 + 2 * ak;
#pragma unroll
                    for (int cc = 0; cc < 4; cc++) {
                        const int row_g = row0 + wm * 32 + mt * 16 + ar + (cc >> 1) * 8;
                        const int col_g = colb + (cc & 1);
                        if (col_g > row_g) s[mt][nt][cc] = -1e30f;
                    }
                }
        }

#pragma unroll
        for (int mt = 0; mt < 2; mt++) {
            float r0m = fmaxf(fmaxf(s[mt][0][0], s[mt][0][1]), fmaxf(s[mt][1][0], s[mt][1][1]));
            r0m = fmaxf(r0m, fmaxf(fmaxf(s[mt][2][0], s[mt][2][1]), fmaxf(s[mt][3][0], s[mt][3][1])));
            float r1m = fmaxf(fmaxf(s[mt][0][2], s[mt][0][3]), fmaxf(s[mt][1][2], s[mt][1][3]));
            r1m = fmaxf(r1m, fmaxf(fmaxf(s[mt][2][2], s[mt][2][3]), fmaxf(s[mt][3][2], s[mt][3][3])));
            r0m = fmaxf(r0m, __shfl_xor_sync(0xffffffffu, r0m, 1));
            r0m = fmaxf(r0m, __shfl_xor_sync(0xffffffffu, r0m, 2));
            r1m = fmaxf(r1m, __shfl_xor_sync(0xffffffffu, r1m, 1));
            r1m = fmaxf(r1m, __shfl_xor_sync(0xffffffffu, r1m, 2));
            if (ak == 0) {
                redmax[wn][wm * 32 + mt * 16 + ar]     = r0m;
                redmax[wn][wm * 32 + mt * 16 + ar + 8] = r1m;
            }
        }
        __syncthreads();

        float m_new[2][2];
#pragma unroll
        for (int mt = 0; mt < 2; mt++)
#pragma unroll
            for (int hh = 0; hh < 2; hh++) {
                const int row = wm * 32 + mt * 16 + ar + hh * 8;
                float mr = fmaxf(fmaxf(redmax[0][row], redmax[1][row]),
                                 fmaxf(redmax[2][row], redmax[3][row]));
                m_new[mt][hh] = fmaxf(m_st[mt][hh], mr);
                if (wn == 0 && ak == 0)
                    corrs[row] = ex2((m_st[mt][hh] - m_new[mt][hh]) * C);
            }

        // p = 2^((s-m)*C): 11/16 on FMA-poly, 5/16 on MUFU (pipe-balanced)
        float psum[2][2];
        psum[0][0] = psum[0][1] = psum[1][0] = psum[1][1] = 0.f;
#pragma unroll
        for (int mt = 0; mt < 2; mt++) {
            const float mC0 = m_new[mt][0] * C;
            const float mC1 = m_new[mt][1] * C;
#pragma unroll
            for (int nt = 0; nt < 4; nt++) {
                const int colb = wn * 32 + nt * 8 + 2 * ak;
                float p0 = exp2poly(fmaf(s[mt][nt][0], C, -mC0));
                float p1 = exp2poly(fmaf(s[mt][nt][1], C, -mC0));
                float p2, p3;
                if (nt == 0) {
                    p2 = exp2poly(fmaf(s[mt][nt][2], C, -mC1));
                    p3 = exp2poly(fmaf(s[mt][nt][3], C, -mC1));
                } else if (nt == 1) {
                    p2 = exp2poly(fmaf(s[mt][nt][2], C, -mC1));
                    p3 = ex2(fmaf(s[mt][nt][3], C, -mC1));
                } else {
                    p2 = ex2(fmaf(s[mt][nt][2], C, -mC1));
                    p3 = ex2(fmaf(s[mt][nt][3], C, -mC1));
                }
                psum[mt][0] += p0 + p1;
                psum[mt][1] += p2 + p3;
                const int r0 = wm * 32 + mt * 16 + ar;
                *(__half2*)&Ks[r0][colb]     = fh2(p0, p1);
                *(__half2*)&Ks[r0 + 8][colb] = fh2(p2, p3);
            }
        }
#pragma unroll
        for (int mt = 0; mt < 2; mt++) {
            psum[mt][0] += __shfl_xor_sync(0xffffffffu, psum[mt][0], 1);
            psum[mt][0] += __shfl_xor_sync(0xffffffffu, psum[mt][0], 2);
            psum[mt][1] += __shfl_xor_sync(0xffffffffu, psum[mt][1], 1);
            psum[mt][1] += __shfl_xor_sync(0xffffffffu, psum[mt][1], 2);
            if (ak == 0) {
                redsum[wn][wm * 32 + mt * 16 + ar]     = psum[mt][0];
                redsum[wn][wm * 32 + mt * 16 + ar + 8] = psum[mt][1];
            }
        }
        CPWAIT(0);                           // V arrived (own group)
        __syncthreads();                     // all threads' V + redsum visible

        float corr[2][2];
#pragma unroll
        for (int mt = 0; mt < 2; mt++)
#pragma unroll
            for (int hh = 0; hh < 2; hh++) {
                const int row = wm * 32 + mt * 16 + ar + hh * 8;
                float sm = (redsum[0][row] + redsum[1][row]) + (redsum[2][row] + redsum[3][row]);
                corr[mt][hh] = corrs[row];
                l_st[mt][hh] = l_st[mt][hh] * corr[mt][hh] + sm;
                m_st[mt][hh] = m_new[mt][hh];
            }
#pragma unroll
        for (int mt = 0; mt < 2; mt++)
#pragma unroll
            for (int nt = 0; nt < 4; nt++) {
                o[mt][nt][0] *= corr[mt][0];
                o[mt][nt][1] *= corr[mt][0];
                o[mt][nt][2] *= corr[mt][1];
                o[mt][nt][3] *= corr[mt][1];
            }

        // O += P * V  (64x128, K=128); V via ldmatrix.trans
#pragma unroll
        for (int ks = 0; ks < 128; ks += 16) {
            uint32_t a[2][4];
            ldsm_x4(a[0][0], a[0][1], a[0][2], a[0][3], ksb + aoff + ks * 2);
            ldsm_x4(a[1][0], a[1][1], a[1][2], a[1][3], ksb + aoff + 16 * FSTRB + ks * 2);
#pragma unroll
            for (int half_n = 0; half_n < 2; half_n++) {
                uint32_t b0, b1, b2, b3;
                ldsm_x4t(b0, b1, b2, b3, vsb + voff + (uint32_t)ks * FSTRB + half_n * 32);
                mma_f16(o[0][2 * half_n],     a[0][0], a[0][1], a[0][2], a[0][3], b0, b1);
                mma_f16(o[1][2 * half_n],     a[1][0], a[1][1], a[1][2], a[1][3], b0, b1);
                mma_f16(o[0][2 * half_n + 1], a[0][0], a[0][1], a[0][2], a[0][3], b2, b3);
                mma_f16(o[1][2 * half_n + 1], a[1][0], a[1][1], a[1][2], a[1][3], b2, b3);
            }
        }
    }

    // epilogue: normalize, write ctx as fp16
#pragma unroll
    for (int mt = 0; mt < 2; mt++) {
        const int r0 = wm * 32 + mt * 16 + ar;
        const float i0 = 1.f / l_st[mt][0];
        const float i1 = 1.f / l_st[mt][1];
        __half* c0p = Ctx + (size_t)(qi * 64 + r0) * HID + h * DHEAD;
        __half* c1p = c0p + 8 * HID;
#pragma unroll
        for (int nt = 0; nt < 4; nt++) {
            const int cb = wn * 32 + nt * 8 + 2 * ak;
            *(__half2*)(c0p + cb) = fh2(o[mt][nt][0] * i0, o[mt][nt][1] * i0);
            *(__half2*)(c1p + cb) = fh2(o[mt][nt][2] * i1, o[mt][nt][3] * i1);
        }
    }
}

// ---------------------------------------------------------------------------
// Per-(s,kvhead) RMSNorm + RoPE for K, in place on fp16.
// ---------------------------------------------------------------------------
__global__ __launch_bounds__(128) void k_normrope_h(
    __half* __restrict__ X, int rowstride,
    const float* __restrict__ sin_t, const float* __restrict__ cos_t,
    const float* __restrict__ w)
{
    const int s = blockIdx.x;
    const int h = blockIdx.y;
    const int d = threadIdx.x;
    __half* row = X + (size_t)s * rowstride + h * DHEAD;
    float v = __half2float(row[d]);
    float ss = v * v;
#pragma unroll
    for (int o = 16; o > 0; o >>= 1) ss += __shfl_xor_sync(0xffffffffu, ss, o);
    __shared__ float wsum[4];
    if ((d & 31) == 0) wsum[d >> 5] = ss;
    __syncthreads();
    float tot = wsum[0] + wsum[1] + wsum[2] + wsum[3];
    float inv = rsqrtf(tot * (1.0f / 128.0f) + 1.1920928955078125e-07f);
    __shared__ float xn[128];
    float xv = v * inv * w[d];
    xn[d] = xv;
    __syncthreads();
    float rot = (d < 64) ? -xn[d + 64] : xn[d - 64];
    row[d] = __float2half(cos_t[s * DHEAD + d] * xv + sin_t[s * DHEAD + d] * rot);
}

// ---------------------------------------------------------------------------
// Launch
// ---------------------------------------------------------------------------
extern "C" void kernel_launch(void* const* d_in, const int* in_sizes, int n_in,
                              void* d_out, int out_size)
{
    (void)in_sizes; (void)n_in; (void)out_size;
    const float* x     = (const float*)d_in[0];
    const float* sin_t = (const float*)d_in[1];
    const float* cos_t = (const float*)d_in[2];
    const float* wq    = (const float*)d_in[4];
    const float* wk    = (const float*)d_in[5];
    const float* wv    = (const float*)d_in[6];
    const float* wo    = (const float*)d_in[7];
    const float* qnw   = (const float*)d_in[8];
    const float* knw   = (const float*)d_in[9];
    float* out = (float*)d_out;

    __half *xh, *wqh, *wkh, *wvh, *woh, *qh, *kh, *vh, *ctxh;
    cudaGetSymbolAddress((void**)&xh,   g_xh);
    cudaGetSymbolAddress((void**)&wqh,  g_wqh);
    cudaGetSymbolAddress((void**)&wkh,  g_wkh);
    cudaGetSymbolAddress((void**)&wvh,  g_wvh);
    cudaGetSymbolAddress((void**)&woh,  g_woh);
    cudaGetSymbolAddress((void**)&qh,   g_qh);
    cudaGetSymbolAddress((void**)&kh,   g_kh);
    cudaGetSymbolAddress((void**)&vh,   g_vh);
    cudaGetSymbolAddress((void**)&ctxh, g_ctxh);

    cudaFuncSetAttribute(k_flash, cudaFuncAttributeMaxDynamicSharedMemorySize, FLASH_SMEM);

    // One fused fp32 -> fp16 conversion launch (7168 blocks)
    k_cvt_all<<<7168, 256>>>(x, wq, wk, wv, wo);

    // Fused QKV projection (fp16 in/out)
    k_gemm_qkv<<<dim3((HID + 2 * KVW) / 128, SEQ / 128), 256>>>(xh, wqh, wkh, wvh, qh, kh, vh);

    // RMSNorm + RoPE for K
    k_normrope_h<<<dim3(SEQ, NKVH), 128>>>(kh, KVW, sin_t, cos_t, knw);

    // Fused flash attention
    k_flash<<<512, 256, FLASH_SMEM>>>(qh, kh, vh, ctxh, sin_t, cos_t, qnw);

    // Output projection (fp16 in, fp32 out)
    k_gemm_o<<<dim3(HID / 128, SEQ / 128), 256>>>(ctxh, woh, out);
}